// round 1
// baseline (speedup 1.0000x reference)
#include <cuda_runtime.h>

#define BB 16
#define CC 256
#define HW 4096
#define NH 8
#define HD 32
#define NG 32
#define CPG 8          // channels per group (256/32)
#define EPSV 1e-5f

// Scratch (device globals -- no allocation allowed in kernel_launch)
__device__ float g_qkv[(size_t)BB * 3 * CC * HW];    // 201 MB
__device__ float g_attout[(size_t)BB * CC * HW];     // 67 MB
__device__ float g_att[(size_t)BB * NH * HD * HD];   // 0.5 MB
__device__ float g_scale[BB * CC];
__device__ float g_shift[BB * CC];

// ---------------------------------------------------------------------------
// K1: GroupNorm statistics -> per (b, channel) scale/shift
//     xn = x * scale + shift, scale = rstd*gn_w, shift = gn_b - mu*rstd*gn_w
// ---------------------------------------------------------------------------
__global__ void gn_stats_kernel(const float* __restrict__ x,
                                const float* __restrict__ gw,
                                const float* __restrict__ gb) {
    const int b = blockIdx.x / NG;
    const int g = blockIdx.x % NG;
    const float* xp = x + ((size_t)b * CC + (size_t)g * CPG) * HW;

    float s = 0.f, s2 = 0.f;
    for (int i = threadIdx.x; i < CPG * HW; i += blockDim.x) {
        float v = xp[i];
        s += v; s2 += v * v;
    }
    __shared__ float rs[32], rs2[32];
    #pragma unroll
    for (int o = 16; o > 0; o >>= 1) {
        s  += __shfl_down_sync(0xFFFFFFFFu, s,  o);
        s2 += __shfl_down_sync(0xFFFFFFFFu, s2, o);
    }
    int lane = threadIdx.x & 31, wid = threadIdx.x >> 5;
    if (lane == 0) { rs[wid] = s; rs2[wid] = s2; }
    __syncthreads();
    if (wid == 0) {
        int nw = blockDim.x >> 5;
        s  = (lane < nw) ? rs[lane]  : 0.f;
        s2 = (lane < nw) ? rs2[lane] : 0.f;
        #pragma unroll
        for (int o = 16; o > 0; o >>= 1) {
            s  += __shfl_down_sync(0xFFFFFFFFu, s,  o);
            s2 += __shfl_down_sync(0xFFFFFFFFu, s2, o);
        }
        if (lane == 0) { rs[0] = s; rs2[0] = s2; }
    }
    __syncthreads();
    const float inv_n = 1.f / (float)(CPG * HW);
    float mu  = rs[0] * inv_n;
    float var = rs2[0] * inv_n - mu * mu;
    float rstd = rsqrtf(var + EPSV);
    if (threadIdx.x < CPG) {
        int c = g * CPG + threadIdx.x;
        float sc = rstd * gw[c];
        g_scale[b * CC + c] = sc;
        g_shift[b * CC + c] = gb[c] - mu * sc;
    }
}

// ---------------------------------------------------------------------------
// K2/K6: batched GEMM  C[b][m][n] = sum_k A[m][k] * Bn[b][k][n]  (+ bias[m])
//        Bn = Xin*scale+shift when use_norm, else Xin.
//        Block tile 64x64, K-tile 16, 256 threads, 4x4 per thread.
//        Shapes: M % 64 == 0, N = HW, K = CC (exact, no bounds checks)
// ---------------------------------------------------------------------------
__global__ void gemm_bn_kernel(const float* __restrict__ A,
                               const float* __restrict__ Xin,
                               float* __restrict__ Cout, int M,
                               const float* __restrict__ bias, int use_norm) {
    __shared__ float As[16][65];   // padded (transposed store)
    __shared__ float Bs[16][64];

    const int b  = blockIdx.z;
    const int m0 = blockIdx.y * 64;
    const int n0 = blockIdx.x * 64;
    const int tid = threadIdx.x;
    const int tx = tid & 15, ty = tid >> 4;
    const float* Xb = Xin + (size_t)b * CC * HW;

    float acc[4][4] = {};

    for (int k0 = 0; k0 < CC; k0 += 16) {
        {   // A tile load (64 rows x 16 k), one float4 per thread, store transposed
            int r  = tid >> 2;
            int c4 = (tid & 3) * 4;
            float4 a = *(const float4*)(A + (size_t)(m0 + r) * CC + k0 + c4);
            As[c4 + 0][r] = a.x; As[c4 + 1][r] = a.y;
            As[c4 + 2][r] = a.z; As[c4 + 3][r] = a.w;
        }
        {   // B tile load (16 k-rows x 64 n), fused groupnorm
            int r  = tid >> 4;
            int c4 = (tid & 15) * 4;
            int k  = k0 + r;
            float4 v = *(const float4*)(Xb + (size_t)k * HW + n0 + c4);
            if (use_norm) {
                float sc = g_scale[b * CC + k], sh = g_shift[b * CC + k];
                v.x = fmaf(v.x, sc, sh); v.y = fmaf(v.y, sc, sh);
                v.z = fmaf(v.z, sc, sh); v.w = fmaf(v.w, sc, sh);
            }
            *(float4*)&Bs[r][c4] = v;
        }
        __syncthreads();
        #pragma unroll
        for (int kk = 0; kk < 16; kk++) {
            float ra[4], rb[4];
            #pragma unroll
            for (int i = 0; i < 4; i++) ra[i] = As[kk][ty * 4 + i];
            #pragma unroll
            for (int j = 0; j < 4; j++) rb[j] = Bs[kk][tx * 4 + j];
            #pragma unroll
            for (int i = 0; i < 4; i++)
                #pragma unroll
                for (int j = 0; j < 4; j++)
                    acc[i][j] = fmaf(ra[i], rb[j], acc[i][j]);
        }
        __syncthreads();
    }
    #pragma unroll
    for (int i = 0; i < 4; i++) {
        int m = m0 + ty * 4 + i;
        float bi = bias ? bias[m] : 0.f;
        float4 o = make_float4(acc[i][0] + bi, acc[i][1] + bi,
                               acc[i][2] + bi, acc[i][3] + bi);
        *(float4*)(Cout + ((size_t)b * M + m) * HW + n0 + tx * 4) = o;
    }
}

// ---------------------------------------------------------------------------
// K3: softmax over n for each K-row (b, h, d): 4096 rows of length 4096
// ---------------------------------------------------------------------------
__global__ void softmax_k_kernel() {
    const int row = blockIdx.x;               // 0 .. BB*CC-1
    const int b = row / CC, ch = row % CC;
    float* p = g_qkv + ((size_t)b * 3 * CC + CC + ch) * HW;

    __shared__ float sm[HW];                  // 16 KB
    __shared__ float red[32];

    float lmax = -3.4e38f;
    for (int i = threadIdx.x; i < HW; i += blockDim.x) {
        float v = p[i];
        sm[i] = v;
        lmax = fmaxf(lmax, v);
    }
    #pragma unroll
    for (int o = 16; o > 0; o >>= 1)
        lmax = fmaxf(lmax, __shfl_down_sync(0xFFFFFFFFu, lmax, o));
    int lane = threadIdx.x & 31, wid = threadIdx.x >> 5;
    if (lane == 0) red[wid] = lmax;
    __syncthreads();
    if (wid == 0) {
        lmax = (lane < (blockDim.x >> 5)) ? red[lane] : -3.4e38f;
        #pragma unroll
        for (int o = 16; o > 0; o >>= 1)
            lmax = fmaxf(lmax, __shfl_down_sync(0xFFFFFFFFu, lmax, o));
        if (lane == 0) red[0] = lmax;
    }
    __syncthreads();
    const float rowmax = red[0];
    __syncthreads();

    float lsum = 0.f;
    for (int i = threadIdx.x; i < HW; i += blockDim.x) {
        float e = __expf(sm[i] - rowmax);
        sm[i] = e;
        lsum += e;
    }
    #pragma unroll
    for (int o = 16; o > 0; o >>= 1)
        lsum += __shfl_down_sync(0xFFFFFFFFu, lsum, o);
    if (lane == 0) red[wid] = lsum;
    __syncthreads();
    if (wid == 0) {
        lsum = (lane < (blockDim.x >> 5)) ? red[lane] : 0.f;
        #pragma unroll
        for (int o = 16; o > 0; o >>= 1)
            lsum += __shfl_down_sync(0xFFFFFFFFu, lsum, o);
        if (lane == 0) red[0] = lsum;
    }
    __syncthreads();
    const float rinv = 1.f / red[0];
    for (int i = threadIdx.x; i < HW; i += blockDim.x)
        p[i] = sm[i] * rinv;
}

// ---------------------------------------------------------------------------
// K4: att[b,h,d,e] = sum_n k[d,n] * v[e,n]   (one block per (b,h))
// ---------------------------------------------------------------------------
__global__ void att_kv_kernel() {
    const int bh = blockIdx.x;                // 0..127
    const int b = bh / NH, h = bh % NH;
    const float* kk = g_qkv + ((size_t)b * 3 * CC + 1 * CC + h * HD) * HW;
    const float* vv = g_qkv + ((size_t)b * 3 * CC + 2 * CC + h * HD) * HW;

    __shared__ float sk[HD][65];
    __shared__ float sv[HD][65];

    const int tid = threadIdx.x;
    float acc[4] = {0.f, 0.f, 0.f, 0.f};

    for (int n0 = 0; n0 < HW; n0 += 64) {
        for (int i = tid; i < HD * 64; i += 256) {
            int r = i >> 6, c = i & 63;
            sk[r][c] = kk[(size_t)r * HW + n0 + c];
            sv[r][c] = vv[(size_t)r * HW + n0 + c];
        }
        __syncthreads();
        #pragma unroll
        for (int p = 0; p < 4; p++) {
            int idx = tid + p * 256;
            int d = idx >> 5, e = idx & 31;
            float a = acc[p];
            #pragma unroll 8
            for (int j = 0; j < 64; j++)
                a = fmaf(sk[d][j], sv[e][j], a);
            acc[p] = a;
        }
        __syncthreads();
    }
    #pragma unroll
    for (int p = 0; p < 4; p++)
        g_att[(size_t)bh * HD * HD + tid + p * 256] = acc[p];
}

// ---------------------------------------------------------------------------
// K5: out[b,h,e,n] = sum_d att[d,e] * q[d,n]
// ---------------------------------------------------------------------------
__global__ void att_q_kernel() {
    const int bh = blockIdx.y;
    const int b = bh / NH, h = bh % NH;
    const int n = blockIdx.x * 256 + threadIdx.x;

    __shared__ float sa[HD][HD];
    for (int i = threadIdx.x; i < HD * HD; i += 256)
        sa[i >> 5][i & 31] = g_att[(size_t)bh * HD * HD + i];
    __syncthreads();

    const float* q = g_qkv + ((size_t)b * 3 * CC + 0 * CC + h * HD) * HW + n;
    float acc[HD];
    #pragma unroll
    for (int e = 0; e < HD; e++) acc[e] = 0.f;

    #pragma unroll
    for (int d = 0; d < HD; d++) {
        float qv = q[(size_t)d * HW];
        #pragma unroll
        for (int e = 0; e < HD; e++)
            acc[e] = fmaf(sa[d][e], qv, acc[e]);
    }
    float* op = g_attout + ((size_t)b * CC + h * HD) * HW + n;
    #pragma unroll
    for (int e = 0; e < HD; e++)
        op[(size_t)e * HW] = acc[e];
}

// ---------------------------------------------------------------------------
extern "C" void kernel_launch(void* const* d_in, const int* in_sizes, int n_in,
                              void* d_out, int out_size) {
    const float* x      = (const float*)d_in[0];
    const float* gn_w   = (const float*)d_in[1];
    const float* gn_b   = (const float*)d_in[2];
    const float* w_qkv  = (const float*)d_in[3];
    const float* w_proj = (const float*)d_in[4];
    const float* b_proj = (const float*)d_in[5];
    float* out = (float*)d_out;

    float* qkv;    cudaGetSymbolAddress((void**)&qkv,    g_qkv);
    float* attout; cudaGetSymbolAddress((void**)&attout, g_attout);

    // K1: groupnorm stats
    gn_stats_kernel<<<BB * NG, 256>>>(x, gn_w, gn_b);

    // K2: QKV projection with fused groupnorm
    {
        dim3 grid(HW / 64, (3 * CC) / 64, BB);
        gemm_bn_kernel<<<grid, 256>>>(w_qkv, x, qkv, 3 * CC, nullptr, 1);
    }

    // K3: softmax over K rows
    softmax_k_kernel<<<BB * CC, 256>>>();

    // K4: att = softmax(K) @ V^T
    att_kv_kernel<<<BB * NH, 256>>>();

    // K5: out = att^T @ Q
    {
        dim3 grid(HW / 256, BB * NH);
        att_q_kernel<<<grid, 256>>>();
    }

    // K6: output projection + bias -> d_out
    {
        dim3 grid(HW / 64, CC / 64, BB);
        gemm_bn_kernel<<<grid, 256>>>(w_proj, attout, out, CC, b_proj, 0);
    }
}

// round 3
// speedup vs baseline: 2.1280x; 2.1280x over previous
#include <cuda_runtime.h>
#include <cuda_bf16.h>
#include <cstdint>

#define BB 16
#define CC 256
#define HW 4096
#define NH 8
#define HD 32
#define NG 32
#define CPG 8
#define EPSV 1e-5f
#define SPLIT 16

// ---------------- scratch (device globals; no allocations allowed) ----------
__device__ float g_qkv[(size_t)BB * 3 * CC * HW];                 // 201 MB
__device__ float g_attout[(size_t)BB * CC * HW];                  // 67 MB
__device__ float g_att[(size_t)BB * NH * HD * HD];                // 0.5 MB
__device__ float g_att_part[(size_t)SPLIT * BB * NH * HD * HD];   // 8 MB
__device__ float g_rowmax[BB * CC];
__device__ float g_rowsum[BB * CC];
__device__ float g_scale[BB * CC];
__device__ float g_shift[BB * CC];

// ---------------- warp-MMA helpers ------------------------------------------
__device__ __forceinline__ uint32_t smem_u32(const void* p) {
    uint32_t a;
    asm("{ .reg .u64 t; cvta.to.shared.u64 t, %1; cvt.u32.u64 %0, t; }"
        : "=r"(a) : "l"(p));
    return a;
}
__device__ __forceinline__ void ldmx4(uint32_t* r, uint32_t addr) {
    asm volatile("ldmatrix.sync.aligned.m8n8.x4.shared.b16 {%0,%1,%2,%3}, [%4];"
                 : "=r"(r[0]), "=r"(r[1]), "=r"(r[2]), "=r"(r[3]) : "r"(addr));
}
__device__ __forceinline__ void ldmx4t(uint32_t* r, uint32_t addr) {
    asm volatile("ldmatrix.sync.aligned.m8n8.x4.trans.shared.b16 {%0,%1,%2,%3}, [%4];"
                 : "=r"(r[0]), "=r"(r[1]), "=r"(r[2]), "=r"(r[3]) : "r"(addr));
}
__device__ __forceinline__ void mma_bf16(float* c, const uint32_t* a, const uint32_t* b) {
    asm volatile("mma.sync.aligned.m16n8k16.row.col.f32.bf16.bf16.f32 "
                 "{%0,%1,%2,%3}, {%4,%5,%6,%7}, {%8,%9}, {%0,%1,%2,%3};"
                 : "+f"(c[0]), "+f"(c[1]), "+f"(c[2]), "+f"(c[3])
                 : "r"(a[0]), "r"(a[1]), "r"(a[2]), "r"(a[3]),
                   "r"(b[0]), "r"(b[1]));
}
__device__ __forceinline__ uint32_t pk2(__nv_bfloat16 a, __nv_bfloat16 b) {
    __nv_bfloat162 t = __halves2bfloat162(a, b);
    return *(uint32_t*)&t;
}

// smem row strides (bf16 units), padded for conflict-free ldmatrix
#define AST 40    // 32 data + 8 pad  -> 80B rows (stride 20 words)
#define BST 136   // 128 data + 8 pad -> 272B rows (stride 68 words)

// ---------------------------------------------------------------------------
// K1: GroupNorm statistics -> per (b, channel) scale/shift
// ---------------------------------------------------------------------------
__global__ void gn_stats_kernel(const float* __restrict__ x,
                                const float* __restrict__ gw,
                                const float* __restrict__ gb) {
    const int b = blockIdx.x / NG;
    const int g = blockIdx.x % NG;
    const float* xp = x + ((size_t)b * CC + (size_t)g * CPG) * HW;

    float s = 0.f, s2 = 0.f;
    for (int i = threadIdx.x; i < CPG * HW; i += blockDim.x) {
        float v = xp[i];
        s += v; s2 += v * v;
    }
    __shared__ float rs[32], rs2[32];
    #pragma unroll
    for (int o = 16; o > 0; o >>= 1) {
        s  += __shfl_down_sync(0xFFFFFFFFu, s,  o);
        s2 += __shfl_down_sync(0xFFFFFFFFu, s2, o);
    }
    int lane = threadIdx.x & 31, wid = threadIdx.x >> 5;
    if (lane == 0) { rs[wid] = s; rs2[wid] = s2; }
    __syncthreads();
    if (wid == 0) {
        int nw = blockDim.x >> 5;
        s  = (lane < nw) ? rs[lane]  : 0.f;
        s2 = (lane < nw) ? rs2[lane] : 0.f;
        #pragma unroll
        for (int o = 16; o > 0; o >>= 1) {
            s  += __shfl_down_sync(0xFFFFFFFFu, s,  o);
            s2 += __shfl_down_sync(0xFFFFFFFFu, s2, o);
        }
        if (lane == 0) { rs[0] = s; rs2[0] = s2; }
    }
    __syncthreads();
    const float inv_n = 1.f / (float)(CPG * HW);
    float mu  = rs[0] * inv_n;
    float var = rs2[0] * inv_n - mu * mu;
    float rstd = rsqrtf(var + EPSV);
    if (threadIdx.x < CPG) {
        int c = g * CPG + threadIdx.x;
        float sc = rstd * gw[c];
        g_scale[b * CC + c] = sc;
        g_shift[b * CC + c] = gb[c] - mu * sc;
    }
}

// ---------------------------------------------------------------------------
// K2/K6: HMMA bf16-split GEMM  C[b][m][n] = sum_k A[m][k]*Bn[b][k][n] (+bias)
//   CTA 128m x 128n, K chunks of 32. 8 warps = 4(m) x 2(n); each warp 32x64.
//   x = hi + lo (bf16); C ~= Ah*Bh + Ah*Bl + Al*Bh  (fp32 acc)
// ---------------------------------------------------------------------------
__global__ __launch_bounds__(256)
void gemm_mma(const float* __restrict__ A, const float* __restrict__ X,
              float* __restrict__ Cout, int M,
              const float* __restrict__ bias, int use_norm) {
    __shared__ __nv_bfloat16 sAh[128 * AST];
    __shared__ __nv_bfloat16 sAl[128 * AST];
    __shared__ __nv_bfloat16 sBh[32 * BST];
    __shared__ __nv_bfloat16 sBl[32 * BST];

    const int tid  = threadIdx.x;
    const int wid  = tid >> 5, lane = tid & 31;
    const int wM   = wid >> 1;           // 0..3  -> m offset wM*32
    const int wN   = wid & 1;            // 0..1  -> n offset wN*64
    const int b  = blockIdx.z;
    const int m0 = blockIdx.y * 128;
    const int n0 = blockIdx.x * 128;

    const float* Xb  = X + (size_t)b * CC * HW;
    const float* scp = g_scale + b * CC;
    const float* shp = g_shift + b * CC;

    const uint32_t aHB = smem_u32(sAh), aLB = smem_u32(sAl);
    const uint32_t bHB = smem_u32(sBh), bLB = smem_u32(sBl);

    float acc[2][8][4];
    #pragma unroll
    for (int i = 0; i < 2; i++)
        #pragma unroll
        for (int j = 0; j < 8; j++)
            #pragma unroll
            for (int q = 0; q < 4; q++) acc[i][j][q] = 0.f;

    // ldmatrix per-lane address components
    const int lt = lane >> 3, lr = lane & 7;
    // A x4 tiles: t0:(r,k0) t1:(r+8,k0) t2:(r,k0+8) t3:(r+8,k0+8)
    const int aRow = lr + ((lt & 1) ? 8 : 0);
    const int aKof = (lt & 2) ? 8 : 0;
    // B x4 trans tiles: t0:(k0,n) t1:(k0+8,n) t2:(k0,n+8) t3:(k0+8,n+8)
    const int bKof = lr + ((lt & 1) ? 8 : 0);
    const int bNof = (lt & 2) ? 8 : 0;

    for (int k0 = 0; k0 < CC; k0 += 32) {
        // ---- load A chunk [128][32] -> hi/lo, rows padded to AST
        #pragma unroll
        for (int it = 0; it < 4; it++) {
            int f4 = it * 256 + tid;
            int row = f4 >> 3, kloc = (f4 & 7) * 4;
            float4 v = *(const float4*)(A + (size_t)(m0 + row) * CC + k0 + kloc);
            __nv_bfloat16 h0 = __float2bfloat16(v.x), h1 = __float2bfloat16(v.y);
            __nv_bfloat16 h2 = __float2bfloat16(v.z), h3 = __float2bfloat16(v.w);
            __nv_bfloat16 l0 = __float2bfloat16(v.x - __bfloat162float(h0));
            __nv_bfloat16 l1 = __float2bfloat16(v.y - __bfloat162float(h1));
            __nv_bfloat16 l2 = __float2bfloat16(v.z - __bfloat162float(h2));
            __nv_bfloat16 l3 = __float2bfloat16(v.w - __bfloat162float(h3));
            int off = row * AST + kloc;
            *(uint2*)&sAh[off] = make_uint2(pk2(h0, h1), pk2(h2, h3));
            *(uint2*)&sAl[off] = make_uint2(pk2(l0, l1), pk2(l2, l3));
        }
        // ---- load B chunk x[k][n] -> [32 k][128 n] hi/lo, fused norm
        #pragma unroll
        for (int it = 0; it < 4; it++) {
            int f4 = it * 256 + tid;
            int kk = f4 >> 5, nn = (f4 & 31) * 4;
            int k = k0 + kk;
            float4 v = *(const float4*)(Xb + (size_t)k * HW + n0 + nn);
            if (use_norm) {
                float sc = scp[k], sh = shp[k];
                v.x = fmaf(v.x, sc, sh); v.y = fmaf(v.y, sc, sh);
                v.z = fmaf(v.z, sc, sh); v.w = fmaf(v.w, sc, sh);
            }
            __nv_bfloat16 h0 = __float2bfloat16(v.x), h1 = __float2bfloat16(v.y);
            __nv_bfloat16 h2 = __float2bfloat16(v.z), h3 = __float2bfloat16(v.w);
            __nv_bfloat16 l0 = __float2bfloat16(v.x - __bfloat162float(h0));
            __nv_bfloat16 l1 = __float2bfloat16(v.y - __bfloat162float(h1));
            __nv_bfloat16 l2 = __float2bfloat16(v.z - __bfloat162float(h2));
            __nv_bfloat16 l3 = __float2bfloat16(v.w - __bfloat162float(h3));
            int off = kk * BST + nn;
            *(uint2*)&sBh[off] = make_uint2(pk2(h0, h1), pk2(h2, h3));
            *(uint2*)&sBl[off] = make_uint2(pk2(l0, l1), pk2(l2, l3));
        }
        __syncthreads();

        #pragma unroll
        for (int ks = 0; ks < 2; ks++) {
            const int kb = ks * 16;
            uint32_t ah[2][4], al[2][4], bh[8][2], bl[8][2];
            #pragma unroll
            for (int mt = 0; mt < 2; mt++) {
                uint32_t ad = ((wM * 32 + mt * 16 + aRow) * AST + kb + aKof) * 2;
                ldmx4(ah[mt], aHB + ad);
                ldmx4(al[mt], aLB + ad);
            }
            #pragma unroll
            for (int np = 0; np < 4; np++) {
                uint32_t bd = ((kb + bKof) * BST + wN * 64 + np * 16 + bNof) * 2;
                uint32_t r[4];
                ldmx4t(r, bHB + bd);
                bh[np * 2][0] = r[0]; bh[np * 2][1] = r[1];
                bh[np * 2 + 1][0] = r[2]; bh[np * 2 + 1][1] = r[3];
                ldmx4t(r, bLB + bd);
                bl[np * 2][0] = r[0]; bl[np * 2][1] = r[1];
                bl[np * 2 + 1][0] = r[2]; bl[np * 2 + 1][1] = r[3];
            }
            #pragma unroll
            for (int mt = 0; mt < 2; mt++)
                #pragma unroll
                for (int nt = 0; nt < 8; nt++) {
                    mma_bf16(acc[mt][nt], ah[mt], bh[nt]);
                    mma_bf16(acc[mt][nt], ah[mt], bl[nt]);
                    mma_bf16(acc[mt][nt], al[mt], bh[nt]);
                }
        }
        __syncthreads();
    }

    // ---- epilogue: c0,c1 -> (row, col..col+1); c2,c3 -> (row+8, ...)
    const int rbase = m0 + wM * 32 + (lane >> 2);
    const int cbase = n0 + wN * 64 + (lane & 3) * 2;
    #pragma unroll
    for (int mt = 0; mt < 2; mt++) {
        int r0 = rbase + mt * 16;
        float bi0 = bias ? bias[r0] : 0.f;
        float bi1 = bias ? bias[r0 + 8] : 0.f;
        #pragma unroll
        for (int nt = 0; nt < 8; nt++) {
            int cc = cbase + nt * 8;
            float* p0 = Cout + ((size_t)b * M + r0) * HW + cc;
            float* p1 = Cout + ((size_t)b * M + r0 + 8) * HW + cc;
            *(float2*)p0 = make_float2(acc[mt][nt][0] + bi0, acc[mt][nt][1] + bi0);
            *(float2*)p1 = make_float2(acc[mt][nt][2] + bi1, acc[mt][nt][3] + bi1);
        }
    }
}

// ---------------------------------------------------------------------------
// K3: per-K-row max and sum(exp(k - max)) -- stats only
// ---------------------------------------------------------------------------
__global__ void rowstats_kernel() {
    const int row = blockIdx.x;               // 0 .. BB*CC-1
    const int b = row / CC, ch = row % CC;
    const float* p = g_qkv + ((size_t)b * 3 * CC + CC + ch) * HW;

    __shared__ float sm[HW];
    __shared__ float red[32];

    float lmax = -3.4e38f;
    for (int i = threadIdx.x; i < HW; i += blockDim.x) {
        float v = p[i];
        sm[i] = v;
        lmax = fmaxf(lmax, v);
    }
    #pragma unroll
    for (int o = 16; o > 0; o >>= 1)
        lmax = fmaxf(lmax, __shfl_down_sync(0xFFFFFFFFu, lmax, o));
    int lane = threadIdx.x & 31, wid = threadIdx.x >> 5;
    if (lane == 0) red[wid] = lmax;
    __syncthreads();
    if (wid == 0) {
        lmax = (lane < (blockDim.x >> 5)) ? red[lane] : -3.4e38f;
        #pragma unroll
        for (int o = 16; o > 0; o >>= 1)
            lmax = fmaxf(lmax, __shfl_down_sync(0xFFFFFFFFu, lmax, o));
        if (lane == 0) red[0] = lmax;
    }
    __syncthreads();
    const float rowmax = red[0];
    __syncthreads();

    float lsum = 0.f;
    for (int i = threadIdx.x; i < HW; i += blockDim.x)
        lsum += __expf(sm[i] - rowmax);
    #pragma unroll
    for (int o = 16; o > 0; o >>= 1)
        lsum += __shfl_down_sync(0xFFFFFFFFu, lsum, o);
    if (lane == 0) red[wid] = lsum;
    __syncthreads();
    if (wid == 0) {
        lsum = (lane < (blockDim.x >> 5)) ? red[lane] : 0.f;
        #pragma unroll
        for (int o = 16; o > 0; o >>= 1)
            lsum += __shfl_down_sync(0xFFFFFFFFu, lsum, o);
        if (lane == 0) {
            g_rowmax[row] = rowmax;
            g_rowsum[row] = lsum;
        }
    }
}

// ---------------------------------------------------------------------------
// K4: partial att over n-splits: part = sum_n exp(k_dn - max_d) * v_en
// ---------------------------------------------------------------------------
__global__ void att_kv_part_kernel() {
    const int s  = blockIdx.x;
    const int bh = blockIdx.y;
    const int b = bh / NH, h = bh % NH;
    const float* kk = g_qkv + ((size_t)b * 3 * CC + 1 * CC + h * HD) * HW;
    const float* vv = g_qkv + ((size_t)b * 3 * CC + 2 * CC + h * HD) * HW;
    const float* rm = g_rowmax + b * CC + h * HD;

    __shared__ float sk[HD][65];
    __shared__ float sv[HD][65];

    const int tid = threadIdx.x;
    const int nbase = s * (HW / SPLIT);
    float acc[4] = {0.f, 0.f, 0.f, 0.f};

    for (int n0 = nbase; n0 < nbase + HW / SPLIT; n0 += 64) {
        for (int i = tid; i < HD * 64; i += 256) {
            int r = i >> 6, c2 = i & 63;
            sk[r][c2] = __expf(kk[(size_t)r * HW + n0 + c2] - rm[r]);
            sv[r][c2] = vv[(size_t)r * HW + n0 + c2];
        }
        __syncthreads();
        #pragma unroll
        for (int p = 0; p < 4; p++) {
            int idx = tid + p * 256;
            int d = idx >> 5, e = idx & 31;
            float a = acc[p];
            #pragma unroll 8
            for (int j = 0; j < 64; j++)
                a = fmaf(sk[d][j], sv[e][j], a);
            acc[p] = a;
        }
        __syncthreads();
    }
    float* op = g_att_part + ((size_t)s * 128 + bh) * (HD * HD);
    #pragma unroll
    for (int p = 0; p < 4; p++)
        op[tid + p * 256] = acc[p];
}

// K4b: reduce partials, apply 1/rowsum
__global__ void att_reduce_kernel() {
    const int bh = blockIdx.x;
    const int b = bh / NH, h = bh % NH;
    for (int idx = threadIdx.x; idx < HD * HD; idx += 256) {
        float ssum = 0.f;
        #pragma unroll
        for (int s = 0; s < SPLIT; s++)
            ssum += g_att_part[((size_t)s * 128 + bh) * (HD * HD) + idx];
        int d = idx >> 5;
        float rinv = 1.f / g_rowsum[b * CC + h * HD + d];
        g_att[(size_t)bh * HD * HD + idx] = ssum * rinv;
    }
}

// ---------------------------------------------------------------------------
// K5: out[b,h,e,n] = sum_d att[d,e] * q[d,n]
// ---------------------------------------------------------------------------
__global__ void att_q_kernel() {
    const int bh = blockIdx.y;
    const int b = bh / NH, h = bh % NH;
    const int n = blockIdx.x * 256 + threadIdx.x;

    __shared__ float sa[HD][HD];
    for (int i = threadIdx.x; i < HD * HD; i += 256)
        sa[i >> 5][i & 31] = g_att[(size_t)bh * HD * HD + i];
    __syncthreads();

    const float* q = g_qkv + ((size_t)b * 3 * CC + 0 * CC + h * HD) * HW + n;
    float acc[HD];
    #pragma unroll
    for (int e = 0; e < HD; e++) acc[e] = 0.f;

    #pragma unroll
    for (int d = 0; d < HD; d++) {
        float qv = q[(size_t)d * HW];
        #pragma unroll
        for (int e = 0; e < HD; e++)
            acc[e] = fmaf(sa[d][e], qv, acc[e]);
    }
    float* op = g_attout + ((size_t)b * CC + h * HD) * HW + n;
    #pragma unroll
    for (int e = 0; e < HD; e++)
        op[(size_t)e * HW] = acc[e];
}

// ---------------------------------------------------------------------------
extern "C" void kernel_launch(void* const* d_in, const int* in_sizes, int n_in,
                              void* d_out, int out_size) {
    const float* x      = (const float*)d_in[0];
    const float* gn_w   = (const float*)d_in[1];
    const float* gn_b   = (const float*)d_in[2];
    const float* w_qkv  = (const float*)d_in[3];
    const float* w_proj = (const float*)d_in[4];
    const float* b_proj = (const float*)d_in[5];
    float* out = (float*)d_out;

    float* qkv;    cudaGetSymbolAddress((void**)&qkv,    g_qkv);
    float* attout; cudaGetSymbolAddress((void**)&attout, g_attout);

    // K1: groupnorm stats
    gn_stats_kernel<<<BB * NG, 256>>>(x, gn_w, gn_b);

    // K2: QKV projection (HMMA bf16-split, fused groupnorm)
    {
        dim3 grid(HW / 128, (3 * CC) / 128, BB);
        gemm_mma<<<grid, 256>>>(w_qkv, x, qkv, 3 * CC, nullptr, 1);
    }

    // K3: K-row max / expsum
    rowstats_kernel<<<BB * CC, 256>>>();

    // K4: partial att = exp(K-max) @ V^T, split over n
    {
        dim3 grid(SPLIT, BB * NH);
        att_kv_part_kernel<<<grid, 256>>>();
    }
    att_reduce_kernel<<<BB * NH, 256>>>();

    // K5: out = att^T @ Q
    {
        dim3 grid(HW / 256, BB * NH);
        att_q_kernel<<<grid, 256>>>();
    }

    // K6: output projection + bias (HMMA)
    {
        dim3 grid(HW / 128, CC / 128, BB);
        gemm_mma<<<grid, 256>>>(w_proj, attout, out, CC, b_proj, 0);
    }
}

// round 4
// speedup vs baseline: 2.1479x; 1.0093x over previous
#include <cuda_runtime.h>
#include <cuda_bf16.h>
#include <cstdint>

#define BB 16
#define CC 256
#define HW 4096
#define NH 8
#define HD 32
#define NG 32
#define CPG 8
#define EPSV 1e-5f
#define SPLIT 32           // n-splits for att_kv (slice = 128)
#define SLICE (HW / SPLIT)

// ---------------- scratch (device globals) ----------------------------------
__device__ __nv_bfloat16 g_xh[(size_t)BB * CC * HW];     // normed x hi
__device__ __nv_bfloat16 g_xl[(size_t)BB * CC * HW];     // normed x lo
__device__ __nv_bfloat16 g_wqh[3 * CC * CC];             // w_qkv hi
__device__ __nv_bfloat16 g_wql[3 * CC * CC];             // w_qkv lo
__device__ __nv_bfloat16 g_qh[(size_t)BB * CC * HW];     // Q hi
__device__ __nv_bfloat16 g_ql[(size_t)BB * CC * HW];     // Q lo
__device__ float g_kv[(size_t)BB * 2 * CC * HW];         // K,V fp32 (134 MB)
__device__ float g_att_part[(size_t)SPLIT * BB * NH * HD * HD];
__device__ float g_lmax[SPLIT * BB * NH * HD];
__device__ float g_lsum[SPLIT * BB * NH * HD];
__device__ float g_att[(size_t)BB * NH * HD * HD];
__device__ __nv_bfloat16 g_weffh[(size_t)BB * CC * CC];
__device__ __nv_bfloat16 g_weffl[(size_t)BB * CC * CC];
__device__ float g_scale[BB * CC];
__device__ float g_shift[BB * CC];

// ---------------- warp-MMA helpers ------------------------------------------
__device__ __forceinline__ uint32_t smem_u32(const void* p) {
    uint32_t a;
    asm("{ .reg .u64 t; cvta.to.shared.u64 t, %1; cvt.u32.u64 %0, t; }"
        : "=r"(a) : "l"(p));
    return a;
}
__device__ __forceinline__ void ldmx4(uint32_t* r, uint32_t addr) {
    asm volatile("ldmatrix.sync.aligned.m8n8.x4.shared.b16 {%0,%1,%2,%3}, [%4];"
                 : "=r"(r[0]), "=r"(r[1]), "=r"(r[2]), "=r"(r[3]) : "r"(addr));
}
__device__ __forceinline__ void ldmx4t(uint32_t* r, uint32_t addr) {
    asm volatile("ldmatrix.sync.aligned.m8n8.x4.trans.shared.b16 {%0,%1,%2,%3}, [%4];"
                 : "=r"(r[0]), "=r"(r[1]), "=r"(r[2]), "=r"(r[3]) : "r"(addr));
}
__device__ __forceinline__ void mma_bf16(float* c, const uint32_t* a, const uint32_t* b) {
    asm volatile("mma.sync.aligned.m16n8k16.row.col.f32.bf16.bf16.f32 "
                 "{%0,%1,%2,%3}, {%4,%5,%6,%7}, {%8,%9}, {%0,%1,%2,%3};"
                 : "+f"(c[0]), "+f"(c[1]), "+f"(c[2]), "+f"(c[3])
                 : "r"(a[0]), "r"(a[1]), "r"(a[2]), "r"(a[3]),
                   "r"(b[0]), "r"(b[1]));
}
__device__ __forceinline__ uint32_t pk2(__nv_bfloat16 a, __nv_bfloat16 b) {
    __nv_bfloat162 t = __halves2bfloat162(a, b);
    return *(uint32_t*)&t;
}

#define AST 40    // A smem row stride (bf16): 80B rows, 16B-aligned, ldsm conflict-free
#define BST 136   // B smem row stride: 272B rows

// ---------------------------------------------------------------------------
// K1: GroupNorm statistics
// ---------------------------------------------------------------------------
__global__ void gn_stats_kernel(const float* __restrict__ x,
                                const float* __restrict__ gw,
                                const float* __restrict__ gb) {
    const int b = blockIdx.x / NG;
    const int g = blockIdx.x % NG;
    const float* xp = x + ((size_t)b * CC + (size_t)g * CPG) * HW;

    float s = 0.f, s2 = 0.f;
    for (int i = threadIdx.x; i < CPG * HW; i += blockDim.x) {
        float v = xp[i];
        s += v; s2 += v * v;
    }
    __shared__ float rs[32], rs2[32];
    #pragma unroll
    for (int o = 16; o > 0; o >>= 1) {
        s  += __shfl_down_sync(0xFFFFFFFFu, s,  o);
        s2 += __shfl_down_sync(0xFFFFFFFFu, s2, o);
    }
    int lane = threadIdx.x & 31, wid = threadIdx.x >> 5;
    if (lane == 0) { rs[wid] = s; rs2[wid] = s2; }
    __syncthreads();
    if (wid == 0) {
        int nw = blockDim.x >> 5;
        s  = (lane < nw) ? rs[lane]  : 0.f;
        s2 = (lane < nw) ? rs2[lane] : 0.f;
        #pragma unroll
        for (int o = 16; o > 0; o >>= 1) {
            s  += __shfl_down_sync(0xFFFFFFFFu, s,  o);
            s2 += __shfl_down_sync(0xFFFFFFFFu, s2, o);
        }
        if (lane == 0) { rs[0] = s; rs2[0] = s2; }
    }
    __syncthreads();
    const float inv_n = 1.f / (float)(CPG * HW);
    float mu  = rs[0] * inv_n;
    float var = rs2[0] * inv_n - mu * mu;
    float rstd = rsqrtf(var + EPSV);
    if (threadIdx.x < CPG) {
        int c = g * CPG + threadIdx.x;
        float sc = rstd * gw[c];
        g_scale[b * CC + c] = sc;
        g_shift[b * CC + c] = gb[c] - mu * sc;
    }
}

// ---------------------------------------------------------------------------
// K1b: apply norm + bf16 hi/lo split of x  (one block per (b,c) row)
// ---------------------------------------------------------------------------
__global__ __launch_bounds__(256) void prep_x_kernel(const float* __restrict__ x) {
    const int bc = blockIdx.x;                  // b*CC + c
    const float sc = g_scale[bc], sh = g_shift[bc];
    const float* xp = x + (size_t)bc * HW;
    __nv_bfloat16* xh = g_xh + (size_t)bc * HW;
    __nv_bfloat16* xl = g_xl + (size_t)bc * HW;
    #pragma unroll
    for (int it = 0; it < 4; it++) {
        int i = (it * 256 + threadIdx.x) * 4;
        float4 v = *(const float4*)(xp + i);
        v.x = fmaf(v.x, sc, sh); v.y = fmaf(v.y, sc, sh);
        v.z = fmaf(v.z, sc, sh); v.w = fmaf(v.w, sc, sh);
        __nv_bfloat16 h0 = __float2bfloat16(v.x), h1 = __float2bfloat16(v.y);
        __nv_bfloat16 h2 = __float2bfloat16(v.z), h3 = __float2bfloat16(v.w);
        __nv_bfloat16 l0 = __float2bfloat16(v.x - __bfloat162float(h0));
        __nv_bfloat16 l1 = __float2bfloat16(v.y - __bfloat162float(h1));
        __nv_bfloat16 l2 = __float2bfloat16(v.z - __bfloat162float(h2));
        __nv_bfloat16 l3 = __float2bfloat16(v.w - __bfloat162float(h3));
        *(uint2*)(xh + i) = make_uint2(pk2(h0, h1), pk2(h2, h3));
        *(uint2*)(xl + i) = make_uint2(pk2(l0, l1), pk2(l2, l3));
    }
}

// K1c: split w_qkv to bf16 hi/lo (768x256)
__global__ __launch_bounds__(256) void prep_w_kernel(const float* __restrict__ w) {
    int i = (blockIdx.x * 256 + threadIdx.x) * 4;
    float4 v = *(const float4*)(w + i);
    __nv_bfloat16 h0 = __float2bfloat16(v.x), h1 = __float2bfloat16(v.y);
    __nv_bfloat16 h2 = __float2bfloat16(v.z), h3 = __float2bfloat16(v.w);
    __nv_bfloat16 l0 = __float2bfloat16(v.x - __bfloat162float(h0));
    __nv_bfloat16 l1 = __float2bfloat16(v.y - __bfloat162float(h1));
    __nv_bfloat16 l2 = __float2bfloat16(v.z - __bfloat162float(h2));
    __nv_bfloat16 l3 = __float2bfloat16(v.w - __bfloat162float(h3));
    *(uint2*)(g_wqh + i) = make_uint2(pk2(h0, h1), pk2(h2, h3));
    *(uint2*)(g_wql + i) = make_uint2(pk2(l0, l1), pk2(l2, l3));
}

// ---------------------------------------------------------------------------
// K2/K6: HMMA GEMM on pre-split bf16.  C = A(hi+lo) * B(hi+lo), 3-term.
//   mode 0: fp32 out + bias (proj).  mode 1: QKV epilogue (Q->bf16, K/V->fp32)
// ---------------------------------------------------------------------------
__global__ __launch_bounds__(256)
void gemm_bf16(const __nv_bfloat16* __restrict__ Ah,
               const __nv_bfloat16* __restrict__ Al, size_t aStride,
               const __nv_bfloat16* __restrict__ Bh,
               const __nv_bfloat16* __restrict__ Bl,
               int M, int mode, const float* __restrict__ bias,
               float* __restrict__ Cout) {
    __shared__ __nv_bfloat16 sAh[128 * AST];
    __shared__ __nv_bfloat16 sAl[128 * AST];
    __shared__ __nv_bfloat16 sBh[32 * BST];
    __shared__ __nv_bfloat16 sBl[32 * BST];

    const int tid = threadIdx.x;
    const int wid = tid >> 5, lane = tid & 31;
    const int wM = wid >> 1, wN = wid & 1;
    const int b  = blockIdx.z;
    const int m0 = blockIdx.y * 128;
    const int n0 = blockIdx.x * 128;

    const __nv_bfloat16* Ahb = Ah + (size_t)b * aStride;
    const __nv_bfloat16* Alb = Al + (size_t)b * aStride;

    const uint32_t aHB = smem_u32(sAh), aLB = smem_u32(sAl);
    const uint32_t bHB = smem_u32(sBh), bLB = smem_u32(sBl);

    float acc[2][8][4];
    #pragma unroll
    for (int i = 0; i < 2; i++)
        #pragma unroll
        for (int j = 0; j < 8; j++)
            #pragma unroll
            for (int q = 0; q < 4; q++) acc[i][j][q] = 0.f;

    const int lt = lane >> 3, lr = lane & 7;
    const int aRow = lr + ((lt & 1) ? 8 : 0);
    const int aKof = (lt & 2) ? 8 : 0;
    const int bKof = lr + ((lt & 1) ? 8 : 0);
    const int bNof = (lt & 2) ? 8 : 0;

    for (int k0 = 0; k0 < CC; k0 += 32) {
        #pragma unroll
        for (int it = 0; it < 2; it++) {      // A: 512 uint4 per buffer
            int idx = it * 256 + tid;
            int row = idx >> 2, q4 = (idx & 3) * 8;
            *(uint4*)&sAh[row * AST + q4] =
                *(const uint4*)(Ahb + (size_t)(m0 + row) * CC + k0 + q4);
            *(uint4*)&sAl[row * AST + q4] =
                *(const uint4*)(Alb + (size_t)(m0 + row) * CC + k0 + q4);
        }
        #pragma unroll
        for (int it = 0; it < 2; it++) {      // B: 512 uint4 per buffer
            int idx = it * 256 + tid;
            int row = idx >> 4, q4 = (idx & 15) * 8;
            size_t g = ((size_t)b * CC + k0 + row) * HW + n0 + q4;
            *(uint4*)&sBh[row * BST + q4] = *(const uint4*)(Bh + g);
            *(uint4*)&sBl[row * BST + q4] = *(const uint4*)(Bl + g);
        }
        __syncthreads();

        #pragma unroll
        for (int ks = 0; ks < 2; ks++) {
            const int kb = ks * 16;
            uint32_t ah[2][4], al[2][4], bh[8][2], bl[8][2];
            #pragma unroll
            for (int mt = 0; mt < 2; mt++) {
                uint32_t ad = ((wM * 32 + mt * 16 + aRow) * AST + kb + aKof) * 2;
                ldmx4(ah[mt], aHB + ad);
                ldmx4(al[mt], aLB + ad);
            }
            #pragma unroll
            for (int np = 0; np < 4; np++) {
                uint32_t bd = ((kb + bKof) * BST + wN * 64 + np * 16 + bNof) * 2;
                uint32_t r[4];
                ldmx4t(r, bHB + bd);
                bh[np * 2][0] = r[0]; bh[np * 2][1] = r[1];
                bh[np * 2 + 1][0] = r[2]; bh[np * 2 + 1][1] = r[3];
                ldmx4t(r, bLB + bd);
                bl[np * 2][0] = r[0]; bl[np * 2][1] = r[1];
                bl[np * 2 + 1][0] = r[2]; bl[np * 2 + 1][1] = r[3];
            }
            #pragma unroll
            for (int mt = 0; mt < 2; mt++)
                #pragma unroll
                for (int nt = 0; nt < 8; nt++) {
                    mma_bf16(acc[mt][nt], ah[mt], bh[nt]);
                    mma_bf16(acc[mt][nt], ah[mt], bl[nt]);
                    mma_bf16(acc[mt][nt], al[mt], bh[nt]);
                }
        }
        __syncthreads();
    }

    const int rbase = m0 + wM * 32 + (lane >> 2);
    const int cbase = n0 + wN * 64 + (lane & 3) * 2;

    if (mode == 0) {
        #pragma unroll
        for (int mt = 0; mt < 2; mt++) {
            int r0 = rbase + mt * 16;
            float bi0 = bias ? bias[r0] : 0.f;
            float bi1 = bias ? bias[r0 + 8] : 0.f;
            #pragma unroll
            for (int nt = 0; nt < 8; nt++) {
                int cc = cbase + nt * 8;
                *(float2*)(Cout + ((size_t)b * M + r0) * HW + cc) =
                    make_float2(acc[mt][nt][0] + bi0, acc[mt][nt][1] + bi0);
                *(float2*)(Cout + ((size_t)b * M + r0 + 8) * HW + cc) =
                    make_float2(acc[mt][nt][2] + bi1, acc[mt][nt][3] + bi1);
            }
        }
    } else {
        #pragma unroll
        for (int mt = 0; mt < 2; mt++) {
            #pragma unroll
            for (int half = 0; half < 2; half++) {
                int r = rbase + mt * 16 + half * 8;
                #pragma unroll
                for (int nt = 0; nt < 8; nt++) {
                    int cc = cbase + nt * 8;
                    float v0 = acc[mt][nt][half * 2 + 0];
                    float v1 = acc[mt][nt][half * 2 + 1];
                    if (r < 256) {            // Q -> bf16 hi/lo
                        __nv_bfloat16 h0 = __float2bfloat16(v0);
                        __nv_bfloat16 h1 = __float2bfloat16(v1);
                        __nv_bfloat16 l0 = __float2bfloat16(v0 - __bfloat162float(h0));
                        __nv_bfloat16 l1 = __float2bfloat16(v1 - __bfloat162float(h1));
                        size_t g = ((size_t)b * CC + r) * HW + cc;
                        *(uint32_t*)(g_qh + g) = pk2(h0, h1);
                        *(uint32_t*)(g_ql + g) = pk2(l0, l1);
                    } else {                  // K,V -> fp32
                        int kv = (r >= 512);
                        int ch = r - (kv ? 512 : 256);
                        *(float2*)(g_kv + ((size_t)(b * 2 + kv) * CC + ch) * HW + cc) =
                            make_float2(v0, v1);
                    }
                }
            }
        }
    }
}

// ---------------------------------------------------------------------------
// K3: att_kv online: per split s, local max/expsum + partial exp(K)@V^T
// ---------------------------------------------------------------------------
__global__ __launch_bounds__(256) void att_kv_online() {
    __shared__ float sk[HD][SLICE + 1];   // 32 x 129
    __shared__ float sv[HD][SLICE + 1];
    __shared__ float smax[HD], ssum[HD];

    const int s  = blockIdx.x;
    const int bh = blockIdx.y;
    const int b = bh >> 3, h = bh & 7;
    const size_t kb = ((size_t)(b * 2 + 0) * CC + h * HD) * HW + s * SLICE;
    const size_t vb = ((size_t)(b * 2 + 1) * CC + h * HD) * HW + s * SLICE;

    const int t = threadIdx.x;
    const int row = t >> 3, seg = t & 7;  // 8 threads per row, 16 cols each

    #pragma unroll
    for (int i = 0; i < 4; i++) {
        int col = seg * 16 + i * 4;
        float4 k4 = *(const float4*)(g_kv + kb + (size_t)row * HW + col);
        float4 v4 = *(const float4*)(g_kv + vb + (size_t)row * HW + col);
        sk[row][col + 0] = k4.x; sk[row][col + 1] = k4.y;
        sk[row][col + 2] = k4.z; sk[row][col + 3] = k4.w;
        sv[row][col + 0] = v4.x; sv[row][col + 1] = v4.y;
        sv[row][col + 2] = v4.z; sv[row][col + 3] = v4.w;
    }
    __syncthreads();

    // local max per row (octet reduce)
    float m = -3.4e38f;
    #pragma unroll
    for (int i = 0; i < 16; i++) m = fmaxf(m, sk[row][seg * 16 + i]);
    #pragma unroll
    for (int o = 1; o < 8; o <<= 1)
        m = fmaxf(m, __shfl_xor_sync(0xFFFFFFFFu, m, o));
    if (seg == 0) smax[row] = m;
    __syncthreads();

    const float rm = smax[row];
    float sum = 0.f;
    #pragma unroll
    for (int i = 0; i < 16; i++) {
        int c = seg * 16 + i;
        float e = __expf(sk[row][c] - rm);
        sk[row][c] = e;
        sum += e;
    }
    #pragma unroll
    for (int o = 1; o < 8; o <<= 1)
        sum += __shfl_xor_sync(0xFFFFFFFFu, sum, o);
    if (seg == 0) ssum[row] = sum;
    __syncthreads();

    // 2x2 output tile per thread
    const int d0 = (t >> 4) * 2, e0 = (t & 15) * 2;
    float a00 = 0.f, a01 = 0.f, a10 = 0.f, a11 = 0.f;
    #pragma unroll 4
    for (int j = 0; j < SLICE; j++) {
        float k0v = sk[d0][j], k1v = sk[d0 + 1][j];
        float v0v = sv[e0][j], v1v = sv[e0 + 1][j];
        a00 = fmaf(k0v, v0v, a00);
        a01 = fmaf(k0v, v1v, a01);
        a10 = fmaf(k1v, v0v, a10);
        a11 = fmaf(k1v, v1v, a11);
    }
    float* P = g_att_part + ((size_t)s * (BB * NH) + bh) * (HD * HD);
    P[d0 * HD + e0]           = a00;
    P[d0 * HD + e0 + 1]       = a01;
    P[(d0 + 1) * HD + e0]     = a10;
    P[(d0 + 1) * HD + e0 + 1] = a11;
    if (t < HD) {
        g_lmax[(s * (BB * NH) + bh) * HD + t] = smax[t];
        g_lsum[(s * (BB * NH) + bh) * HD + t] = ssum[t];
    }
}

// K3b: combine splits: att = (sum_s P_s * exp(lmax_s - gmax)) / denom
__global__ __launch_bounds__(256) void att_reduce_kernel() {
    const int bh = blockIdx.x;
    __shared__ float sfac[SPLIT][HD];
    __shared__ float sdinv[HD];
    const int t = threadIdx.x;

    if (t < HD) {
        float gm = -3.4e38f;
        #pragma unroll 4
        for (int s = 0; s < SPLIT; s++)
            gm = fmaxf(gm, g_lmax[(s * (BB * NH) + bh) * HD + t]);
        float den = 0.f;
        #pragma unroll 4
        for (int s = 0; s < SPLIT; s++) {
            float f = __expf(g_lmax[(s * (BB * NH) + bh) * HD + t] - gm);
            sfac[s][t] = f;
            den += g_lsum[(s * (BB * NH) + bh) * HD + t] * f;
        }
        sdinv[t] = 1.f / den;
    }
    __syncthreads();

    #pragma unroll
    for (int idx = t; idx < HD * HD; idx += 256) {
        int d = idx >> 5;
        float acc = 0.f;
        #pragma unroll 4
        for (int s = 0; s < SPLIT; s++)
            acc = fmaf(g_att_part[((size_t)s * (BB * NH) + bh) * (HD * HD) + idx],
                       sfac[s][d], acc);
        g_att[(size_t)bh * (HD * HD) + idx] = acc * sdinv[d];
    }
}

// ---------------------------------------------------------------------------
// K4: fold att into proj weights: Weff[b][o][h*32+d] = sum_e Wp[o][h*32+e]*att[b,h,d,e]
// ---------------------------------------------------------------------------
__global__ __launch_bounds__(256) void weff_kernel(const float* __restrict__ wp) {
    const int b = blockIdx.x;
    __shared__ float satt[NH][HD][HD];      // 32 KB
    const int t = threadIdx.x;
    for (int i = t; i < NH * HD * HD; i += 256)
        ((float*)satt)[i] = g_att[(size_t)b * NH * HD * HD + i];
    __syncthreads();

    const int o = t;
    const float* wrow = wp + (size_t)o * CC;
    __nv_bfloat16* wh = g_weffh + ((size_t)b * CC + o) * CC;
    __nv_bfloat16* wl = g_weffl + ((size_t)b * CC + o) * CC;
    #pragma unroll
    for (int h = 0; h < NH; h++) {
        float wreg[HD];
        #pragma unroll
        for (int e = 0; e < HD; e++) wreg[e] = wrow[h * HD + e];
        #pragma unroll 2
        for (int d = 0; d < HD; d++) {
            float s = 0.f;
            #pragma unroll
            for (int e = 0; e < HD; e++)
                s = fmaf(wreg[e], satt[h][d][e], s);
            __nv_bfloat16 hh = __float2bfloat16(s);
            __nv_bfloat16 ll = __float2bfloat16(s - __bfloat162float(hh));
            wh[h * HD + d] = hh;
            wl[h * HD + d] = ll;
        }
    }
}

// ---------------------------------------------------------------------------
extern "C" void kernel_launch(void* const* d_in, const int* in_sizes, int n_in,
                              void* d_out, int out_size) {
    const float* x      = (const float*)d_in[0];
    const float* gn_w   = (const float*)d_in[1];
    const float* gn_b   = (const float*)d_in[2];
    const float* w_qkv  = (const float*)d_in[3];
    const float* w_proj = (const float*)d_in[4];
    const float* b_proj = (const float*)d_in[5];
    float* out = (float*)d_out;

    __nv_bfloat16 *xh, *xl, *wqh, *wql, *qh, *ql, *wfh, *wfl;
    cudaGetSymbolAddress((void**)&xh,  g_xh);
    cudaGetSymbolAddress((void**)&xl,  g_xl);
    cudaGetSymbolAddress((void**)&wqh, g_wqh);
    cudaGetSymbolAddress((void**)&wql, g_wql);
    cudaGetSymbolAddress((void**)&qh,  g_qh);
    cudaGetSymbolAddress((void**)&ql,  g_ql);
    cudaGetSymbolAddress((void**)&wfh, g_weffh);
    cudaGetSymbolAddress((void**)&wfl, g_weffl);

    // K1: groupnorm stats, then apply+split; split weights
    gn_stats_kernel<<<BB * NG, 256>>>(x, gn_w, gn_b);
    prep_x_kernel<<<BB * CC, 256>>>(x);
    prep_w_kernel<<<(3 * CC * CC) / 1024, 256>>>(w_qkv);

    // K2: QKV projection (Q -> bf16 hi/lo, K/V -> fp32)
    {
        dim3 grid(HW / 128, (3 * CC) / 128, BB);
        gemm_bf16<<<grid, 256>>>(wqh, wql, 0, xh, xl, 3 * CC, 1, nullptr, nullptr);
    }

    // K3: online softmax-weighted K@V^T partials + reduce
    {
        dim3 grid(SPLIT, BB * NH);
        att_kv_online<<<grid, 256>>>();
    }
    att_reduce_kernel<<<BB * NH, 256>>>();

    // K4: fold att into proj weights
    weff_kernel<<<BB, 256>>>(w_proj);

    // K5: out = Weff[b] @ Q + bias
    {
        dim3 grid(HW / 128, CC / 128, BB);
        gemm_bf16<<<grid, 256>>>(wfh, wfl, (size_t)CC * CC, qh, ql, CC, 0, b_proj, out);
    }
}

// round 5
// speedup vs baseline: 2.2339x; 1.0401x over previous
#include <cuda_runtime.h>
#include <cuda_bf16.h>
#include <cstdint>

#define BB 16
#define CC 256
#define HW 4096
#define NH 8
#define HD 32
#define NG 32
#define CPG 8
#define EPSV 1e-5f
#define SPLIT 32           // n-splits for att_kv (slice = 128)
#define SLICE (HW / SPLIT)

// ---------------- scratch (device globals) ----------------------------------
__device__ __nv_bfloat16 g_xh[(size_t)BB * CC * HW];     // normed x hi
__device__ __nv_bfloat16 g_xl[(size_t)BB * CC * HW];     // normed x lo
__device__ __nv_bfloat16 g_wqh[3 * CC * CC];             // w_qkv hi
__device__ __nv_bfloat16 g_wql[3 * CC * CC];             // w_qkv lo
__device__ __nv_bfloat16 g_qh[(size_t)BB * CC * HW];     // Q hi
__device__ __nv_bfloat16 g_ql[(size_t)BB * CC * HW];     // Q lo
__device__ float g_kv[(size_t)BB * 2 * CC * HW];         // K,V fp32 (134 MB)
__device__ float g_att_part[(size_t)SPLIT * BB * NH * HD * HD];
__device__ float g_lmax[SPLIT * BB * NH * HD];
__device__ float g_lsum[SPLIT * BB * NH * HD];
__device__ float g_att[(size_t)BB * NH * HD * HD];
__device__ __nv_bfloat16 g_weffh[(size_t)BB * CC * CC];
__device__ __nv_bfloat16 g_weffl[(size_t)BB * CC * CC];
__device__ float g_scale[BB * CC];
__device__ float g_shift[BB * CC];

// ---------------- warp-MMA helpers ------------------------------------------
__device__ __forceinline__ uint32_t smem_u32(const void* p) {
    uint32_t a;
    asm("{ .reg .u64 t; cvta.to.shared.u64 t, %1; cvt.u32.u64 %0, t; }"
        : "=r"(a) : "l"(p));
    return a;
}
__device__ __forceinline__ void ldmx4(uint32_t* r, uint32_t addr) {
    asm volatile("ldmatrix.sync.aligned.m8n8.x4.shared.b16 {%0,%1,%2,%3}, [%4];"
                 : "=r"(r[0]), "=r"(r[1]), "=r"(r[2]), "=r"(r[3]) : "r"(addr));
}
__device__ __forceinline__ void ldmx4t(uint32_t* r, uint32_t addr) {
    asm volatile("ldmatrix.sync.aligned.m8n8.x4.trans.shared.b16 {%0,%1,%2,%3}, [%4];"
                 : "=r"(r[0]), "=r"(r[1]), "=r"(r[2]), "=r"(r[3]) : "r"(addr));
}
__device__ __forceinline__ void mma_bf16(float* c, const uint32_t* a, const uint32_t* b) {
    asm volatile("mma.sync.aligned.m16n8k16.row.col.f32.bf16.bf16.f32 "
                 "{%0,%1,%2,%3}, {%4,%5,%6,%7}, {%8,%9}, {%0,%1,%2,%3};"
                 : "+f"(c[0]), "+f"(c[1]), "+f"(c[2]), "+f"(c[3])
                 : "r"(a[0]), "r"(a[1]), "r"(a[2]), "r"(a[3]),
                   "r"(b[0]), "r"(b[1]));
}
__device__ __forceinline__ uint32_t pk2(__nv_bfloat16 a, __nv_bfloat16 b) {
    __nv_bfloat162 t = __halves2bfloat162(a, b);
    return *(uint32_t*)&t;
}
__device__ __forceinline__ void cp16(uint32_t dst, const void* src) {
    asm volatile("cp.async.cg.shared.global [%0], [%1], 16;" :: "r"(dst), "l"(src));
}

#define AST 40    // A smem row stride (bf16): 80B rows
#define BST 136   // B smem row stride: 272B rows

// per-stage smem layout (bytes)
#define ST_AH 0
#define ST_AL 10240
#define ST_BH 20480
#define ST_BL 29184
#define ST_BYTES 37888
#define SMEM_GEMM (2 * ST_BYTES)

// ---------------------------------------------------------------------------
// K1: GroupNorm statistics
// ---------------------------------------------------------------------------
__global__ void gn_stats_kernel(const float* __restrict__ x,
                                const float* __restrict__ gw,
                                const float* __restrict__ gb) {
    const int b = blockIdx.x / NG;
    const int g = blockIdx.x % NG;
    const float* xp = x + ((size_t)b * CC + (size_t)g * CPG) * HW;

    float s = 0.f, s2 = 0.f;
    for (int i = threadIdx.x; i < CPG * HW; i += blockDim.x) {
        float v = xp[i];
        s += v; s2 += v * v;
    }
    __shared__ float rs[32], rs2[32];
    #pragma unroll
    for (int o = 16; o > 0; o >>= 1) {
        s  += __shfl_down_sync(0xFFFFFFFFu, s,  o);
        s2 += __shfl_down_sync(0xFFFFFFFFu, s2, o);
    }
    int lane = threadIdx.x & 31, wid = threadIdx.x >> 5;
    if (lane == 0) { rs[wid] = s; rs2[wid] = s2; }
    __syncthreads();
    if (wid == 0) {
        int nw = blockDim.x >> 5;
        s  = (lane < nw) ? rs[lane]  : 0.f;
        s2 = (lane < nw) ? rs2[lane] : 0.f;
        #pragma unroll
        for (int o = 16; o > 0; o >>= 1) {
            s  += __shfl_down_sync(0xFFFFFFFFu, s,  o);
            s2 += __shfl_down_sync(0xFFFFFFFFu, s2, o);
        }
        if (lane == 0) { rs[0] = s; rs2[0] = s2; }
    }
    __syncthreads();
    const float inv_n = 1.f / (float)(CPG * HW);
    float mu  = rs[0] * inv_n;
    float var = rs2[0] * inv_n - mu * mu;
    float rstd = rsqrtf(var + EPSV);
    if (threadIdx.x < CPG) {
        int c = g * CPG + threadIdx.x;
        float sc = rstd * gw[c];
        g_scale[b * CC + c] = sc;
        g_shift[b * CC + c] = gb[c] - mu * sc;
    }
}

// ---------------------------------------------------------------------------
// K1b: apply norm + bf16 hi/lo split of x
// ---------------------------------------------------------------------------
__global__ __launch_bounds__(256) void prep_x_kernel(const float* __restrict__ x) {
    const int bc = blockIdx.x;
    const float sc = g_scale[bc], sh = g_shift[bc];
    const float* xp = x + (size_t)bc * HW;
    __nv_bfloat16* xh = g_xh + (size_t)bc * HW;
    __nv_bfloat16* xl = g_xl + (size_t)bc * HW;
    #pragma unroll
    for (int it = 0; it < 4; it++) {
        int i = (it * 256 + threadIdx.x) * 4;
        float4 v = *(const float4*)(xp + i);
        v.x = fmaf(v.x, sc, sh); v.y = fmaf(v.y, sc, sh);
        v.z = fmaf(v.z, sc, sh); v.w = fmaf(v.w, sc, sh);
        __nv_bfloat16 h0 = __float2bfloat16(v.x), h1 = __float2bfloat16(v.y);
        __nv_bfloat16 h2 = __float2bfloat16(v.z), h3 = __float2bfloat16(v.w);
        __nv_bfloat16 l0 = __float2bfloat16(v.x - __bfloat162float(h0));
        __nv_bfloat16 l1 = __float2bfloat16(v.y - __bfloat162float(h1));
        __nv_bfloat16 l2 = __float2bfloat16(v.z - __bfloat162float(h2));
        __nv_bfloat16 l3 = __float2bfloat16(v.w - __bfloat162float(h3));
        *(uint2*)(xh + i) = make_uint2(pk2(h0, h1), pk2(h2, h3));
        *(uint2*)(xl + i) = make_uint2(pk2(l0, l1), pk2(l2, l3));
    }
}

// K1c: split w_qkv to bf16 hi/lo
__global__ __launch_bounds__(256) void prep_w_kernel(const float* __restrict__ w) {
    int i = (blockIdx.x * 256 + threadIdx.x) * 4;
    float4 v = *(const float4*)(w + i);
    __nv_bfloat16 h0 = __float2bfloat16(v.x), h1 = __float2bfloat16(v.y);
    __nv_bfloat16 h2 = __float2bfloat16(v.z), h3 = __float2bfloat16(v.w);
    __nv_bfloat16 l0 = __float2bfloat16(v.x - __bfloat162float(h0));
    __nv_bfloat16 l1 = __float2bfloat16(v.y - __bfloat162float(h1));
    __nv_bfloat16 l2 = __float2bfloat16(v.z - __bfloat162float(h2));
    __nv_bfloat16 l3 = __float2bfloat16(v.w - __bfloat162float(h3));
    *(uint2*)(g_wqh + i) = make_uint2(pk2(h0, h1), pk2(h2, h3));
    *(uint2*)(g_wql + i) = make_uint2(pk2(l0, l1), pk2(l2, l3));
}

// ---------------------------------------------------------------------------
// K2/K6: HMMA GEMM, 2-stage cp.async pipeline.
//   mode 0: fp32 out + bias (proj).  mode 1: QKV epilogue (Q->bf16, K/V->fp32)
// ---------------------------------------------------------------------------
__global__ __launch_bounds__(256)
void gemm_bf16(const __nv_bfloat16* __restrict__ Ah,
               const __nv_bfloat16* __restrict__ Al, size_t aStride,
               const __nv_bfloat16* __restrict__ Bh,
               const __nv_bfloat16* __restrict__ Bl,
               int M, int mode, const float* __restrict__ bias,
               float* __restrict__ Cout) {
    extern __shared__ char smem[];
    const uint32_t sb = smem_u32(smem);

    const int tid = threadIdx.x;
    const int wid = tid >> 5, lane = tid & 31;
    const int wM = wid >> 1, wN = wid & 1;
    const int b  = blockIdx.z;
    const int m0 = blockIdx.y * 128;
    const int n0 = blockIdx.x * 128;

    const __nv_bfloat16* Ahb = Ah + (size_t)b * aStride;
    const __nv_bfloat16* Alb = Al + (size_t)b * aStride;

    // per-thread load coordinates (2 chunks each for A and B, x hi/lo)
    const int aRowL0 = tid >> 2,            aQ4 = (tid & 3) * 8;
    const int bRowL0 = tid >> 4,            bQ4 = (tid & 15) * 8;

    auto issue = [&](int kc, int stage) {
        const uint32_t st = sb + stage * ST_BYTES;
        const int k0 = kc * 32;
        #pragma unroll
        for (int it = 0; it < 2; it++) {
            int row = aRowL0 + it * 64;
            const __nv_bfloat16* s0 = Ahb + (size_t)(m0 + row) * CC + k0 + aQ4;
            const __nv_bfloat16* s1 = Alb + (size_t)(m0 + row) * CC + k0 + aQ4;
            uint32_t d = (uint32_t)(row * AST + aQ4) * 2;
            cp16(st + ST_AH + d, s0);
            cp16(st + ST_AL + d, s1);
        }
        #pragma unroll
        for (int it = 0; it < 2; it++) {
            int row = bRowL0 + it * 16;
            size_t g = ((size_t)b * CC + k0 + row) * HW + n0 + bQ4;
            uint32_t d = (uint32_t)(row * BST + bQ4) * 2;
            cp16(st + ST_BH + d, Bh + g);
            cp16(st + ST_BL + d, Bl + g);
        }
        asm volatile("cp.async.commit_group;");
    };

    float acc[2][8][4];
    #pragma unroll
    for (int i = 0; i < 2; i++)
        #pragma unroll
        for (int j = 0; j < 8; j++)
            #pragma unroll
            for (int q = 0; q < 4; q++) acc[i][j][q] = 0.f;

    const int lt = lane >> 3, lr = lane & 7;
    const int aRow = lr + ((lt & 1) ? 8 : 0);
    const int aKof = (lt & 2) ? 8 : 0;
    const int bKof = lr + ((lt & 1) ? 8 : 0);
    const int bNof = (lt & 2) ? 8 : 0;

    issue(0, 0);

    for (int kc = 0; kc < 8; kc++) {
        const int stage = kc & 1;
        if (kc < 7) {
            issue(kc + 1, stage ^ 1);
            asm volatile("cp.async.wait_group 1;");
        } else {
            asm volatile("cp.async.wait_group 0;");
        }
        __syncthreads();

        const uint32_t aHB = sb + stage * ST_BYTES + ST_AH;
        const uint32_t aLB = sb + stage * ST_BYTES + ST_AL;
        const uint32_t bHB = sb + stage * ST_BYTES + ST_BH;
        const uint32_t bLB = sb + stage * ST_BYTES + ST_BL;

        #pragma unroll
        for (int ks = 0; ks < 2; ks++) {
            const int kb = ks * 16;
            uint32_t ah[2][4], al[2][4], bh[8][2], bl[8][2];
            #pragma unroll
            for (int mt = 0; mt < 2; mt++) {
                uint32_t ad = ((wM * 32 + mt * 16 + aRow) * AST + kb + aKof) * 2;
                ldmx4(ah[mt], aHB + ad);
                ldmx4(al[mt], aLB + ad);
            }
            #pragma unroll
            for (int np = 0; np < 4; np++) {
                uint32_t bd = ((kb + bKof) * BST + wN * 64 + np * 16 + bNof) * 2;
                uint32_t r[4];
                ldmx4t(r, bHB + bd);
                bh[np * 2][0] = r[0]; bh[np * 2][1] = r[1];
                bh[np * 2 + 1][0] = r[2]; bh[np * 2 + 1][1] = r[3];
                ldmx4t(r, bLB + bd);
                bl[np * 2][0] = r[0]; bl[np * 2][1] = r[1];
                bl[np * 2 + 1][0] = r[2]; bl[np * 2 + 1][1] = r[3];
            }
            #pragma unroll
            for (int mt = 0; mt < 2; mt++)
                #pragma unroll
                for (int nt = 0; nt < 8; nt++) {
                    mma_bf16(acc[mt][nt], ah[mt], bh[nt]);
                    mma_bf16(acc[mt][nt], ah[mt], bl[nt]);
                    mma_bf16(acc[mt][nt], al[mt], bh[nt]);
                }
        }
        __syncthreads();
    }

    const int rbase = m0 + wM * 32 + (lane >> 2);
    const int cbase = n0 + wN * 64 + (lane & 3) * 2;

    if (mode == 0) {
        #pragma unroll
        for (int mt = 0; mt < 2; mt++) {
            int r0 = rbase + mt * 16;
            float bi0 = bias ? bias[r0] : 0.f;
            float bi1 = bias ? bias[r0 + 8] : 0.f;
            #pragma unroll
            for (int nt = 0; nt < 8; nt++) {
                int cc = cbase + nt * 8;
                *(float2*)(Cout + ((size_t)b * M + r0) * HW + cc) =
                    make_float2(acc[mt][nt][0] + bi0, acc[mt][nt][1] + bi0);
                *(float2*)(Cout + ((size_t)b * M + r0 + 8) * HW + cc) =
                    make_float2(acc[mt][nt][2] + bi1, acc[mt][nt][3] + bi1);
            }
        }
    } else {
        #pragma unroll
        for (int mt = 0; mt < 2; mt++) {
            #pragma unroll
            for (int half = 0; half < 2; half++) {
                int r = rbase + mt * 16 + half * 8;
                #pragma unroll
                for (int nt = 0; nt < 8; nt++) {
                    int cc = cbase + nt * 8;
                    float v0 = acc[mt][nt][half * 2 + 0];
                    float v1 = acc[mt][nt][half * 2 + 1];
                    if (r < 256) {            // Q -> bf16 hi/lo
                        __nv_bfloat16 h0 = __float2bfloat16(v0);
                        __nv_bfloat16 h1 = __float2bfloat16(v1);
                        __nv_bfloat16 l0 = __float2bfloat16(v0 - __bfloat162float(h0));
                        __nv_bfloat16 l1 = __float2bfloat16(v1 - __bfloat162float(h1));
                        size_t g = ((size_t)b * CC + r) * HW + cc;
                        *(uint32_t*)(g_qh + g) = pk2(h0, h1);
                        *(uint32_t*)(g_ql + g) = pk2(l0, l1);
                    } else {                  // K,V -> fp32
                        int kv = (r >= 512);
                        int ch = r - (kv ? 512 : 256);
                        *(float2*)(g_kv + ((size_t)(b * 2 + kv) * CC + ch) * HW + cc) =
                            make_float2(v0, v1);
                    }
                }
            }
        }
    }
}

// ---------------------------------------------------------------------------
// K3: att_kv online: per split s, local max/expsum + partial exp(K)@V^T
// ---------------------------------------------------------------------------
__global__ __launch_bounds__(256) void att_kv_online() {
    __shared__ float sk[HD][SLICE + 1];
    __shared__ float sv[HD][SLICE + 1];
    __shared__ float smax[HD], ssum[HD];

    const int s  = blockIdx.x;
    const int bh = blockIdx.y;
    const int b = bh >> 3, h = bh & 7;
    const size_t kb = ((size_t)(b * 2 + 0) * CC + h * HD) * HW + s * SLICE;
    const size_t vb = ((size_t)(b * 2 + 1) * CC + h * HD) * HW + s * SLICE;

    const int t = threadIdx.x;
    const int row = t >> 3, seg = t & 7;

    #pragma unroll
    for (int i = 0; i < 4; i++) {
        int col = seg * 16 + i * 4;
        float4 k4 = *(const float4*)(g_kv + kb + (size_t)row * HW + col);
        float4 v4 = *(const float4*)(g_kv + vb + (size_t)row * HW + col);
        sk[row][col + 0] = k4.x; sk[row][col + 1] = k4.y;
        sk[row][col + 2] = k4.z; sk[row][col + 3] = k4.w;
        sv[row][col + 0] = v4.x; sv[row][col + 1] = v4.y;
        sv[row][col + 2] = v4.z; sv[row][col + 3] = v4.w;
    }
    __syncthreads();

    float m = -3.4e38f;
    #pragma unroll
    for (int i = 0; i < 16; i++) m = fmaxf(m, sk[row][seg * 16 + i]);
    #pragma unroll
    for (int o = 1; o < 8; o <<= 1)
        m = fmaxf(m, __shfl_xor_sync(0xFFFFFFFFu, m, o));
    if (seg == 0) smax[row] = m;
    __syncthreads();

    const float rm = smax[row];
    float sum = 0.f;
    #pragma unroll
    for (int i = 0; i < 16; i++) {
        int c = seg * 16 + i;
        float e = __expf(sk[row][c] - rm);
        sk[row][c] = e;
        sum += e;
    }
    #pragma unroll
    for (int o = 1; o < 8; o <<= 1)
        sum += __shfl_xor_sync(0xFFFFFFFFu, sum, o);
    if (seg == 0) ssum[row] = sum;
    __syncthreads();

    const int d0 = (t >> 4) * 2, e0 = (t & 15) * 2;
    float a00 = 0.f, a01 = 0.f, a10 = 0.f, a11 = 0.f;
    #pragma unroll 4
    for (int j = 0; j < SLICE; j++) {
        float k0v = sk[d0][j], k1v = sk[d0 + 1][j];
        float v0v = sv[e0][j], v1v = sv[e0 + 1][j];
        a00 = fmaf(k0v, v0v, a00);
        a01 = fmaf(k0v, v1v, a01);
        a10 = fmaf(k1v, v0v, a10);
        a11 = fmaf(k1v, v1v, a11);
    }
    float* P = g_att_part + ((size_t)s * (BB * NH) + bh) * (HD * HD);
    P[d0 * HD + e0]           = a00;
    P[d0 * HD + e0 + 1]       = a01;
    P[(d0 + 1) * HD + e0]     = a10;
    P[(d0 + 1) * HD + e0 + 1] = a11;
    if (t < HD) {
        g_lmax[(s * (BB * NH) + bh) * HD + t] = smax[t];
        g_lsum[(s * (BB * NH) + bh) * HD + t] = ssum[t];
    }
}

// K3b: combine splits
__global__ __launch_bounds__(256) void att_reduce_kernel() {
    const int bh = blockIdx.x;
    __shared__ float sfac[SPLIT][HD];
    __shared__ float sdinv[HD];
    const int t = threadIdx.x;

    if (t < HD) {
        float gm = -3.4e38f;
        #pragma unroll 4
        for (int s = 0; s < SPLIT; s++)
            gm = fmaxf(gm, g_lmax[(s * (BB * NH) + bh) * HD + t]);
        float den = 0.f;
        #pragma unroll 4
        for (int s = 0; s < SPLIT; s++) {
            float f = __expf(g_lmax[(s * (BB * NH) + bh) * HD + t] - gm);
            sfac[s][t] = f;
            den += g_lsum[(s * (BB * NH) + bh) * HD + t] * f;
        }
        sdinv[t] = 1.f / den;
    }
    __syncthreads();

    #pragma unroll
    for (int idx = t; idx < HD * HD; idx += 256) {
        int d = idx >> 5;
        float acc = 0.f;
        #pragma unroll 4
        for (int s = 0; s < SPLIT; s++)
            acc = fmaf(g_att_part[((size_t)s * (BB * NH) + bh) * (HD * HD) + idx],
                       sfac[s][d], acc);
        g_att[(size_t)bh * (HD * HD) + idx] = acc * sdinv[d];
    }
}

// ---------------------------------------------------------------------------
// K4: fold att into proj weights
// ---------------------------------------------------------------------------
__global__ __launch_bounds__(256) void weff_kernel(const float* __restrict__ wp) {
    const int b = blockIdx.x;
    __shared__ float satt[NH][HD][HD];
    const int t = threadIdx.x;
    for (int i = t; i < NH * HD * HD; i += 256)
        ((float*)satt)[i] = g_att[(size_t)b * NH * HD * HD + i];
    __syncthreads();

    const int o = t;
    const float* wrow = wp + (size_t)o * CC;
    __nv_bfloat16* wh = g_weffh + ((size_t)b * CC + o) * CC;
    __nv_bfloat16* wl = g_weffl + ((size_t)b * CC + o) * CC;
    #pragma unroll
    for (int h = 0; h < NH; h++) {
        float wreg[HD];
        #pragma unroll
        for (int e = 0; e < HD; e++) wreg[e] = wrow[h * HD + e];
        #pragma unroll 2
        for (int d = 0; d < HD; d++) {
            float s = 0.f;
            #pragma unroll
            for (int e = 0; e < HD; e++)
                s = fmaf(wreg[e], satt[h][d][e], s);
            __nv_bfloat16 hh = __float2bfloat16(s);
            __nv_bfloat16 ll = __float2bfloat16(s - __bfloat162float(hh));
            wh[h * HD + d] = hh;
            wl[h * HD + d] = ll;
        }
    }
}

// ---------------------------------------------------------------------------
extern "C" void kernel_launch(void* const* d_in, const int* in_sizes, int n_in,
                              void* d_out, int out_size) {
    const float* x      = (const float*)d_in[0];
    const float* gn_w   = (const float*)d_in[1];
    const float* gn_b   = (const float*)d_in[2];
    const float* w_qkv  = (const float*)d_in[3];
    const float* w_proj = (const float*)d_in[4];
    const float* b_proj = (const float*)d_in[5];
    float* out = (float*)d_out;

    __nv_bfloat16 *xh, *xl, *wqh, *wql, *qh, *ql, *wfh, *wfl;
    cudaGetSymbolAddress((void**)&xh,  g_xh);
    cudaGetSymbolAddress((void**)&xl,  g_xl);
    cudaGetSymbolAddress((void**)&wqh, g_wqh);
    cudaGetSymbolAddress((void**)&wql, g_wql);
    cudaGetSymbolAddress((void**)&qh,  g_qh);
    cudaGetSymbolAddress((void**)&ql,  g_ql);
    cudaGetSymbolAddress((void**)&wfh, g_weffh);
    cudaGetSymbolAddress((void**)&wfl, g_weffl);

    cudaFuncSetAttribute(gemm_bf16, cudaFuncAttributeMaxDynamicSharedMemorySize,
                         SMEM_GEMM);

    // K1: groupnorm stats, then apply+split; split weights
    gn_stats_kernel<<<BB * NG, 256>>>(x, gn_w, gn_b);
    prep_x_kernel<<<BB * CC, 256>>>(x);
    prep_w_kernel<<<(3 * CC * CC) / 1024, 256>>>(w_qkv);

    // K2: QKV projection (Q -> bf16 hi/lo, K/V -> fp32)
    {
        dim3 grid(HW / 128, (3 * CC) / 128, BB);
        gemm_bf16<<<grid, 256, SMEM_GEMM>>>(wqh, wql, 0, xh, xl, 3 * CC, 1,
                                            nullptr, nullptr);
    }

    // K3: online softmax-weighted K@V^T partials + reduce
    {
        dim3 grid(SPLIT, BB * NH);
        att_kv_online<<<grid, 256>>>();
    }
    att_reduce_kernel<<<BB * NH, 256>>>();

    // K4: fold att into proj weights
    weff_kernel<<<BB, 256>>>(w_proj);

    // K5: out = Weff[b] @ Q + bias
    {
        dim3 grid(HW / 128, CC / 128, BB);
        gemm_bf16<<<grid, 256, SMEM_GEMM>>>(wfh, wfl, (size_t)CC * CC, qh, ql,
                                            CC, 0, b_proj, out);
    }
}

// round 6
// speedup vs baseline: 2.6867x; 1.2027x over previous
#include <cuda_runtime.h>
#include <cuda_bf16.h>
#include <cstdint>

#define BB 16
#define CC 256
#define HW 4096
#define NH 8
#define HD 32
#define NG 32
#define CPG 8
#define EPSV 1e-5f
#define SPLIT 32           // n-splits for att_kv (slice = 128)
#define SLICE (HW / SPLIT)
#define SKST 132           // att_kv smem row stride (floats)

// ---------------- scratch (device globals) ----------------------------------
__device__ __nv_bfloat16 g_xh[(size_t)BB * CC * HW];     // normed x hi
__device__ __nv_bfloat16 g_xl[(size_t)BB * CC * HW];     // normed x lo
__device__ __nv_bfloat16 g_wqh[2 * CC * CC];             // w_qkv K,V rows hi
__device__ __nv_bfloat16 g_wql[2 * CC * CC];             // w_qkv K,V rows lo
__device__ float g_kv[(size_t)BB * 2 * CC * HW];         // K,V fp32 (134 MB)
__device__ float g_att_part[(size_t)SPLIT * BB * NH * HD * HD];
__device__ float g_lmax[SPLIT * BB * NH * HD];
__device__ float g_lsum[SPLIT * BB * NH * HD];
__device__ float g_att[(size_t)BB * NH * HD * HD];
__device__ float g_weff[(size_t)BB * CC * CC];           // Wp . att  (fp32)
__device__ __nv_bfloat16 g_w2h[(size_t)BB * CC * CC];    // W2 hi
__device__ __nv_bfloat16 g_w2l[(size_t)BB * CC * CC];    // W2 lo
__device__ float g_scale[BB * CC];
__device__ float g_shift[BB * CC];

// ---------------- warp-MMA helpers ------------------------------------------
__device__ __forceinline__ uint32_t smem_u32(const void* p) {
    uint32_t a;
    asm("{ .reg .u64 t; cvta.to.shared.u64 t, %1; cvt.u32.u64 %0, t; }"
        : "=r"(a) : "l"(p));
    return a;
}
__device__ __forceinline__ void ldmx4(uint32_t* r, uint32_t addr) {
    asm volatile("ldmatrix.sync.aligned.m8n8.x4.shared.b16 {%0,%1,%2,%3}, [%4];"
                 : "=r"(r[0]), "=r"(r[1]), "=r"(r[2]), "=r"(r[3]) : "r"(addr));
}
__device__ __forceinline__ void ldmx4t(uint32_t* r, uint32_t addr) {
    asm volatile("ldmatrix.sync.aligned.m8n8.x4.trans.shared.b16 {%0,%1,%2,%3}, [%4];"
                 : "=r"(r[0]), "=r"(r[1]), "=r"(r[2]), "=r"(r[3]) : "r"(addr));
}
__device__ __forceinline__ void mma_bf16(float* c, const uint32_t* a, const uint32_t* b) {
    asm volatile("mma.sync.aligned.m16n8k16.row.col.f32.bf16.bf16.f32 "
                 "{%0,%1,%2,%3}, {%4,%5,%6,%7}, {%8,%9}, {%0,%1,%2,%3};"
                 : "+f"(c[0]), "+f"(c[1]), "+f"(c[2]), "+f"(c[3])
                 : "r"(a[0]), "r"(a[1]), "r"(a[2]), "r"(a[3]),
                   "r"(b[0]), "r"(b[1]));
}
__device__ __forceinline__ uint32_t pk2(__nv_bfloat16 a, __nv_bfloat16 b) {
    __nv_bfloat162 t = __halves2bfloat162(a, b);
    return *(uint32_t*)&t;
}
__device__ __forceinline__ void cp16(uint32_t dst, const void* src) {
    asm volatile("cp.async.cg.shared.global [%0], [%1], 16;" :: "r"(dst), "l"(src));
}

#define AST 40    // A smem row stride (bf16): 80B rows
#define BST 136   // B smem row stride: 272B rows

// per-stage smem layout (bytes)
#define ST_AH 0
#define ST_AL 10240
#define ST_BH 20480
#define ST_BL 29184
#define ST_BYTES 37888
#define SMEM_GEMM (2 * ST_BYTES)

// ---------------------------------------------------------------------------
// K1: GroupNorm statistics
// ---------------------------------------------------------------------------
__global__ void gn_stats_kernel(const float* __restrict__ x,
                                const float* __restrict__ gw,
                                const float* __restrict__ gb) {
    const int b = blockIdx.x / NG;
    const int g = blockIdx.x % NG;
    const float* xp = x + ((size_t)b * CC + (size_t)g * CPG) * HW;

    float s = 0.f, s2 = 0.f;
    for (int i = threadIdx.x; i < CPG * HW; i += blockDim.x) {
        float v = xp[i];
        s += v; s2 += v * v;
    }
    __shared__ float rs[32], rs2[32];
    #pragma unroll
    for (int o = 16; o > 0; o >>= 1) {
        s  += __shfl_down_sync(0xFFFFFFFFu, s,  o);
        s2 += __shfl_down_sync(0xFFFFFFFFu, s2, o);
    }
    int lane = threadIdx.x & 31, wid = threadIdx.x >> 5;
    if (lane == 0) { rs[wid] = s; rs2[wid] = s2; }
    __syncthreads();
    if (wid == 0) {
        int nw = blockDim.x >> 5;
        s  = (lane < nw) ? rs[lane]  : 0.f;
        s2 = (lane < nw) ? rs2[lane] : 0.f;
        #pragma unroll
        for (int o = 16; o > 0; o >>= 1) {
            s  += __shfl_down_sync(0xFFFFFFFFu, s,  o);
            s2 += __shfl_down_sync(0xFFFFFFFFu, s2, o);
        }
        if (lane == 0) { rs[0] = s; rs2[0] = s2; }
    }
    __syncthreads();
    const float inv_n = 1.f / (float)(CPG * HW);
    float mu  = rs[0] * inv_n;
    float var = rs2[0] * inv_n - mu * mu;
    float rstd = rsqrtf(var + EPSV);
    if (threadIdx.x < CPG) {
        int c = g * CPG + threadIdx.x;
        float sc = rstd * gw[c];
        g_scale[b * CC + c] = sc;
        g_shift[b * CC + c] = gb[c] - mu * sc;
    }
}

// ---------------------------------------------------------------------------
// K1b: apply norm + bf16 hi/lo split of x
// ---------------------------------------------------------------------------
__global__ __launch_bounds__(256) void prep_x_kernel(const float* __restrict__ x) {
    const int bc = blockIdx.x;
    const float sc = g_scale[bc], sh = g_shift[bc];
    const float* xp = x + (size_t)bc * HW;
    __nv_bfloat16* xh = g_xh + (size_t)bc * HW;
    __nv_bfloat16* xl = g_xl + (size_t)bc * HW;
    #pragma unroll
    for (int it = 0; it < 4; it++) {
        int i = (it * 256 + threadIdx.x) * 4;
        float4 v = *(const float4*)(xp + i);
        v.x = fmaf(v.x, sc, sh); v.y = fmaf(v.y, sc, sh);
        v.z = fmaf(v.z, sc, sh); v.w = fmaf(v.w, sc, sh);
        __nv_bfloat16 h0 = __float2bfloat16(v.x), h1 = __float2bfloat16(v.y);
        __nv_bfloat16 h2 = __float2bfloat16(v.z), h3 = __float2bfloat16(v.w);
        __nv_bfloat16 l0 = __float2bfloat16(v.x - __bfloat162float(h0));
        __nv_bfloat16 l1 = __float2bfloat16(v.y - __bfloat162float(h1));
        __nv_bfloat16 l2 = __float2bfloat16(v.z - __bfloat162float(h2));
        __nv_bfloat16 l3 = __float2bfloat16(v.w - __bfloat162float(h3));
        *(uint2*)(xh + i) = make_uint2(pk2(h0, h1), pk2(h2, h3));
        *(uint2*)(xl + i) = make_uint2(pk2(l0, l1), pk2(l2, l3));
    }
}

// K1c: split w_qkv K,V rows (256..767) to bf16 hi/lo
__global__ __launch_bounds__(256) void prep_w_kernel(const float* __restrict__ w) {
    int i = (blockIdx.x * 256 + threadIdx.x) * 4;
    float4 v = *(const float4*)(w + 256 * CC + i);
    __nv_bfloat16 h0 = __float2bfloat16(v.x), h1 = __float2bfloat16(v.y);
    __nv_bfloat16 h2 = __float2bfloat16(v.z), h3 = __float2bfloat16(v.w);
    __nv_bfloat16 l0 = __float2bfloat16(v.x - __bfloat162float(h0));
    __nv_bfloat16 l1 = __float2bfloat16(v.y - __bfloat162float(h1));
    __nv_bfloat16 l2 = __float2bfloat16(v.z - __bfloat162float(h2));
    __nv_bfloat16 l3 = __float2bfloat16(v.w - __bfloat162float(h3));
    *(uint2*)(g_wqh + i) = make_uint2(pk2(h0, h1), pk2(h2, h3));
    *(uint2*)(g_wql + i) = make_uint2(pk2(l0, l1), pk2(l2, l3));
}

// ---------------------------------------------------------------------------
// K2/K6: HMMA GEMM, 2-stage cp.async pipeline.
//   mode 0: fp32 out + bias (final).  mode 1: K/V epilogue (fp32 to g_kv)
// ---------------------------------------------------------------------------
__global__ __launch_bounds__(256)
void gemm_bf16(const __nv_bfloat16* __restrict__ Ah,
               const __nv_bfloat16* __restrict__ Al, size_t aStride,
               const __nv_bfloat16* __restrict__ Bh,
               const __nv_bfloat16* __restrict__ Bl,
               int M, int mode, const float* __restrict__ bias,
               float* __restrict__ Cout) {
    extern __shared__ char smem[];
    const uint32_t sb = smem_u32(smem);

    const int tid = threadIdx.x;
    const int wid = tid >> 5, lane = tid & 31;
    const int wM = wid >> 1, wN = wid & 1;
    const int b  = blockIdx.z;
    const int m0 = blockIdx.y * 128;
    const int n0 = blockIdx.x * 128;

    const __nv_bfloat16* Ahb = Ah + (size_t)b * aStride;
    const __nv_bfloat16* Alb = Al + (size_t)b * aStride;

    const int aRowL0 = tid >> 2, aQ4 = (tid & 3) * 8;
    const int bRowL0 = tid >> 4, bQ4 = (tid & 15) * 8;

    auto issue = [&](int kc, int stage) {
        const uint32_t st = sb + stage * ST_BYTES;
        const int k0 = kc * 32;
        #pragma unroll
        for (int it = 0; it < 2; it++) {
            int row = aRowL0 + it * 64;
            const __nv_bfloat16* s0 = Ahb + (size_t)(m0 + row) * CC + k0 + aQ4;
            const __nv_bfloat16* s1 = Alb + (size_t)(m0 + row) * CC + k0 + aQ4;
            uint32_t d = (uint32_t)(row * AST + aQ4) * 2;
            cp16(st + ST_AH + d, s0);
            cp16(st + ST_AL + d, s1);
        }
        #pragma unroll
        for (int it = 0; it < 2; it++) {
            int row = bRowL0 + it * 16;
            size_t g = ((size_t)b * CC + k0 + row) * HW + n0 + bQ4;
            uint32_t d = (uint32_t)(row * BST + bQ4) * 2;
            cp16(st + ST_BH + d, Bh + g);
            cp16(st + ST_BL + d, Bl + g);
        }
        asm volatile("cp.async.commit_group;");
    };

    float acc[2][8][4];
    #pragma unroll
    for (int i = 0; i < 2; i++)
        #pragma unroll
        for (int j = 0; j < 8; j++)
            #pragma unroll
            for (int q = 0; q < 4; q++) acc[i][j][q] = 0.f;

    const int lt = lane >> 3, lr = lane & 7;
    const int aRow = lr + ((lt & 1) ? 8 : 0);
    const int aKof = (lt & 2) ? 8 : 0;
    const int bKof = lr + ((lt & 1) ? 8 : 0);
    const int bNof = (lt & 2) ? 8 : 0;

    issue(0, 0);

    for (int kc = 0; kc < 8; kc++) {
        const int stage = kc & 1;
        if (kc < 7) {
            issue(kc + 1, stage ^ 1);
            asm volatile("cp.async.wait_group 1;");
        } else {
            asm volatile("cp.async.wait_group 0;");
        }
        __syncthreads();

        const uint32_t aHB = sb + stage * ST_BYTES + ST_AH;
        const uint32_t aLB = sb + stage * ST_BYTES + ST_AL;
        const uint32_t bHB = sb + stage * ST_BYTES + ST_BH;
        const uint32_t bLB = sb + stage * ST_BYTES + ST_BL;

        #pragma unroll
        for (int ks = 0; ks < 2; ks++) {
            const int kb = ks * 16;
            uint32_t ah[2][4], al[2][4], bh[8][2], bl[8][2];
            #pragma unroll
            for (int mt = 0; mt < 2; mt++) {
                uint32_t ad = ((wM * 32 + mt * 16 + aRow) * AST + kb + aKof) * 2;
                ldmx4(ah[mt], aHB + ad);
                ldmx4(al[mt], aLB + ad);
            }
            #pragma unroll
            for (int np = 0; np < 4; np++) {
                uint32_t bd = ((kb + bKof) * BST + wN * 64 + np * 16 + bNof) * 2;
                uint32_t r[4];
                ldmx4t(r, bHB + bd);
                bh[np * 2][0] = r[0]; bh[np * 2][1] = r[1];
                bh[np * 2 + 1][0] = r[2]; bh[np * 2 + 1][1] = r[3];
                ldmx4t(r, bLB + bd);
                bl[np * 2][0] = r[0]; bl[np * 2][1] = r[1];
                bl[np * 2 + 1][0] = r[2]; bl[np * 2 + 1][1] = r[3];
            }
            #pragma unroll
            for (int mt = 0; mt < 2; mt++)
                #pragma unroll
                for (int nt = 0; nt < 8; nt++) {
                    mma_bf16(acc[mt][nt], ah[mt], bh[nt]);
                    mma_bf16(acc[mt][nt], ah[mt], bl[nt]);
                    mma_bf16(acc[mt][nt], al[mt], bh[nt]);
                }
        }
        __syncthreads();
    }

    const int rbase = m0 + wM * 32 + (lane >> 2);
    const int cbase = n0 + wN * 64 + (lane & 3) * 2;

    if (mode == 0) {
        #pragma unroll
        for (int mt = 0; mt < 2; mt++) {
            int r0 = rbase + mt * 16;
            float bi0 = bias ? bias[r0] : 0.f;
            float bi1 = bias ? bias[r0 + 8] : 0.f;
            #pragma unroll
            for (int nt = 0; nt < 8; nt++) {
                int cc = cbase + nt * 8;
                *(float2*)(Cout + ((size_t)b * M + r0) * HW + cc) =
                    make_float2(acc[mt][nt][0] + bi0, acc[mt][nt][1] + bi0);
                *(float2*)(Cout + ((size_t)b * M + r0 + 8) * HW + cc) =
                    make_float2(acc[mt][nt][2] + bi1, acc[mt][nt][3] + bi1);
            }
        }
    } else {
        #pragma unroll
        for (int mt = 0; mt < 2; mt++) {
            #pragma unroll
            for (int half = 0; half < 2; half++) {
                int r = rbase + mt * 16 + half * 8;
                int kv = (r >= 256);
                int ch = r & 255;
                #pragma unroll
                for (int nt = 0; nt < 8; nt++) {
                    int cc = cbase + nt * 8;
                    *(float2*)(g_kv + ((size_t)(b * 2 + kv) * CC + ch) * HW + cc) =
                        make_float2(acc[mt][nt][half * 2 + 0],
                                    acc[mt][nt][half * 2 + 1]);
                }
            }
        }
    }
}

// ---------------------------------------------------------------------------
// K3: att_kv online: per split s, local max/expsum + partial exp(K)@V^T
//     4x4 tiles, j-split across 4 thread groups, float4 j-vector loads
// ---------------------------------------------------------------------------
__global__ __launch_bounds__(256) void att_kv_online() {
    __shared__ float sk[HD * SKST];
    __shared__ float sv[HD * SKST];
    __shared__ float smax[HD], ssum[HD];

    const int s  = blockIdx.x;
    const int bh = blockIdx.y;
    const int b = bh >> 3, h = bh & 7;
    const size_t kb = ((size_t)(b * 2 + 0) * CC + h * HD) * HW + s * SLICE;
    const size_t vb = ((size_t)(b * 2 + 1) * CC + h * HD) * HW + s * SLICE;

    const int t = threadIdx.x;
    const int row = t >> 3, seg = t & 7;

    #pragma unroll
    for (int i = 0; i < 4; i++) {
        int col = seg * 16 + i * 4;
        float4 k4 = *(const float4*)(g_kv + kb + (size_t)row * HW + col);
        float4 v4 = *(const float4*)(g_kv + vb + (size_t)row * HW + col);
        *(float4*)&sk[row * SKST + col] = k4;
        *(float4*)&sv[row * SKST + col] = v4;
    }
    __syncthreads();

    float m = -3.4e38f;
    #pragma unroll
    for (int i = 0; i < 16; i++) m = fmaxf(m, sk[row * SKST + seg * 16 + i]);
    #pragma unroll
    for (int o = 1; o < 8; o <<= 1)
        m = fmaxf(m, __shfl_xor_sync(0xFFFFFFFFu, m, o));
    if (seg == 0) smax[row] = m;
    __syncthreads();

    const float rm = smax[row];
    float sum = 0.f;
    #pragma unroll
    for (int i = 0; i < 16; i++) {
        int c = row * SKST + seg * 16 + i;
        float e = __expf(sk[c] - rm);
        sk[c] = e;
        sum += e;
    }
    #pragma unroll
    for (int o = 1; o < 8; o <<= 1)
        sum += __shfl_xor_sync(0xFFFFFFFFu, sum, o);
    if (seg == 0) ssum[row] = sum;
    __syncthreads();

    // 4x4 tile, j-split: jg in 0..3 handles 32 j's
    const int jg = t >> 6, tile = t & 63;
    const int d0 = (tile >> 3) * 4, e0 = (tile & 7) * 4;
    float a[4][4];
    #pragma unroll
    for (int i = 0; i < 4; i++)
        #pragma unroll
        for (int j = 0; j < 4; j++) a[i][j] = 0.f;

    #pragma unroll 2
    for (int j0 = jg * 32; j0 < jg * 32 + 32; j0 += 4) {
        float4 kq[4], vq[4];
        #pragma unroll
        for (int i = 0; i < 4; i++) {
            kq[i] = *(const float4*)&sk[(d0 + i) * SKST + j0];
            vq[i] = *(const float4*)&sv[(e0 + i) * SKST + j0];
        }
        #pragma unroll
        for (int i = 0; i < 4; i++)
            #pragma unroll
            for (int j = 0; j < 4; j++) {
                a[i][j] = fmaf(kq[i].x, vq[j].x, a[i][j]);
                a[i][j] = fmaf(kq[i].y, vq[j].y, a[i][j]);
                a[i][j] = fmaf(kq[i].z, vq[j].z, a[i][j]);
                a[i][j] = fmaf(kq[i].w, vq[j].w, a[i][j]);
            }
    }
    __syncthreads();

    float* sp = sk;   // reuse sk region: 4 * 1024 floats = 16 KB < 16.9 KB
    #pragma unroll
    for (int i = 0; i < 4; i++)
        #pragma unroll
        for (int j = 0; j < 4; j++)
            sp[jg * 1024 + (d0 + i) * HD + (e0 + j)] = a[i][j];
    __syncthreads();

    float* P = g_att_part + ((size_t)s * (BB * NH) + bh) * (HD * HD);
    #pragma unroll
    for (int r = 0; r < 4; r++) {
        int idx = t + r * 256;
        P[idx] = sp[idx] + sp[1024 + idx] + sp[2048 + idx] + sp[3072 + idx];
    }
    if (t < HD) {
        g_lmax[(s * (BB * NH) + bh) * HD + t] = smax[t];
        g_lsum[(s * (BB * NH) + bh) * HD + t] = ssum[t];
    }
}

// K3b: combine splits
__global__ __launch_bounds__(256) void att_reduce_kernel() {
    const int bh = blockIdx.x;
    __shared__ float sfac[SPLIT][HD];
    __shared__ float sdinv[HD];
    const int t = threadIdx.x;

    if (t < HD) {
        float gm = -3.4e38f;
        #pragma unroll 4
        for (int s = 0; s < SPLIT; s++)
            gm = fmaxf(gm, g_lmax[(s * (BB * NH) + bh) * HD + t]);
        float den = 0.f;
        #pragma unroll 4
        for (int s = 0; s < SPLIT; s++) {
            float f = __expf(g_lmax[(s * (BB * NH) + bh) * HD + t] - gm);
            sfac[s][t] = f;
            den += g_lsum[(s * (BB * NH) + bh) * HD + t] * f;
        }
        sdinv[t] = 1.f / den;
    }
    __syncthreads();

    #pragma unroll
    for (int idx = t; idx < HD * HD; idx += 256) {
        int d = idx >> 5;
        float acc = 0.f;
        #pragma unroll 4
        for (int s = 0; s < SPLIT; s++)
            acc = fmaf(g_att_part[((size_t)s * (BB * NH) + bh) * (HD * HD) + idx],
                       sfac[s][d], acc);
        g_att[(size_t)bh * (HD * HD) + idx] = acc * sdinv[d];
    }
}

// ---------------------------------------------------------------------------
// K4: Weff[b] = Wp . att[b]  (block-diagonal att), fp32 out
// ---------------------------------------------------------------------------
__global__ __launch_bounds__(256) void weff_kernel(const float* __restrict__ wp) {
    const int b = blockIdx.x;
    __shared__ float satt[NH][HD][HD];
    const int t = threadIdx.x;
    for (int i = t; i < NH * HD * HD; i += 256)
        ((float*)satt)[i] = g_att[(size_t)b * NH * HD * HD + i];
    __syncthreads();

    const int o = t;
    const float* wrow = wp + (size_t)o * CC;
    float* wout = g_weff + ((size_t)b * CC + o) * CC;
    #pragma unroll
    for (int h = 0; h < NH; h++) {
        float wreg[HD];
        #pragma unroll
        for (int e = 0; e < HD; e++) wreg[e] = wrow[h * HD + e];
        #pragma unroll 2
        for (int d = 0; d < HD; d++) {
            float s = 0.f;
            #pragma unroll
            for (int e = 0; e < HD; e++)
                s = fmaf(wreg[e], satt[h][d][e], s);
            wout[h * HD + d] = s;
        }
    }
}

// ---------------------------------------------------------------------------
// K4b: W2[b] = Weff[b] . Wq_q  (fp32), split to bf16 hi/lo
//   block = (b, 16 output rows); thread = output column
// ---------------------------------------------------------------------------
__global__ __launch_bounds__(256) void w2_kernel(const float* __restrict__ wq) {
    __shared__ float sW[16 * 256];
    const int b = blockIdx.x, r0 = blockIdx.y * 16;
    const int t = threadIdx.x;

    const float4* src = (const float4*)(g_weff + ((size_t)b * CC + r0) * CC);
    #pragma unroll
    for (int i = 0; i < 4; i++)
        ((float4*)sW)[i * 256 + t] = src[i * 256 + t];
    __syncthreads();

    const int c = t;
    float acc[16];
    #pragma unroll
    for (int o = 0; o < 16; o++) acc[o] = 0.f;

    for (int d = 0; d < CC; d += 4) {
        float wv0 = wq[(size_t)(d + 0) * CC + c];
        float wv1 = wq[(size_t)(d + 1) * CC + c];
        float wv2 = wq[(size_t)(d + 2) * CC + c];
        float wv3 = wq[(size_t)(d + 3) * CC + c];
        #pragma unroll
        for (int o = 0; o < 16; o++) {
            float4 sw = *(const float4*)&sW[o * 256 + d];
            acc[o] = fmaf(sw.x, wv0, acc[o]);
            acc[o] = fmaf(sw.y, wv1, acc[o]);
            acc[o] = fmaf(sw.z, wv2, acc[o]);
            acc[o] = fmaf(sw.w, wv3, acc[o]);
        }
    }
    #pragma unroll
    for (int o = 0; o < 16; o++) {
        float v = acc[o];
        __nv_bfloat16 hh = __float2bfloat16(v);
        __nv_bfloat16 ll = __float2bfloat16(v - __bfloat162float(hh));
        size_t g = ((size_t)b * CC + r0 + o) * CC + c;
        g_w2h[g] = hh;
        g_w2l[g] = ll;
    }
}

// ---------------------------------------------------------------------------
extern "C" void kernel_launch(void* const* d_in, const int* in_sizes, int n_in,
                              void* d_out, int out_size) {
    const float* x      = (const float*)d_in[0];
    const float* gn_w   = (const float*)d_in[1];
    const float* gn_b   = (const float*)d_in[2];
    const float* w_qkv  = (const float*)d_in[3];
    const float* w_proj = (const float*)d_in[4];
    const float* b_proj = (const float*)d_in[5];
    float* out = (float*)d_out;

    __nv_bfloat16 *xh, *xl, *wqh, *wql, *w2h, *w2l;
    cudaGetSymbolAddress((void**)&xh,  g_xh);
    cudaGetSymbolAddress((void**)&xl,  g_xl);
    cudaGetSymbolAddress((void**)&wqh, g_wqh);
    cudaGetSymbolAddress((void**)&wql, g_wql);
    cudaGetSymbolAddress((void**)&w2h, g_w2h);
    cudaGetSymbolAddress((void**)&w2l, g_w2l);

    cudaFuncSetAttribute(gemm_bf16, cudaFuncAttributeMaxDynamicSharedMemorySize,
                         SMEM_GEMM);

    // K1: groupnorm stats, then apply+split; split K/V weights
    gn_stats_kernel<<<BB * NG, 256>>>(x, gn_w, gn_b);
    prep_x_kernel<<<BB * CC, 256>>>(x);
    prep_w_kernel<<<(2 * CC * CC) / 1024, 256>>>(w_qkv);

    // K2: K,V projection (fp32 out to g_kv)
    {
        dim3 grid(HW / 128, (2 * CC) / 128, BB);
        gemm_bf16<<<grid, 256, SMEM_GEMM>>>(wqh, wql, 0, xh, xl, 2 * CC, 1,
                                            nullptr, nullptr);
    }

    // K3: online softmax-weighted K@V^T partials + reduce
    {
        dim3 grid(SPLIT, BB * NH);
        att_kv_online<<<grid, 256>>>();
    }
    att_reduce_kernel<<<BB * NH, 256>>>();

    // K4: Weff = Wp.att (fp32), then W2 = Weff.Wq_q (split bf16)
    weff_kernel<<<BB, 256>>>(w_proj);
    {
        dim3 grid(BB, CC / 16);
        w2_kernel<<<grid, 256>>>(w_qkv);
    }

    // K5: out = W2[b] @ xn + bias
    {
        dim3 grid(HW / 128, CC / 128, BB);
        gemm_bf16<<<grid, 256, SMEM_GEMM>>>(w2h, w2l, (size_t)CC * CC, xh, xl,
                                            CC, 0, b_proj, out);
    }
}

// round 8
// speedup vs baseline: 3.1962x; 1.1896x over previous
#include <cuda_runtime.h>
#include <cuda_bf16.h>
#include <cstdint>

#define BB 16
#define CC 256
#define HW 4096
#define NH 8
#define HD 32
#define NG 32
#define CPG 8
#define EPSV 1e-5f
#define SPLIT 32           // n-tiles (slice = 128)

// ---------------- scratch (device globals) ----------------------------------
__device__ __nv_bfloat16 g_xh[(size_t)BB * CC * HW];     // normed x hi
__device__ __nv_bfloat16 g_xl[(size_t)BB * CC * HW];     // normed x lo
__device__ __nv_bfloat16 g_wqh[2 * CC * CC];             // K,V weights hi (rearranged)
__device__ __nv_bfloat16 g_wql[2 * CC * CC];             // K,V weights lo
__device__ float g_att_part[(size_t)SPLIT * BB * NH * HD * HD];
__device__ float g_lmax[SPLIT * BB * NH * HD];
__device__ float g_lsum[SPLIT * BB * NH * HD];
__device__ float g_att[(size_t)BB * NH * HD * HD];
__device__ float g_weff[(size_t)BB * CC * CC];
__device__ __nv_bfloat16 g_w2h[(size_t)BB * CC * CC];
__device__ __nv_bfloat16 g_w2l[(size_t)BB * CC * CC];
__device__ float g_scale[BB * CC];
__device__ float g_shift[BB * CC];

// ---------------- warp-MMA helpers ------------------------------------------
__device__ __forceinline__ uint32_t smem_u32(const void* p) {
    uint32_t a;
    asm("{ .reg .u64 t; cvta.to.shared.u64 t, %1; cvt.u32.u64 %0, t; }"
        : "=r"(a) : "l"(p));
    return a;
}
__device__ __forceinline__ void ldmx4(uint32_t* r, uint32_t addr) {
    asm volatile("ldmatrix.sync.aligned.m8n8.x4.shared.b16 {%0,%1,%2,%3}, [%4];"
                 : "=r"(r[0]), "=r"(r[1]), "=r"(r[2]), "=r"(r[3]) : "r"(addr));
}
__device__ __forceinline__ void ldmx4t(uint32_t* r, uint32_t addr) {
    asm volatile("ldmatrix.sync.aligned.m8n8.x4.trans.shared.b16 {%0,%1,%2,%3}, [%4];"
                 : "=r"(r[0]), "=r"(r[1]), "=r"(r[2]), "=r"(r[3]) : "r"(addr));
}
__device__ __forceinline__ void ldmx2(uint32_t* r, uint32_t addr) {
    asm volatile("ldmatrix.sync.aligned.m8n8.x2.shared.b16 {%0,%1}, [%2];"
                 : "=r"(r[0]), "=r"(r[1]) : "r"(addr));
}
__device__ __forceinline__ void mma_bf16(float* c, const uint32_t* a, const uint32_t* b) {
    asm volatile("mma.sync.aligned.m16n8k16.row.col.f32.bf16.bf16.f32 "
                 "{%0,%1,%2,%3}, {%4,%5,%6,%7}, {%8,%9}, {%0,%1,%2,%3};"
                 : "+f"(c[0]), "+f"(c[1]), "+f"(c[2]), "+f"(c[3])
                 : "r"(a[0]), "r"(a[1]), "r"(a[2]), "r"(a[3]),
                   "r"(b[0]), "r"(b[1]));
}
__device__ __forceinline__ uint32_t pk2(__nv_bfloat16 a, __nv_bfloat16 b) {
    __nv_bfloat162 t = __halves2bfloat162(a, b);
    return *(uint32_t*)&t;
}
__device__ __forceinline__ void cp16(uint32_t dst, const void* src) {
    asm volatile("cp.async.cg.shared.global [%0], [%1], 16;" :: "r"(dst), "l"(src));
}

#define AST 40    // A smem row stride (bf16)
#define BST 136   // B smem row stride (bf16)
#define PST 72    // P-stage plane row stride (bf16)

// fused kernel smem layout
#define F_AH 0
#define F_AL 20480
#define F_BH 40960
#define F_BL 49664
#define F_STAGE 58368
#define F_SMEM  (2 * F_STAGE)      // 116736
#define PKH 0
#define PKL 18432
#define PVH 36864
#define PVL 55296
#define PMAX 73728                 // float[2][128]
#define PSUM 74752                 // float[2][128]

// final gemm smem layout (256 threads)
#define ST_AH 0
#define ST_AL 10240
#define ST_BH 20480
#define ST_BL 29184
#define ST_BYTES 37888
#define SMEM_GEMM (2 * ST_BYTES)

// ---------------------------------------------------------------------------
// K1: GroupNorm statistics
// ---------------------------------------------------------------------------
__global__ void gn_stats_kernel(const float* __restrict__ x,
                                const float* __restrict__ gw,
                                const float* __restrict__ gb) {
    const int b = blockIdx.x / NG;
    const int g = blockIdx.x % NG;
    const float* xp = x + ((size_t)b * CC + (size_t)g * CPG) * HW;

    float s = 0.f, s2 = 0.f;
    for (int i = threadIdx.x; i < CPG * HW; i += blockDim.x) {
        float v = xp[i];
        s += v; s2 += v * v;
    }
    __shared__ float rs[32], rs2[32];
    #pragma unroll
    for (int o = 16; o > 0; o >>= 1) {
        s  += __shfl_down_sync(0xFFFFFFFFu, s,  o);
        s2 += __shfl_down_sync(0xFFFFFFFFu, s2, o);
    }
    int lane = threadIdx.x & 31, wid = threadIdx.x >> 5;
    if (lane == 0) { rs[wid] = s; rs2[wid] = s2; }
    __syncthreads();
    if (wid == 0) {
        int nw = blockDim.x >> 5;
        s  = (lane < nw) ? rs[lane]  : 0.f;
        s2 = (lane < nw) ? rs2[lane] : 0.f;
        #pragma unroll
        for (int o = 16; o > 0; o >>= 1) {
            s  += __shfl_down_sync(0xFFFFFFFFu, s,  o);
            s2 += __shfl_down_sync(0xFFFFFFFFu, s2, o);
        }
        if (lane == 0) { rs[0] = s; rs2[0] = s2; }
    }
    __syncthreads();
    const float inv_n = 1.f / (float)(CPG * HW);
    float mu  = rs[0] * inv_n;
    float var = rs2[0] * inv_n - mu * mu;
    float rstd = rsqrtf(var + EPSV);
    if (threadIdx.x < CPG) {
        int c = g * CPG + threadIdx.x;
        float sc = rstd * gw[c];
        g_scale[b * CC + c] = sc;
        g_shift[b * CC + c] = gb[c] - mu * sc;
    }
}

// ---------------------------------------------------------------------------
// K1b: apply norm + bf16 hi/lo split of x
// ---------------------------------------------------------------------------
__global__ __launch_bounds__(256) void prep_x_kernel(const float* __restrict__ x) {
    const int bc = blockIdx.x;
    const float sc = g_scale[bc], sh = g_shift[bc];
    const float* xp = x + (size_t)bc * HW;
    __nv_bfloat16* xh = g_xh + (size_t)bc * HW;
    __nv_bfloat16* xl = g_xl + (size_t)bc * HW;
    #pragma unroll
    for (int it = 0; it < 4; it++) {
        int i = (it * 256 + threadIdx.x) * 4;
        float4 v = *(const float4*)(xp + i);
        v.x = fmaf(v.x, sc, sh); v.y = fmaf(v.y, sc, sh);
        v.z = fmaf(v.z, sc, sh); v.w = fmaf(v.w, sc, sh);
        __nv_bfloat16 h0 = __float2bfloat16(v.x), h1 = __float2bfloat16(v.y);
        __nv_bfloat16 h2 = __float2bfloat16(v.z), h3 = __float2bfloat16(v.w);
        __nv_bfloat16 l0 = __float2bfloat16(v.x - __bfloat162float(h0));
        __nv_bfloat16 l1 = __float2bfloat16(v.y - __bfloat162float(h1));
        __nv_bfloat16 l2 = __float2bfloat16(v.z - __bfloat162float(h2));
        __nv_bfloat16 l3 = __float2bfloat16(v.w - __bfloat162float(h3));
        *(uint2*)(xh + i) = make_uint2(pk2(h0, h1), pk2(h2, h3));
        *(uint2*)(xl + i) = make_uint2(pk2(l0, l1), pk2(l2, l3));
    }
}

// K1c: split + rearrange w_qkv K,V rows: dst[hh][0..127]=K(256+hh*128+r),
//      dst[hh][128..255]=V(512+hh*128+r)
__global__ __launch_bounds__(256) void prep_w_kernel(const float* __restrict__ w) {
    int idx = blockIdx.x * 256 + threadIdx.x;   // 0 .. 32767 float4s
    int r = idx >> 6, c4 = (idx & 63) * 4;
    int hh = r >> 8, rr = r & 255;
    int src = (rr < 128) ? (256 + hh * 128 + rr) : (512 + hh * 128 + rr - 128);
    float4 v = *(const float4*)(w + (size_t)src * CC + c4);
    __nv_bfloat16 h0 = __float2bfloat16(v.x), h1 = __float2bfloat16(v.y);
    __nv_bfloat16 h2 = __float2bfloat16(v.z), h3 = __float2bfloat16(v.w);
    __nv_bfloat16 l0 = __float2bfloat16(v.x - __bfloat162float(h0));
    __nv_bfloat16 l1 = __float2bfloat16(v.y - __bfloat162float(h1));
    __nv_bfloat16 l2 = __float2bfloat16(v.z - __bfloat162float(h2));
    __nv_bfloat16 l3 = __float2bfloat16(v.w - __bfloat162float(h3));
    size_t o = (size_t)r * CC + c4;
    *(uint2*)(g_wqh + o) = make_uint2(pk2(h0, h1), pk2(h2, h3));
    *(uint2*)(g_wql + o) = make_uint2(pk2(l0, l1), pk2(l2, l3));
}

// ---------------------------------------------------------------------------
// K2: fused KV GEMM + online attention partials.
//   512 threads. CTA: (n-tile s, half hh, batch b) -> K rows hh*128..+128 and
//   V rows hh*128..+128 over n slice of 128. Epilogue computes
//   P_s[d][e] = sum_n exp(K - lmax)*V via HMMA; writes P, lmax, lsum.
// ---------------------------------------------------------------------------
__global__ __launch_bounds__(512)
void gemm_kv_att() {
    extern __shared__ char smem[];
    const uint32_t sb = smem_u32(smem);

    const int tid = threadIdx.x;
    const int wid = tid >> 5, lane = tid & 31;
    const int wM = wid >> 1, wN = wid & 1;     // wM 0-3 = K rows, 4-7 = V rows
    const int s  = blockIdx.x;
    const int hh = blockIdx.y;
    const int b  = blockIdx.z;
    const int n0 = s * 128;

    const __nv_bfloat16* Ahb = g_wqh + (size_t)hh * 256 * CC;
    const __nv_bfloat16* Alb = g_wql + (size_t)hh * 256 * CC;
    const __nv_bfloat16* Bh  = g_xh + (size_t)b * CC * HW;
    const __nv_bfloat16* Bl  = g_xl + (size_t)b * CC * HW;

    const int bRowL0 = tid >> 4, bQ4 = (tid & 15) * 8;

    auto issue = [&](int kc, int stage) {
        const uint32_t st = sb + stage * F_STAGE;
        const int k0 = kc * 32;
        #pragma unroll
        for (int it = 0; it < 2; it++) {       // A: 1024 cp16 per plane
            int idx = it * 512 + tid;
            int row = idx >> 2, q4 = (idx & 3) * 8;
            uint32_t d = (uint32_t)(row * AST + q4) * 2;
            cp16(st + F_AH + d, Ahb + (size_t)row * CC + k0 + q4);
            cp16(st + F_AL + d, Alb + (size_t)row * CC + k0 + q4);
        }
        {                                      // B: 512 cp16 per plane
            size_t g = ((size_t)(k0 + bRowL0)) * HW + n0 + bQ4;
            uint32_t d = (uint32_t)(bRowL0 * BST + bQ4) * 2;
            cp16(st + F_BH + d, Bh + g);
            cp16(st + F_BL + d, Bl + g);
        }
        asm volatile("cp.async.commit_group;");
    };

    float acc[2][8][4];
    #pragma unroll
    for (int i = 0; i < 2; i++)
        #pragma unroll
        for (int j = 0; j < 8; j++)
            #pragma unroll
            for (int q = 0; q < 4; q++) acc[i][j][q] = 0.f;

    const int lt = lane >> 3, lr = lane & 7;
    const int aRow = lr + ((lt & 1) ? 8 : 0);
    const int aKof = (lt & 2) ? 8 : 0;
    const int bKof = lr + ((lt & 1) ? 8 : 0);
    const int bNof = (lt & 2) ? 8 : 0;

    issue(0, 0);

    for (int kc = 0; kc < 8; kc++) {
        const int stage = kc & 1;
        if (kc < 7) {
            issue(kc + 1, stage ^ 1);
            asm volatile("cp.async.wait_group 1;");
        } else {
            asm volatile("cp.async.wait_group 0;");
        }
        __syncthreads();

        const uint32_t aHB = sb + stage * F_STAGE + F_AH;
        const uint32_t aLB = sb + stage * F_STAGE + F_AL;
        const uint32_t bHB = sb + stage * F_STAGE + F_BH;
        const uint32_t bLB = sb + stage * F_STAGE + F_BL;

        #pragma unroll
        for (int ks = 0; ks < 2; ks++) {
            const int kb = ks * 16;
            uint32_t ah[2][4], al[2][4], bh[8][2], bl[8][2];
            #pragma unroll
            for (int mt = 0; mt < 2; mt++) {
                uint32_t ad = ((wM * 32 + mt * 16 + aRow) * AST + kb + aKof) * 2;
                ldmx4(ah[mt], aHB + ad);
                ldmx4(al[mt], aLB + ad);
            }
            #pragma unroll
            for (int np = 0; np < 4; np++) {
                uint32_t bd = ((kb + bKof) * BST + wN * 64 + np * 16 + bNof) * 2;
                uint32_t r[4];
                ldmx4t(r, bHB + bd);
                bh[np * 2][0] = r[0]; bh[np * 2][1] = r[1];
                bh[np * 2 + 1][0] = r[2]; bh[np * 2 + 1][1] = r[3];
                ldmx4t(r, bLB + bd);
                bl[np * 2][0] = r[0]; bl[np * 2][1] = r[1];
                bl[np * 2 + 1][0] = r[2]; bl[np * 2 + 1][1] = r[3];
            }
            #pragma unroll
            for (int mt = 0; mt < 2; mt++)
                #pragma unroll
                for (int nt = 0; nt < 8; nt++) {
                    mma_bf16(acc[mt][nt], ah[mt], bh[nt]);
                    mma_bf16(acc[mt][nt], ah[mt], bl[nt]);
                    mma_bf16(acc[mt][nt], al[mt], bh[nt]);
                }
        }
        __syncthreads();
    }

    // ================= fused attention epilogue =================
    const int rq = lane >> 2, cq = lane & 3;
    const bool isK = (wM < 4);
    float* smMax = (float*)(smem + PMAX);  // [2][128]
    float* smSum = (float*)(smem + PSUM);  // [2][128]

    // 1. per-warp row max over this warp's 64 cols
    if (isK) {
        #pragma unroll
        for (int mt = 0; mt < 2; mt++)
            #pragma unroll
            for (int rh = 0; rh < 2; rh++) {
                float m = -3.4e38f;
                #pragma unroll
                for (int nt = 0; nt < 8; nt++) {
                    m = fmaxf(m, acc[mt][nt][rh * 2]);
                    m = fmaxf(m, acc[mt][nt][rh * 2 + 1]);
                }
                m = fmaxf(m, __shfl_xor_sync(0xFFFFFFFFu, m, 1));
                m = fmaxf(m, __shfl_xor_sync(0xFFFFFFFFu, m, 2));
                if (cq == 0)
                    smMax[wN * 128 + wM * 32 + mt * 16 + rh * 8 + rq] = m;
            }
    }
    __syncthreads();

    // 2. exp with combined max + row sums
    if (isK) {
        #pragma unroll
        for (int mt = 0; mt < 2; mt++)
            #pragma unroll
            for (int rh = 0; rh < 2; rh++) {
                int row = wM * 32 + mt * 16 + rh * 8 + rq;
                float km = fmaxf(smMax[row], smMax[128 + row]);
                float ss = 0.f;
                #pragma unroll
                for (int nt = 0; nt < 8; nt++) {
                    float e0 = __expf(acc[mt][nt][rh * 2]     - km);
                    float e1 = __expf(acc[mt][nt][rh * 2 + 1] - km);
                    acc[mt][nt][rh * 2]     = e0;
                    acc[mt][nt][rh * 2 + 1] = e1;
                    ss += e0 + e1;
                }
                ss += __shfl_xor_sync(0xFFFFFFFFu, ss, 1);
                ss += __shfl_xor_sync(0xFFFFFFFFu, ss, 2);
                if (cq == 0) smSum[wN * 128 + row] = ss;
            }
    }

    // 3. two n-passes: stage expK/V tiles (bf16 hi/lo) + P-MMA
    float pp[2][4];
    #pragma unroll
    for (int mt = 0; mt < 2; mt++)
        #pragma unroll
        for (int q = 0; q < 4; q++) pp[mt][q] = 0.f;

    const int head = wid >> 2, sub = wid & 3;
    const int l16 = lane & 15;
    // B (V) fragment rows: head*32 + sub*8 + (l16&7)  [FIX: head offset]
    const uint32_t baddrBase =
        ((head * 32 + sub * 8 + (l16 & 7)) * PST + (l16 >> 3) * 8) * 2;

    #pragma unroll
    for (int p = 0; p < 2; p++) {
        __syncthreads();
        if (wN == p) {
            const int rowb = (wM & 3) * 32;
            #pragma unroll
            for (int mt = 0; mt < 2; mt++)
                #pragma unroll
                for (int rh = 0; rh < 2; rh++) {
                    int row = rowb + mt * 16 + rh * 8 + rq;
                    #pragma unroll
                    for (int nt = 0; nt < 8; nt++) {
                        int c = nt * 8 + cq * 2;
                        float v0 = acc[mt][nt][rh * 2];
                        float v1 = acc[mt][nt][rh * 2 + 1];
                        __nv_bfloat16 h0 = __float2bfloat16(v0);
                        __nv_bfloat16 h1 = __float2bfloat16(v1);
                        __nv_bfloat16 q0 = __float2bfloat16(v0 - __bfloat162float(h0));
                        __nv_bfloat16 q1 = __float2bfloat16(v1 - __bfloat162float(h1));
                        uint32_t off = (uint32_t)(row * PST + c) * 2;
                        *(uint32_t*)(smem + (isK ? PKH : PVH) + off) = pk2(h0, h1);
                        *(uint32_t*)(smem + (isK ? PKL : PVL) + off) = pk2(q0, q1);
                    }
                }
        }
        __syncthreads();

        #pragma unroll
        for (int ks = 0; ks < 4; ks++) {
            const int kb = ks * 16;
            uint32_t b2h[2], b2l[2];
            ldmx2(b2h, sb + PVH + baddrBase + (uint32_t)kb * 2);
            ldmx2(b2l, sb + PVL + baddrBase + (uint32_t)kb * 2);
            #pragma unroll
            for (int mt = 0; mt < 2; mt++) {
                uint32_t a2h[4], a2l[4];
                uint32_t ad = ((head * 32 + mt * 16 + aRow) * PST + kb + aKof) * 2;
                ldmx4(a2h, sb + PKH + ad);
                ldmx4(a2l, sb + PKL + ad);
                mma_bf16(pp[mt], a2h, b2h);
                mma_bf16(pp[mt], a2h, b2l);
                mma_bf16(pp[mt], a2l, b2h);
            }
        }
    }

    // 4. write P partials, lmax, lsum
    const int bh = b * NH + hh * 4 + head;
    float* P = g_att_part + ((size_t)s * (BB * NH) + bh) * (HD * HD);
    #pragma unroll
    for (int mt = 0; mt < 2; mt++) {
        int d = mt * 16 + rq;
        int e = sub * 8 + cq * 2;
        *(float2*)&P[d * HD + e]       = make_float2(pp[mt][0], pp[mt][1]);
        *(float2*)&P[(d + 8) * HD + e] = make_float2(pp[mt][2], pp[mt][3]);
    }
    if (tid < 128) {
        int h = hh * 4 + (tid >> 5);
        int o = (s * (BB * NH) + b * NH + h) * HD + (tid & 31);
        g_lmax[o] = fmaxf(smMax[tid], smMax[128 + tid]);
        g_lsum[o] = smSum[tid] + smSum[128 + tid];
    }
}

// ---------------------------------------------------------------------------
// K3b: combine splits
// ---------------------------------------------------------------------------
__global__ __launch_bounds__(256) void att_reduce_kernel() {
    const int bh = blockIdx.x;
    __shared__ float sfac[SPLIT][HD];
    __shared__ float sdinv[HD];
    const int t = threadIdx.x;

    if (t < HD) {
        float gm = -3.4e38f;
        #pragma unroll 4
        for (int s = 0; s < SPLIT; s++)
            gm = fmaxf(gm, g_lmax[(s * (BB * NH) + bh) * HD + t]);
        float den = 0.f;
        #pragma unroll 4
        for (int s = 0; s < SPLIT; s++) {
            float f = __expf(g_lmax[(s * (BB * NH) + bh) * HD + t] - gm);
            sfac[s][t] = f;
            den += g_lsum[(s * (BB * NH) + bh) * HD + t] * f;
        }
        sdinv[t] = 1.f / den;
    }
    __syncthreads();

    #pragma unroll
    for (int idx = t; idx < HD * HD; idx += 256) {
        int d = idx >> 5;
        float acc = 0.f;
        #pragma unroll 4
        for (int s = 0; s < SPLIT; s++)
            acc = fmaf(g_att_part[((size_t)s * (BB * NH) + bh) * (HD * HD) + idx],
                       sfac[s][d], acc);
        g_att[(size_t)bh * (HD * HD) + idx] = acc * sdinv[d];
    }
}

// ---------------------------------------------------------------------------
// K4: Weff[b] = Wp . att[b]
// ---------------------------------------------------------------------------
__global__ __launch_bounds__(256) void weff_kernel(const float* __restrict__ wp) {
    const int b = blockIdx.x;
    __shared__ float satt[NH][HD][HD];
    const int t = threadIdx.x;
    for (int i = t; i < NH * HD * HD; i += 256)
        ((float*)satt)[i] = g_att[(size_t)b * NH * HD * HD + i];
    __syncthreads();

    const int o = t;
    const float* wrow = wp + (size_t)o * CC;
    float* wout = g_weff + ((size_t)b * CC + o) * CC;
    #pragma unroll
    for (int h = 0; h < NH; h++) {
        float wreg[HD];
        #pragma unroll
        for (int e = 0; e < HD; e++) wreg[e] = wrow[h * HD + e];
        #pragma unroll 2
        for (int d = 0; d < HD; d++) {
            float s = 0.f;
            #pragma unroll
            for (int e = 0; e < HD; e++)
                s = fmaf(wreg[e], satt[h][d][e], s);
            wout[h * HD + d] = s;
        }
    }
}

// ---------------------------------------------------------------------------
// K4b: W2[b] = Weff[b] . Wq_q, split to bf16 hi/lo
// ---------------------------------------------------------------------------
__global__ __launch_bounds__(256) void w2_kernel(const float* __restrict__ wq) {
    __shared__ float sW[16 * 256];
    const int b = blockIdx.x, r0 = blockIdx.y * 16;
    const int t = threadIdx.x;

    const float4* src = (const float4*)(g_weff + ((size_t)b * CC + r0) * CC);
    #pragma unroll
    for (int i = 0; i < 4; i++)
        ((float4*)sW)[i * 256 + t] = src[i * 256 + t];
    __syncthreads();

    const int c = t;
    float acc[16];
    #pragma unroll
    for (int o = 0; o < 16; o++) acc[o] = 0.f;

    for (int d = 0; d < CC; d += 4) {
        float wv0 = wq[(size_t)(d + 0) * CC + c];
        float wv1 = wq[(size_t)(d + 1) * CC + c];
        float wv2 = wq[(size_t)(d + 2) * CC + c];
        float wv3 = wq[(size_t)(d + 3) * CC + c];
        #pragma unroll
        for (int o = 0; o < 16; o++) {
            float4 sw = *(const float4*)&sW[o * 256 + d];
            acc[o] = fmaf(sw.x, wv0, acc[o]);
            acc[o] = fmaf(sw.y, wv1, acc[o]);
            acc[o] = fmaf(sw.z, wv2, acc[o]);
            acc[o] = fmaf(sw.w, wv3, acc[o]);
        }
    }
    #pragma unroll
    for (int o = 0; o < 16; o++) {
        float v = acc[o];
        __nv_bfloat16 hh = __float2bfloat16(v);
        __nv_bfloat16 ll = __float2bfloat16(v - __bfloat162float(hh));
        size_t g = ((size_t)b * CC + r0 + o) * CC + c;
        g_w2h[g] = hh;
        g_w2l[g] = ll;
    }
}

// ---------------------------------------------------------------------------
// K5: final GEMM out = W2[b] @ xn + bias (256 threads, 2-stage cp.async)
// ---------------------------------------------------------------------------
__global__ __launch_bounds__(256)
void gemm_final(const float* __restrict__ bias, float* __restrict__ Cout) {
    extern __shared__ char smem[];
    const uint32_t sb = smem_u32(smem);

    const int tid = threadIdx.x;
    const int wid = tid >> 5, lane = tid & 31;
    const int wM = wid >> 1, wN = wid & 1;
    const int b  = blockIdx.z;
    const int m0 = blockIdx.y * 128;
    const int n0 = blockIdx.x * 128;

    const __nv_bfloat16* Ahb = g_w2h + (size_t)b * CC * CC;
    const __nv_bfloat16* Alb = g_w2l + (size_t)b * CC * CC;
    const __nv_bfloat16* Bh  = g_xh + (size_t)b * CC * HW;
    const __nv_bfloat16* Bl  = g_xl + (size_t)b * CC * HW;

    const int aRowL0 = tid >> 2, aQ4 = (tid & 3) * 8;
    const int bRowL0 = tid >> 4, bQ4 = (tid & 15) * 8;

    auto issue = [&](int kc, int stage) {
        const uint32_t st = sb + stage * ST_BYTES;
        const int k0 = kc * 32;
        #pragma unroll
        for (int it = 0; it < 2; it++) {
            int row = aRowL0 + it * 64;
            uint32_t d = (uint32_t)(row * AST + aQ4) * 2;
            cp16(st + ST_AH + d, Ahb + (size_t)(m0 + row) * CC + k0 + aQ4);
            cp16(st + ST_AL + d, Alb + (size_t)(m0 + row) * CC + k0 + aQ4);
        }
        #pragma unroll
        for (int it = 0; it < 2; it++) {
            int row = bRowL0 + it * 16;
            size_t g = ((size_t)(k0 + row)) * HW + n0 + bQ4;
            uint32_t d = (uint32_t)(row * BST + bQ4) * 2;
            cp16(st + ST_BH + d, Bh + g);
            cp16(st + ST_BL + d, Bl + g);
        }
        asm volatile("cp.async.commit_group;");
    };

    float acc[2][8][4];
    #pragma unroll
    for (int i = 0; i < 2; i++)
        #pragma unroll
        for (int j = 0; j < 8; j++)
            #pragma unroll
            for (int q = 0; q < 4; q++) acc[i][j][q] = 0.f;

    const int lt = lane >> 3, lr = lane & 7;
    const int aRow = lr + ((lt & 1) ? 8 : 0);
    const int aKof = (lt & 2) ? 8 : 0;
    const int bKof = lr + ((lt & 1) ? 8 : 0);
    const int bNof = (lt & 2) ? 8 : 0;

    issue(0, 0);

    for (int kc = 0; kc < 8; kc++) {
        const int stage = kc & 1;
        if (kc < 7) {
            issue(kc + 1, stage ^ 1);
            asm volatile("cp.async.wait_group 1;");
        } else {
            asm volatile("cp.async.wait_group 0;");
        }
        __syncthreads();

        const uint32_t aHB = sb + stage * ST_BYTES + ST_AH;
        const uint32_t aLB = sb + stage * ST_BYTES + ST_AL;
        const uint32_t bHB = sb + stage * ST_BYTES + ST_BH;
        const uint32_t bLB = sb + stage * ST_BYTES + ST_BL;

        #pragma unroll
        for (int ks = 0; ks < 2; ks++) {
            const int kb = ks * 16;
            uint32_t ah[2][4], al[2][4], bh[8][2], bl[8][2];
            #pragma unroll
            for (int mt = 0; mt < 2; mt++) {
                uint32_t ad = ((wM * 32 + mt * 16 + aRow) * AST + kb + aKof) * 2;
                ldmx4(ah[mt], aHB + ad);
                ldmx4(al[mt], aLB + ad);
            }
            #pragma unroll
            for (int np = 0; np < 4; np++) {
                uint32_t bd = ((kb + bKof) * BST + wN * 64 + np * 16 + bNof) * 2;
                uint32_t r[4];
                ldmx4t(r, bHB + bd);
                bh[np * 2][0] = r[0]; bh[np * 2][1] = r[1];
                bh[np * 2 + 1][0] = r[2]; bh[np * 2 + 1][1] = r[3];
                ldmx4t(r, bLB + bd);
                bl[np * 2][0] = r[0]; bl[np * 2][1] = r[1];
                bl[np * 2 + 1][0] = r[2]; bl[np * 2 + 1][1] = r[3];
            }
            #pragma unroll
            for (int mt = 0; mt < 2; mt++)
                #pragma unroll
                for (int nt = 0; nt < 8; nt++) {
                    mma_bf16(acc[mt][nt], ah[mt], bh[nt]);
                    mma_bf16(acc[mt][nt], ah[mt], bl[nt]);
                    mma_bf16(acc[mt][nt], al[mt], bh[nt]);
                }
        }
        __syncthreads();
    }

    const int rbase = m0 + wM * 32 + (lane >> 2);
    const int cbase = n0 + wN * 64 + (lane & 3) * 2;
    #pragma unroll
    for (int mt = 0; mt < 2; mt++) {
        int r0 = rbase + mt * 16;
        float bi0 = bias[r0];
        float bi1 = bias[r0 + 8];
        #pragma unroll
        for (int nt = 0; nt < 8; nt++) {
            int cc = cbase + nt * 8;
            *(float2*)(Cout + ((size_t)b * CC + r0) * HW + cc) =
                make_float2(acc[mt][nt][0] + bi0, acc[mt][nt][1] + bi0);
            *(float2*)(Cout + ((size_t)b * CC + r0 + 8) * HW + cc) =
                make_float2(acc[mt][nt][2] + bi1, acc[mt][nt][3] + bi1);
        }
    }
}

// ---------------------------------------------------------------------------
extern "C" void kernel_launch(void* const* d_in, const int* in_sizes, int n_in,
                              void* d_out, int out_size) {
    const float* x      = (const float*)d_in[0];
    const float* gn_w   = (const float*)d_in[1];
    const float* gn_b   = (const float*)d_in[2];
    const float* w_qkv  = (const float*)d_in[3];
    const float* w_proj = (const float*)d_in[4];
    const float* b_proj = (const float*)d_in[5];
    float* out = (float*)d_out;

    cudaFuncSetAttribute(gemm_kv_att, cudaFuncAttributeMaxDynamicSharedMemorySize,
                         F_SMEM);
    cudaFuncSetAttribute(gemm_final, cudaFuncAttributeMaxDynamicSharedMemorySize,
                         SMEM_GEMM);

    // K1: groupnorm stats, apply+split x, split+rearrange K/V weights
    gn_stats_kernel<<<BB * NG, 256>>>(x, gn_w, gn_b);
    prep_x_kernel<<<BB * CC, 256>>>(x);
    prep_w_kernel<<<128, 256>>>(w_qkv);

    // K2: fused KV projection + attention partials
    {
        dim3 grid(SPLIT, 2, BB);
        gemm_kv_att<<<grid, 512, F_SMEM>>>();
    }

    // K3: combine splits
    att_reduce_kernel<<<BB * NH, 256>>>();

    // K4: Weff = Wp.att, W2 = Weff.Wq_q
    weff_kernel<<<BB, 256>>>(w_proj);
    {
        dim3 grid(BB, CC / 16);
        w2_kernel<<<grid, 256>>>(w_qkv);
    }

    // K5: out = W2[b] @ xn + bias
    {
        dim3 grid(HW / 128, CC / 128, BB);
        gemm_final<<<grid, 256, SMEM_GEMM>>>(b_proj, out);
    }
}

// round 9
// speedup vs baseline: 3.2564x; 1.0188x over previous
#include <cuda_runtime.h>
#include <cuda_bf16.h>
#include <cstdint>

#define BB 16
#define CC 256
#define HW 4096
#define NH 8
#define HD 32
#define NG 32
#define CPG 8
#define EPSV 1e-5f
#define SPLIT 32           // n-tiles (slice = 128)

// ---------------- scratch (device globals) ----------------------------------
__device__ __nv_bfloat16 g_xh[(size_t)BB * CC * HW];     // normed x hi
__device__ __nv_bfloat16 g_xl[(size_t)BB * CC * HW];     // normed x lo
__device__ __nv_bfloat16 g_wqh[2 * CC * CC];             // K,V weights hi (rearranged)
__device__ __nv_bfloat16 g_wql[2 * CC * CC];             // K,V weights lo
__device__ float g_att_part[(size_t)SPLIT * BB * NH * HD * HD];
__device__ float g_lmax[SPLIT * BB * NH * HD];
__device__ float g_lsum[SPLIT * BB * NH * HD];
__device__ float g_att[(size_t)BB * NH * HD * HD];
__device__ float g_weff[(size_t)BB * CC * CC];
__device__ __nv_bfloat16 g_w2h[(size_t)BB * CC * CC];
__device__ __nv_bfloat16 g_w2l[(size_t)BB * CC * CC];

// ---------------- warp-MMA helpers ------------------------------------------
__device__ __forceinline__ uint32_t smem_u32(const void* p) {
    uint32_t a;
    asm("{ .reg .u64 t; cvta.to.shared.u64 t, %1; cvt.u32.u64 %0, t; }"
        : "=r"(a) : "l"(p));
    return a;
}
__device__ __forceinline__ void ldmx4(uint32_t* r, uint32_t addr) {
    asm volatile("ldmatrix.sync.aligned.m8n8.x4.shared.b16 {%0,%1,%2,%3}, [%4];"
                 : "=r"(r[0]), "=r"(r[1]), "=r"(r[2]), "=r"(r[3]) : "r"(addr));
}
__device__ __forceinline__ void ldmx4t(uint32_t* r, uint32_t addr) {
    asm volatile("ldmatrix.sync.aligned.m8n8.x4.trans.shared.b16 {%0,%1,%2,%3}, [%4];"
                 : "=r"(r[0]), "=r"(r[1]), "=r"(r[2]), "=r"(r[3]) : "r"(addr));
}
__device__ __forceinline__ void ldmx2(uint32_t* r, uint32_t addr) {
    asm volatile("ldmatrix.sync.aligned.m8n8.x2.shared.b16 {%0,%1}, [%2];"
                 : "=r"(r[0]), "=r"(r[1]) : "r"(addr));
}
__device__ __forceinline__ void mma_bf16(float* c, const uint32_t* a, const uint32_t* b) {
    asm volatile("mma.sync.aligned.m16n8k16.row.col.f32.bf16.bf16.f32 "
                 "{%0,%1,%2,%3}, {%4,%5,%6,%7}, {%8,%9}, {%0,%1,%2,%3};"
                 : "+f"(c[0]), "+f"(c[1]), "+f"(c[2]), "+f"(c[3])
                 : "r"(a[0]), "r"(a[1]), "r"(a[2]), "r"(a[3]),
                   "r"(b[0]), "r"(b[1]));
}
__device__ __forceinline__ uint32_t pk2(__nv_bfloat16 a, __nv_bfloat16 b) {
    __nv_bfloat162 t = __halves2bfloat162(a, b);
    return *(uint32_t*)&t;
}
__device__ __forceinline__ void cp16(uint32_t dst, const void* src) {
    asm volatile("cp.async.cg.shared.global [%0], [%1], 16;" :: "r"(dst), "l"(src));
}

#define AST 40    // A smem row stride (bf16)
#define BST 136   // B smem row stride (bf16)
#define PST 72    // P-stage plane row stride (bf16)

// fused kernel smem layout (3 stages)
#define F_AH 0
#define F_AL 20480
#define F_BH 40960
#define F_BL 49664
#define F_STAGE 58368
#define F_SMEM  (3 * F_STAGE)      // 175104
#define PKH 0
#define PKL 18432
#define PVH 36864
#define PVL 55296
#define PMAX 73728                 // float[2][128]
#define PSUM 74752                 // float[2][128]

// final gemm smem layout (3 stages)
#define ST_AH 0
#define ST_AL 10240
#define ST_BH 20480
#define ST_BL 29184
#define ST_BYTES 37888
#define SMEM_GEMM (3 * ST_BYTES)   // 113664

// ---------------------------------------------------------------------------
// K1: fused GroupNorm (stats + apply) + bf16 hi/lo split of x.
//   One block per (b, group): 8 rows x 4096. Pass 2 re-reads from L2.
// ---------------------------------------------------------------------------
__global__ __launch_bounds__(256)
void gn_prep_kernel(const float* __restrict__ x,
                    const float* __restrict__ gw,
                    const float* __restrict__ gb) {
    const int b = blockIdx.x / NG;
    const int g = blockIdx.x % NG;
    const size_t base = ((size_t)b * CC + (size_t)g * CPG) * HW;
    const float* xp = x + base;
    const int tid = threadIdx.x;

    float s = 0.f, s2 = 0.f;
    #pragma unroll 8
    for (int it = 0; it < 32; it++) {
        float4 v = *(const float4*)(xp + (size_t)(it * 256 + tid) * 4);
        s  += v.x + v.y + v.z + v.w;
        s2 += v.x * v.x + v.y * v.y + v.z * v.z + v.w * v.w;
    }
    __shared__ float rs[32], rs2[32];
    #pragma unroll
    for (int o = 16; o > 0; o >>= 1) {
        s  += __shfl_down_sync(0xFFFFFFFFu, s,  o);
        s2 += __shfl_down_sync(0xFFFFFFFFu, s2, o);
    }
    int lane = tid & 31, wid = tid >> 5;
    if (lane == 0) { rs[wid] = s; rs2[wid] = s2; }
    __syncthreads();
    if (wid == 0) {
        s  = (lane < 8) ? rs[lane]  : 0.f;
        s2 = (lane < 8) ? rs2[lane] : 0.f;
        #pragma unroll
        for (int o = 4; o > 0; o >>= 1) {
            s  += __shfl_down_sync(0xFFFFFFFFu, s,  o);
            s2 += __shfl_down_sync(0xFFFFFFFFu, s2, o);
        }
        if (lane == 0) { rs[0] = s; rs2[0] = s2; }
    }
    __syncthreads();
    const float inv_n = 1.f / (float)(CPG * HW);
    const float mu   = rs[0] * inv_n;
    const float var  = rs2[0] * inv_n - mu * mu;
    const float rstd = rsqrtf(var + EPSV);

    __shared__ float ssc[CPG], ssh[CPG];
    if (tid < CPG) {
        int c = g * CPG + tid;
        float scv = rstd * gw[c];
        ssc[tid] = scv;
        ssh[tid] = gb[c] - mu * scv;
    }
    __syncthreads();

    __nv_bfloat16* xh = g_xh + base;
    __nv_bfloat16* xl = g_xl + base;
    #pragma unroll 8
    for (int it = 0; it < 32; it++) {
        int idx = it * 256 + tid;            // float4 index; 1024 per row
        int row = idx >> 10;
        float sc = ssc[row], sh = ssh[row];
        float4 v = *(const float4*)(xp + (size_t)idx * 4);
        v.x = fmaf(v.x, sc, sh); v.y = fmaf(v.y, sc, sh);
        v.z = fmaf(v.z, sc, sh); v.w = fmaf(v.w, sc, sh);
        __nv_bfloat16 h0 = __float2bfloat16(v.x), h1 = __float2bfloat16(v.y);
        __nv_bfloat16 h2 = __float2bfloat16(v.z), h3 = __float2bfloat16(v.w);
        __nv_bfloat16 l0 = __float2bfloat16(v.x - __bfloat162float(h0));
        __nv_bfloat16 l1 = __float2bfloat16(v.y - __bfloat162float(h1));
        __nv_bfloat16 l2 = __float2bfloat16(v.z - __bfloat162float(h2));
        __nv_bfloat16 l3 = __float2bfloat16(v.w - __bfloat162float(h3));
        *(uint2*)(xh + (size_t)idx * 4) = make_uint2(pk2(h0, h1), pk2(h2, h3));
        *(uint2*)(xl + (size_t)idx * 4) = make_uint2(pk2(l0, l1), pk2(l2, l3));
    }
}

// K1c: split + rearrange w_qkv K,V rows: dst[hh][0..127]=K(256+hh*128+r),
//      dst[hh][128..255]=V(512+hh*128+r)
__global__ __launch_bounds__(256) void prep_w_kernel(const float* __restrict__ w) {
    int idx = blockIdx.x * 256 + threadIdx.x;   // 0 .. 32767 float4s
    int r = idx >> 6, c4 = (idx & 63) * 4;
    int hh = r >> 8, rr = r & 255;
    int src = (rr < 128) ? (256 + hh * 128 + rr) : (512 + hh * 128 + rr - 128);
    float4 v = *(const float4*)(w + (size_t)src * CC + c4);
    __nv_bfloat16 h0 = __float2bfloat16(v.x), h1 = __float2bfloat16(v.y);
    __nv_bfloat16 h2 = __float2bfloat16(v.z), h3 = __float2bfloat16(v.w);
    __nv_bfloat16 l0 = __float2bfloat16(v.x - __bfloat162float(h0));
    __nv_bfloat16 l1 = __float2bfloat16(v.y - __bfloat162float(h1));
    __nv_bfloat16 l2 = __float2bfloat16(v.z - __bfloat162float(h2));
    __nv_bfloat16 l3 = __float2bfloat16(v.w - __bfloat162float(h3));
    size_t o = (size_t)r * CC + c4;
    *(uint2*)(g_wqh + o) = make_uint2(pk2(h0, h1), pk2(h2, h3));
    *(uint2*)(g_wql + o) = make_uint2(pk2(l0, l1), pk2(l2, l3));
}

// ---------------------------------------------------------------------------
// K2: fused KV GEMM + online attention partials (3-stage cp.async pipeline).
// ---------------------------------------------------------------------------
__global__ __launch_bounds__(512)
void gemm_kv_att() {
    extern __shared__ char smem[];
    const uint32_t sb = smem_u32(smem);

    const int tid = threadIdx.x;
    const int wid = tid >> 5, lane = tid & 31;
    const int wM = wid >> 1, wN = wid & 1;     // wM 0-3 = K rows, 4-7 = V rows
    const int s  = blockIdx.x;
    const int hh = blockIdx.y;
    const int b  = blockIdx.z;
    const int n0 = s * 128;

    const __nv_bfloat16* Ahb = g_wqh + (size_t)hh * 256 * CC;
    const __nv_bfloat16* Alb = g_wql + (size_t)hh * 256 * CC;
    const __nv_bfloat16* Bh  = g_xh + (size_t)b * CC * HW;
    const __nv_bfloat16* Bl  = g_xl + (size_t)b * CC * HW;

    const int bRowL0 = tid >> 4, bQ4 = (tid & 15) * 8;

    auto issue = [&](int kc, int stage) {
        const uint32_t st = sb + stage * F_STAGE;
        const int k0 = kc * 32;
        #pragma unroll
        for (int it = 0; it < 2; it++) {       // A: 1024 cp16 per plane
            int idx = it * 512 + tid;
            int row = idx >> 2, q4 = (idx & 3) * 8;
            uint32_t d = (uint32_t)(row * AST + q4) * 2;
            cp16(st + F_AH + d, Ahb + (size_t)row * CC + k0 + q4);
            cp16(st + F_AL + d, Alb + (size_t)row * CC + k0 + q4);
        }
        {                                      // B: 512 cp16 per plane
            size_t g = ((size_t)(k0 + bRowL0)) * HW + n0 + bQ4;
            uint32_t d = (uint32_t)(bRowL0 * BST + bQ4) * 2;
            cp16(st + F_BH + d, Bh + g);
            cp16(st + F_BL + d, Bl + g);
        }
        asm volatile("cp.async.commit_group;");
    };

    float acc[2][8][4];
    #pragma unroll
    for (int i = 0; i < 2; i++)
        #pragma unroll
        for (int j = 0; j < 8; j++)
            #pragma unroll
            for (int q = 0; q < 4; q++) acc[i][j][q] = 0.f;

    const int lt = lane >> 3, lr = lane & 7;
    const int aRow = lr + ((lt & 1) ? 8 : 0);
    const int aKof = (lt & 2) ? 8 : 0;
    const int bKof = lr + ((lt & 1) ? 8 : 0);
    const int bNof = (lt & 2) ? 8 : 0;

    issue(0, 0);
    issue(1, 1);

    for (int kc = 0; kc < 8; kc++) {
        const int stage = kc % 3;
        if (kc < 6) {
            issue(kc + 2, (kc + 2) % 3);
            asm volatile("cp.async.wait_group 2;");
        } else if (kc == 6) {
            asm volatile("cp.async.wait_group 1;");
        } else {
            asm volatile("cp.async.wait_group 0;");
        }
        __syncthreads();

        const uint32_t aHB = sb + stage * F_STAGE + F_AH;
        const uint32_t aLB = sb + stage * F_STAGE + F_AL;
        const uint32_t bHB = sb + stage * F_STAGE + F_BH;
        const uint32_t bLB = sb + stage * F_STAGE + F_BL;

        #pragma unroll
        for (int ks = 0; ks < 2; ks++) {
            const int kb = ks * 16;
            uint32_t ah[2][4], al[2][4], bh[8][2], bl[8][2];
            #pragma unroll
            for (int mt = 0; mt < 2; mt++) {
                uint32_t ad = ((wM * 32 + mt * 16 + aRow) * AST + kb + aKof) * 2;
                ldmx4(ah[mt], aHB + ad);
                ldmx4(al[mt], aLB + ad);
            }
            #pragma unroll
            for (int np = 0; np < 4; np++) {
                uint32_t bd = ((kb + bKof) * BST + wN * 64 + np * 16 + bNof) * 2;
                uint32_t r[4];
                ldmx4t(r, bHB + bd);
                bh[np * 2][0] = r[0]; bh[np * 2][1] = r[1];
                bh[np * 2 + 1][0] = r[2]; bh[np * 2 + 1][1] = r[3];
                ldmx4t(r, bLB + bd);
                bl[np * 2][0] = r[0]; bl[np * 2][1] = r[1];
                bl[np * 2 + 1][0] = r[2]; bl[np * 2 + 1][1] = r[3];
            }
            #pragma unroll
            for (int mt = 0; mt < 2; mt++)
                #pragma unroll
                for (int nt = 0; nt < 8; nt++) {
                    mma_bf16(acc[mt][nt], ah[mt], bh[nt]);
                    mma_bf16(acc[mt][nt], ah[mt], bl[nt]);
                    mma_bf16(acc[mt][nt], al[mt], bh[nt]);
                }
        }
        __syncthreads();
    }

    // ================= fused attention epilogue =================
    const int rq = lane >> 2, cq = lane & 3;
    const bool isK = (wM < 4);
    float* smMax = (float*)(smem + PMAX);  // [2][128]
    float* smSum = (float*)(smem + PSUM);  // [2][128]

    // 1. per-warp row max over this warp's 64 cols
    if (isK) {
        #pragma unroll
        for (int mt = 0; mt < 2; mt++)
            #pragma unroll
            for (int rh = 0; rh < 2; rh++) {
                float m = -3.4e38f;
                #pragma unroll
                for (int nt = 0; nt < 8; nt++) {
                    m = fmaxf(m, acc[mt][nt][rh * 2]);
                    m = fmaxf(m, acc[mt][nt][rh * 2 + 1]);
                }
                m = fmaxf(m, __shfl_xor_sync(0xFFFFFFFFu, m, 1));
                m = fmaxf(m, __shfl_xor_sync(0xFFFFFFFFu, m, 2));
                if (cq == 0)
                    smMax[wN * 128 + wM * 32 + mt * 16 + rh * 8 + rq] = m;
            }
    }
    __syncthreads();

    // 2. exp with combined max + row sums
    if (isK) {
        #pragma unroll
        for (int mt = 0; mt < 2; mt++)
            #pragma unroll
            for (int rh = 0; rh < 2; rh++) {
                int row = wM * 32 + mt * 16 + rh * 8 + rq;
                float km = fmaxf(smMax[row], smMax[128 + row]);
                float ss = 0.f;
                #pragma unroll
                for (int nt = 0; nt < 8; nt++) {
                    float e0 = __expf(acc[mt][nt][rh * 2]     - km);
                    float e1 = __expf(acc[mt][nt][rh * 2 + 1] - km);
                    acc[mt][nt][rh * 2]     = e0;
                    acc[mt][nt][rh * 2 + 1] = e1;
                    ss += e0 + e1;
                }
                ss += __shfl_xor_sync(0xFFFFFFFFu, ss, 1);
                ss += __shfl_xor_sync(0xFFFFFFFFu, ss, 2);
                if (cq == 0) smSum[wN * 128 + row] = ss;
            }
    }

    // 3. two n-passes: stage expK/V tiles (bf16 hi/lo) + P-MMA
    float pp[2][4];
    #pragma unroll
    for (int mt = 0; mt < 2; mt++)
        #pragma unroll
        for (int q = 0; q < 4; q++) pp[mt][q] = 0.f;

    const int head = wid >> 2, sub = wid & 3;
    const int l16 = lane & 15;
    const uint32_t baddrBase =
        ((head * 32 + sub * 8 + (l16 & 7)) * PST + (l16 >> 3) * 8) * 2;

    #pragma unroll
    for (int p = 0; p < 2; p++) {
        __syncthreads();
        if (wN == p) {
            const int rowb = (wM & 3) * 32;
            #pragma unroll
            for (int mt = 0; mt < 2; mt++)
                #pragma unroll
                for (int rh = 0; rh < 2; rh++) {
                    int row = rowb + mt * 16 + rh * 8 + rq;
                    #pragma unroll
                    for (int nt = 0; nt < 8; nt++) {
                        int c = nt * 8 + cq * 2;
                        float v0 = acc[mt][nt][rh * 2];
                        float v1 = acc[mt][nt][rh * 2 + 1];
                        __nv_bfloat16 h0 = __float2bfloat16(v0);
                        __nv_bfloat16 h1 = __float2bfloat16(v1);
                        __nv_bfloat16 q0 = __float2bfloat16(v0 - __bfloat162float(h0));
                        __nv_bfloat16 q1 = __float2bfloat16(v1 - __bfloat162float(h1));
                        uint32_t off = (uint32_t)(row * PST + c) * 2;
                        *(uint32_t*)(smem + (isK ? PKH : PVH) + off) = pk2(h0, h1);
                        *(uint32_t*)(smem + (isK ? PKL : PVL) + off) = pk2(q0, q1);
                    }
                }
        }
        __syncthreads();

        #pragma unroll
        for (int ks = 0; ks < 4; ks++) {
            const int kb = ks * 16;
            uint32_t b2h[2], b2l[2];
            ldmx2(b2h, sb + PVH + baddrBase + (uint32_t)kb * 2);
            ldmx2(b2l, sb + PVL + baddrBase + (uint32_t)kb * 2);
            #pragma unroll
            for (int mt = 0; mt < 2; mt++) {
                uint32_t a2h[4], a2l[4];
                uint32_t ad = ((head * 32 + mt * 16 + aRow) * PST + kb + aKof) * 2;
                ldmx4(a2h, sb + PKH + ad);
                ldmx4(a2l, sb + PKL + ad);
                mma_bf16(pp[mt], a2h, b2h);
                mma_bf16(pp[mt], a2h, b2l);
                mma_bf16(pp[mt], a2l, b2h);
            }
        }
    }

    // 4. write P partials, lmax, lsum
    const int bh = b * NH + hh * 4 + head;
    float* P = g_att_part + ((size_t)s * (BB * NH) + bh) * (HD * HD);
    #pragma unroll
    for (int mt = 0; mt < 2; mt++) {
        int d = mt * 16 + rq;
        int e = sub * 8 + cq * 2;
        *(float2*)&P[d * HD + e]       = make_float2(pp[mt][0], pp[mt][1]);
        *(float2*)&P[(d + 8) * HD + e] = make_float2(pp[mt][2], pp[mt][3]);
    }
    if (tid < 128) {
        int h = hh * 4 + (tid >> 5);
        int o = (s * (BB * NH) + b * NH + h) * HD + (tid & 31);
        g_lmax[o] = fmaxf(smMax[tid], smMax[128 + tid]);
        g_lsum[o] = smSum[tid] + smSum[128 + tid];
    }
}

// ---------------------------------------------------------------------------
// K3b: combine splits
// ---------------------------------------------------------------------------
__global__ __launch_bounds__(256) void att_reduce_kernel() {
    const int bh = blockIdx.x;
    __shared__ float sfac[SPLIT][HD];
    __shared__ float sdinv[HD];
    const int t = threadIdx.x;

    if (t < HD) {
        float gm = -3.4e38f;
        #pragma unroll 4
        for (int s = 0; s < SPLIT; s++)
            gm = fmaxf(gm, g_lmax[(s * (BB * NH) + bh) * HD + t]);
        float den = 0.f;
        #pragma unroll 4
        for (int s = 0; s < SPLIT; s++) {
            float f = __expf(g_lmax[(s * (BB * NH) + bh) * HD + t] - gm);
            sfac[s][t] = f;
            den += g_lsum[(s * (BB * NH) + bh) * HD + t] * f;
        }
        sdinv[t] = 1.f / den;
    }
    __syncthreads();

    #pragma unroll
    for (int idx = t; idx < HD * HD; idx += 256) {
        int d = idx >> 5;
        float acc = 0.f;
        #pragma unroll 4
        for (int s = 0; s < SPLIT; s++)
            acc = fmaf(g_att_part[((size_t)s * (BB * NH) + bh) * (HD * HD) + idx],
                       sfac[s][d], acc);
        g_att[(size_t)bh * (HD * HD) + idx] = acc * sdinv[d];
    }
}

// ---------------------------------------------------------------------------
// K4: Weff[b] = Wp . att[b]
// ---------------------------------------------------------------------------
__global__ __launch_bounds__(256) void weff_kernel(const float* __restrict__ wp) {
    const int b = blockIdx.x;
    __shared__ float satt[NH][HD][HD];
    const int t = threadIdx.x;
    for (int i = t; i < NH * HD * HD; i += 256)
        ((float*)satt)[i] = g_att[(size_t)b * NH * HD * HD + i];
    __syncthreads();

    const int o = t;
    const float* wrow = wp + (size_t)o * CC;
    float* wout = g_weff + ((size_t)b * CC + o) * CC;
    #pragma unroll
    for (int h = 0; h < NH; h++) {
        float wreg[HD];
        #pragma unroll
        for (int e = 0; e < HD; e++) wreg[e] = wrow[h * HD + e];
        #pragma unroll 2
        for (int d = 0; d < HD; d++) {
            float s = 0.f;
            #pragma unroll
            for (int e = 0; e < HD; e++)
                s = fmaf(wreg[e], satt[h][d][e], s);
            wout[h * HD + d] = s;
        }
    }
}

// ---------------------------------------------------------------------------
// K4b: W2[b] = Weff[b] . Wq_q, split to bf16 hi/lo
// ---------------------------------------------------------------------------
__global__ __launch_bounds__(256) void w2_kernel(const float* __restrict__ wq) {
    __shared__ float sW[16 * 256];
    const int b = blockIdx.x, r0 = blockIdx.y * 16;
    const int t = threadIdx.x;

    const float4* src = (const float4*)(g_weff + ((size_t)b * CC + r0) * CC);
    #pragma unroll
    for (int i = 0; i < 4; i++)
        ((float4*)sW)[i * 256 + t] = src[i * 256 + t];
    __syncthreads();

    const int c = t;
    float acc[16];
    #pragma unroll
    for (int o = 0; o < 16; o++) acc[o] = 0.f;

    for (int d = 0; d < CC; d += 4) {
        float wv0 = wq[(size_t)(d + 0) * CC + c];
        float wv1 = wq[(size_t)(d + 1) * CC + c];
        float wv2 = wq[(size_t)(d + 2) * CC + c];
        float wv3 = wq[(size_t)(d + 3) * CC + c];
        #pragma unroll
        for (int o = 0; o < 16; o++) {
            float4 sw = *(const float4*)&sW[o * 256 + d];
            acc[o] = fmaf(sw.x, wv0, acc[o]);
            acc[o] = fmaf(sw.y, wv1, acc[o]);
            acc[o] = fmaf(sw.z, wv2, acc[o]);
            acc[o] = fmaf(sw.w, wv3, acc[o]);
        }
    }
    #pragma unroll
    for (int o = 0; o < 16; o++) {
        float v = acc[o];
        __nv_bfloat16 hh = __float2bfloat16(v);
        __nv_bfloat16 ll = __float2bfloat16(v - __bfloat162float(hh));
        size_t g = ((size_t)b * CC + r0 + o) * CC + c;
        g_w2h[g] = hh;
        g_w2l[g] = ll;
    }
}

// ---------------------------------------------------------------------------
// K5: final GEMM out = W2[b] @ xn + bias (256 threads, 3-stage cp.async)
// ---------------------------------------------------------------------------
__global__ __launch_bounds__(256)
void gemm_final(const float* __restrict__ bias, float* __restrict__ Cout) {
    extern __shared__ char smem[];
    const uint32_t sb = smem_u32(smem);

    const int tid = threadIdx.x;
    const int wid = tid >> 5, lane = tid & 31;
    const int wM = wid >> 1, wN = wid & 1;
    const int b  = blockIdx.z;
    const int m0 = blockIdx.y * 128;
    const int n0 = blockIdx.x * 128;

    const __nv_bfloat16* Ahb = g_w2h + (size_t)b * CC * CC;
    const __nv_bfloat16* Alb = g_w2l + (size_t)b * CC * CC;
    const __nv_bfloat16* Bh  = g_xh + (size_t)b * CC * HW;
    const __nv_bfloat16* Bl  = g_xl + (size_t)b * CC * HW;

    const int aRowL0 = tid >> 2, aQ4 = (tid & 3) * 8;
    const int bRowL0 = tid >> 4, bQ4 = (tid & 15) * 8;

    auto issue = [&](int kc, int stage) {
        const uint32_t st = sb + stage * ST_BYTES;
        const int k0 = kc * 32;
        #pragma unroll
        for (int it = 0; it < 2; it++) {
            int row = aRowL0 + it * 64;
            uint32_t d = (uint32_t)(row * AST + aQ4) * 2;
            cp16(st + ST_AH + d, Ahb + (size_t)(m0 + row) * CC + k0 + aQ4);
            cp16(st + ST_AL + d, Alb + (size_t)(m0 + row) * CC + k0 + aQ4);
        }
        #pragma unroll
        for (int it = 0; it < 2; it++) {
            int row = bRowL0 + it * 16;
            size_t g = ((size_t)(k0 + row)) * HW + n0 + bQ4;
            uint32_t d = (uint32_t)(row * BST + bQ4) * 2;
            cp16(st + ST_BH + d, Bh + g);
            cp16(st + ST_BL + d, Bl + g);
        }
        asm volatile("cp.async.commit_group;");
    };

    float acc[2][8][4];
    #pragma unroll
    for (int i = 0; i < 2; i++)
        #pragma unroll
        for (int j = 0; j < 8; j++)
            #pragma unroll
            for (int q = 0; q < 4; q++) acc[i][j][q] = 0.f;

    const int lt = lane >> 3, lr = lane & 7;
    const int aRow = lr + ((lt & 1) ? 8 : 0);
    const int aKof = (lt & 2) ? 8 : 0;
    const int bKof = lr + ((lt & 1) ? 8 : 0);
    const int bNof = (lt & 2) ? 8 : 0;

    issue(0, 0);
    issue(1, 1);

    for (int kc = 0; kc < 8; kc++) {
        const int stage = kc % 3;
        if (kc < 6) {
            issue(kc + 2, (kc + 2) % 3);
            asm volatile("cp.async.wait_group 2;");
        } else if (kc == 6) {
            asm volatile("cp.async.wait_group 1;");
        } else {
            asm volatile("cp.async.wait_group 0;");
        }
        __syncthreads();

        const uint32_t aHB = sb + stage * ST_BYTES + ST_AH;
        const uint32_t aLB = sb + stage * ST_BYTES + ST_AL;
        const uint32_t bHB = sb + stage * ST_BYTES + ST_BH;
        const uint32_t bLB = sb + stage * ST_BYTES + ST_BL;

        #pragma unroll
        for (int ks = 0; ks < 2; ks++) {
            const int kb = ks * 16;
            uint32_t ah[2][4], al[2][4], bh[8][2], bl[8][2];
            #pragma unroll
            for (int mt = 0; mt < 2; mt++) {
                uint32_t ad = ((wM * 32 + mt * 16 + aRow) * AST + kb + aKof) * 2;
                ldmx4(ah[mt], aHB + ad);
                ldmx4(al[mt], aLB + ad);
            }
            #pragma unroll
            for (int np = 0; np < 4; np++) {
                uint32_t bd = ((kb + bKof) * BST + wN * 64 + np * 16 + bNof) * 2;
                uint32_t r[4];
                ldmx4t(r, bHB + bd);
                bh[np * 2][0] = r[0]; bh[np * 2][1] = r[1];
                bh[np * 2 + 1][0] = r[2]; bh[np * 2 + 1][1] = r[3];
                ldmx4t(r, bLB + bd);
                bl[np * 2][0] = r[0]; bl[np * 2][1] = r[1];
                bl[np * 2 + 1][0] = r[2]; bl[np * 2 + 1][1] = r[3];
            }
            #pragma unroll
            for (int mt = 0; mt < 2; mt++)
                #pragma unroll
                for (int nt = 0; nt < 8; nt++) {
                    mma_bf16(acc[mt][nt], ah[mt], bh[nt]);
                    mma_bf16(acc[mt][nt], ah[mt], bl[nt]);
                    mma_bf16(acc[mt][nt], al[mt], bh[nt]);
                }
        }
        __syncthreads();
    }

    const int rbase = m0 + wM * 32 + (lane >> 2);
    const int cbase = n0 + wN * 64 + (lane & 3) * 2;
    #pragma unroll
    for (int mt = 0; mt < 2; mt++) {
        int r0 = rbase + mt * 16;
        float bi0 = bias[r0];
        float bi1 = bias[r0 + 8];
        #pragma unroll
        for (int nt = 0; nt < 8; nt++) {
            int cc = cbase + nt * 8;
            *(float2*)(Cout + ((size_t)b * CC + r0) * HW + cc) =
                make_float2(acc[mt][nt][0] + bi0, acc[mt][nt][1] + bi0);
            *(float2*)(Cout + ((size_t)b * CC + r0 + 8) * HW + cc) =
                make_float2(acc[mt][nt][2] + bi1, acc[mt][nt][3] + bi1);
        }
    }
}

// ---------------------------------------------------------------------------
extern "C" void kernel_launch(void* const* d_in, const int* in_sizes, int n_in,
                              void* d_out, int out_size) {
    const float* x      = (const float*)d_in[0];
    const float* gn_w   = (const float*)d_in[1];
    const float* gn_b   = (const float*)d_in[2];
    const float* w_qkv  = (const float*)d_in[3];
    const float* w_proj = (const float*)d_in[4];
    const float* b_proj = (const float*)d_in[5];
    float* out = (float*)d_out;

    cudaFuncSetAttribute(gemm_kv_att, cudaFuncAttributeMaxDynamicSharedMemorySize,
                         F_SMEM);
    cudaFuncSetAttribute(gemm_final, cudaFuncAttributeMaxDynamicSharedMemorySize,
                         SMEM_GEMM);

    // K1: fused groupnorm + split x; split+rearrange K/V weights
    gn_prep_kernel<<<BB * NG, 256>>>(x, gn_w, gn_b);
    prep_w_kernel<<<128, 256>>>(w_qkv);

    // K2: fused KV projection + attention partials
    {
        dim3 grid(SPLIT, 2, BB);
        gemm_kv_att<<<grid, 512, F_SMEM>>>();
    }

    // K3: combine splits
    att_reduce_kernel<<<BB * NH, 256>>>();

    // K4: Weff = Wp.att, W2 = Weff.Wq_q
    weff_kernel<<<BB, 256>>>(w_proj);
    {
        dim3 grid(BB, CC / 16);
        w2_kernel<<<grid, 256>>>(w_qkv);
    }

    // K5: out = W2[b] @ xn + bias
    {
        dim3 grid(HW / 128, CC / 128, BB);
        gemm_final<<<grid, 256, SMEM_GEMM>>>(b_proj, out);
    }
}

// round 10
// speedup vs baseline: 4.2007x; 1.2900x over previous
#include <cuda_runtime.h>
#include <cuda_bf16.h>
#include <cstdint>

#define BB 16
#define CC 256
#define HW 4096
#define NH 8
#define HD 32
#define NG 32
#define CPG 8
#define EPSV 1e-5f
#define SPLIT 32           // n-tiles (slice = 128)

// ---------------- scratch (device globals) ----------------------------------
__device__ __nv_bfloat16 g_xh[(size_t)BB * CC * HW];     // normed x hi
__device__ __nv_bfloat16 g_xl[(size_t)BB * CC * HW];     // normed x lo
__device__ __nv_bfloat16 g_wqh[2 * CC * CC];             // K,V weights hi (rearranged)
__device__ __nv_bfloat16 g_wql[2 * CC * CC];             // K,V weights lo
__device__ float g_att_part[(size_t)BB * NH * SPLIT * HD * HD];  // [bh][s][d*e]
__device__ float g_lmax[SPLIT * BB * NH * HD];
__device__ float g_lsum[SPLIT * BB * NH * HD];
__device__ float g_weff[(size_t)BB * CC * CC];
__device__ __nv_bfloat16 g_w2h[(size_t)BB * CC * CC];
__device__ __nv_bfloat16 g_w2l[(size_t)BB * CC * CC];

// ---------------- warp-MMA helpers ------------------------------------------
__device__ __forceinline__ uint32_t smem_u32(const void* p) {
    uint32_t a;
    asm("{ .reg .u64 t; cvta.to.shared.u64 t, %1; cvt.u32.u64 %0, t; }"
        : "=r"(a) : "l"(p));
    return a;
}
__device__ __forceinline__ void ldmx4(uint32_t* r, uint32_t addr) {
    asm volatile("ldmatrix.sync.aligned.m8n8.x4.shared.b16 {%0,%1,%2,%3}, [%4];"
                 : "=r"(r[0]), "=r"(r[1]), "=r"(r[2]), "=r"(r[3]) : "r"(addr));
}
__device__ __forceinline__ void ldmx4t(uint32_t* r, uint32_t addr) {
    asm volatile("ldmatrix.sync.aligned.m8n8.x4.trans.shared.b16 {%0,%1,%2,%3}, [%4];"
                 : "=r"(r[0]), "=r"(r[1]), "=r"(r[2]), "=r"(r[3]) : "r"(addr));
}
__device__ __forceinline__ void ldmx2(uint32_t* r, uint32_t addr) {
    asm volatile("ldmatrix.sync.aligned.m8n8.x2.shared.b16 {%0,%1}, [%2];"
                 : "=r"(r[0]), "=r"(r[1]) : "r"(addr));
}
__device__ __forceinline__ void mma_bf16(float* c, const uint32_t* a, const uint32_t* b) {
    asm volatile("mma.sync.aligned.m16n8k16.row.col.f32.bf16.bf16.f32 "
                 "{%0,%1,%2,%3}, {%4,%5,%6,%7}, {%8,%9}, {%0,%1,%2,%3};"
                 : "+f"(c[0]), "+f"(c[1]), "+f"(c[2]), "+f"(c[3])
                 : "r"(a[0]), "r"(a[1]), "r"(a[2]), "r"(a[3]),
                   "r"(b[0]), "r"(b[1]));
}
__device__ __forceinline__ uint32_t pk2(__nv_bfloat16 a, __nv_bfloat16 b) {
    __nv_bfloat162 t = __halves2bfloat162(a, b);
    return *(uint32_t*)&t;
}
__device__ __forceinline__ void cp16(uint32_t dst, const void* src) {
    asm volatile("cp.async.cg.shared.global [%0], [%1], 16;" :: "r"(dst), "l"(src));
}

#define AST 40    // A smem row stride (bf16)
#define BST 136   // B smem row stride (bf16)
#define PST 72    // P-stage plane row stride (bf16)

// fused kernel smem layout (3 stages)
#define F_AH 0
#define F_AL 20480
#define F_BH 40960
#define F_BL 49664
#define F_STAGE 58368
#define F_SMEM  (3 * F_STAGE)      // 175104
#define PKH 0
#define PKL 18432
#define PVH 36864
#define PVL 55296
#define PMAX 73728                 // float[2][128]
#define PSUM 74752                 // float[2][128]

// final gemm smem layout (3 stages)
#define ST_AH 0
#define ST_AL 10240
#define ST_BH 20480
#define ST_BL 29184
#define ST_BYTES 37888
#define SMEM_GEMM (3 * ST_BYTES)   // 113664

// ---------------------------------------------------------------------------
// K1: fused GroupNorm (stats + apply) + bf16 hi/lo split of x.
// ---------------------------------------------------------------------------
__global__ __launch_bounds__(256)
void gn_prep_kernel(const float* __restrict__ x,
                    const float* __restrict__ gw,
                    const float* __restrict__ gb) {
    const int b = blockIdx.x / NG;
    const int g = blockIdx.x % NG;
    const size_t base = ((size_t)b * CC + (size_t)g * CPG) * HW;
    const float* xp = x + base;
    const int tid = threadIdx.x;

    float s = 0.f, s2 = 0.f;
    #pragma unroll 8
    for (int it = 0; it < 32; it++) {
        float4 v = *(const float4*)(xp + (size_t)(it * 256 + tid) * 4);
        s  += v.x + v.y + v.z + v.w;
        s2 += v.x * v.x + v.y * v.y + v.z * v.z + v.w * v.w;
    }
    __shared__ float rs[32], rs2[32];
    #pragma unroll
    for (int o = 16; o > 0; o >>= 1) {
        s  += __shfl_down_sync(0xFFFFFFFFu, s,  o);
        s2 += __shfl_down_sync(0xFFFFFFFFu, s2, o);
    }
    int lane = tid & 31, wid = tid >> 5;
    if (lane == 0) { rs[wid] = s; rs2[wid] = s2; }
    __syncthreads();
    if (wid == 0) {
        s  = (lane < 8) ? rs[lane]  : 0.f;
        s2 = (lane < 8) ? rs2[lane] : 0.f;
        #pragma unroll
        for (int o = 4; o > 0; o >>= 1) {
            s  += __shfl_down_sync(0xFFFFFFFFu, s,  o);
            s2 += __shfl_down_sync(0xFFFFFFFFu, s2, o);
        }
        if (lane == 0) { rs[0] = s; rs2[0] = s2; }
    }
    __syncthreads();
    const float inv_n = 1.f / (float)(CPG * HW);
    const float mu   = rs[0] * inv_n;
    const float var  = rs2[0] * inv_n - mu * mu;
    const float rstd = rsqrtf(var + EPSV);

    __shared__ float ssc[CPG], ssh[CPG];
    if (tid < CPG) {
        int c = g * CPG + tid;
        float scv = rstd * gw[c];
        ssc[tid] = scv;
        ssh[tid] = gb[c] - mu * scv;
    }
    __syncthreads();

    __nv_bfloat16* xh = g_xh + base;
    __nv_bfloat16* xl = g_xl + base;
    #pragma unroll 8
    for (int it = 0; it < 32; it++) {
        int idx = it * 256 + tid;            // float4 index; 1024 per row
        int row = idx >> 10;
        float sc = ssc[row], sh = ssh[row];
        float4 v = *(const float4*)(xp + (size_t)idx * 4);
        v.x = fmaf(v.x, sc, sh); v.y = fmaf(v.y, sc, sh);
        v.z = fmaf(v.z, sc, sh); v.w = fmaf(v.w, sc, sh);
        __nv_bfloat16 h0 = __float2bfloat16(v.x), h1 = __float2bfloat16(v.y);
        __nv_bfloat16 h2 = __float2bfloat16(v.z), h3 = __float2bfloat16(v.w);
        __nv_bfloat16 l0 = __float2bfloat16(v.x - __bfloat162float(h0));
        __nv_bfloat16 l1 = __float2bfloat16(v.y - __bfloat162float(h1));
        __nv_bfloat16 l2 = __float2bfloat16(v.z - __bfloat162float(h2));
        __nv_bfloat16 l3 = __float2bfloat16(v.w - __bfloat162float(h3));
        *(uint2*)(xh + (size_t)idx * 4) = make_uint2(pk2(h0, h1), pk2(h2, h3));
        *(uint2*)(xl + (size_t)idx * 4) = make_uint2(pk2(l0, l1), pk2(l2, l3));
    }
}

// K1c: split + rearrange w_qkv K,V rows
__global__ __launch_bounds__(256) void prep_w_kernel(const float* __restrict__ w) {
    int idx = blockIdx.x * 256 + threadIdx.x;   // 0 .. 32767 float4s
    int r = idx >> 6, c4 = (idx & 63) * 4;
    int hh = r >> 8, rr = r & 255;
    int src = (rr < 128) ? (256 + hh * 128 + rr) : (512 + hh * 128 + rr - 128);
    float4 v = *(const float4*)(w + (size_t)src * CC + c4);
    __nv_bfloat16 h0 = __float2bfloat16(v.x), h1 = __float2bfloat16(v.y);
    __nv_bfloat16 h2 = __float2bfloat16(v.z), h3 = __float2bfloat16(v.w);
    __nv_bfloat16 l0 = __float2bfloat16(v.x - __bfloat162float(h0));
    __nv_bfloat16 l1 = __float2bfloat16(v.y - __bfloat162float(h1));
    __nv_bfloat16 l2 = __float2bfloat16(v.z - __bfloat162float(h2));
    __nv_bfloat16 l3 = __float2bfloat16(v.w - __bfloat162float(h3));
    size_t o = (size_t)r * CC + c4;
    *(uint2*)(g_wqh + o) = make_uint2(pk2(h0, h1), pk2(h2, h3));
    *(uint2*)(g_wql + o) = make_uint2(pk2(l0, l1), pk2(l2, l3));
}

// ---------------------------------------------------------------------------
// K2: fused KV GEMM + online attention partials (3-stage cp.async pipeline).
// ---------------------------------------------------------------------------
__global__ __launch_bounds__(512)
void gemm_kv_att() {
    extern __shared__ char smem[];
    const uint32_t sb = smem_u32(smem);

    const int tid = threadIdx.x;
    const int wid = tid >> 5, lane = tid & 31;
    const int wM = wid >> 1, wN = wid & 1;     // wM 0-3 = K rows, 4-7 = V rows
    const int s  = blockIdx.x;
    const int hh = blockIdx.y;
    const int b  = blockIdx.z;
    const int n0 = s * 128;

    const __nv_bfloat16* Ahb = g_wqh + (size_t)hh * 256 * CC;
    const __nv_bfloat16* Alb = g_wql + (size_t)hh * 256 * CC;
    const __nv_bfloat16* Bh  = g_xh + (size_t)b * CC * HW;
    const __nv_bfloat16* Bl  = g_xl + (size_t)b * CC * HW;

    const int bRowL0 = tid >> 4, bQ4 = (tid & 15) * 8;

    auto issue = [&](int kc, int stage) {
        const uint32_t st = sb + stage * F_STAGE;
        const int k0 = kc * 32;
        #pragma unroll
        for (int it = 0; it < 2; it++) {       // A: 1024 cp16 per plane
            int idx = it * 512 + tid;
            int row = idx >> 2, q4 = (idx & 3) * 8;
            uint32_t d = (uint32_t)(row * AST + q4) * 2;
            cp16(st + F_AH + d, Ahb + (size_t)row * CC + k0 + q4);
            cp16(st + F_AL + d, Alb + (size_t)row * CC + k0 + q4);
        }
        {                                      // B: 512 cp16 per plane
            size_t g = ((size_t)(k0 + bRowL0)) * HW + n0 + bQ4;
            uint32_t d = (uint32_t)(bRowL0 * BST + bQ4) * 2;
            cp16(st + F_BH + d, Bh + g);
            cp16(st + F_BL + d, Bl + g);
        }
        asm volatile("cp.async.commit_group;");
    };

    float acc[2][8][4];
    #pragma unroll
    for (int i = 0; i < 2; i++)
        #pragma unroll
        for (int j = 0; j < 8; j++)
            #pragma unroll
            for (int q = 0; q < 4; q++) acc[i][j][q] = 0.f;

    const int lt = lane >> 3, lr = lane & 7;
    const int aRow = lr + ((lt & 1) ? 8 : 0);
    const int aKof = (lt & 2) ? 8 : 0;
    const int bKof = lr + ((lt & 1) ? 8 : 0);
    const int bNof = (lt & 2) ? 8 : 0;

    issue(0, 0);
    issue(1, 1);

    for (int kc = 0; kc < 8; kc++) {
        const int stage = kc % 3;
        if (kc < 6) {
            issue(kc + 2, (kc + 2) % 3);
            asm volatile("cp.async.wait_group 2;");
        } else if (kc == 6) {
            asm volatile("cp.async.wait_group 1;");
        } else {
            asm volatile("cp.async.wait_group 0;");
        }
        __syncthreads();

        const uint32_t aHB = sb + stage * F_STAGE + F_AH;
        const uint32_t aLB = sb + stage * F_STAGE + F_AL;
        const uint32_t bHB = sb + stage * F_STAGE + F_BH;
        const uint32_t bLB = sb + stage * F_STAGE + F_BL;

        #pragma unroll
        for (int ks = 0; ks < 2; ks++) {
            const int kb = ks * 16;
            uint32_t ah[2][4], al[2][4], bh[8][2], bl[8][2];
            #pragma unroll
            for (int mt = 0; mt < 2; mt++) {
                uint32_t ad = ((wM * 32 + mt * 16 + aRow) * AST + kb + aKof) * 2;
                ldmx4(ah[mt], aHB + ad);
                ldmx4(al[mt], aLB + ad);
            }
            #pragma unroll
            for (int np = 0; np < 4; np++) {
                uint32_t bd = ((kb + bKof) * BST + wN * 64 + np * 16 + bNof) * 2;
                uint32_t r[4];
                ldmx4t(r, bHB + bd);
                bh[np * 2][0] = r[0]; bh[np * 2][1] = r[1];
                bh[np * 2 + 1][0] = r[2]; bh[np * 2 + 1][1] = r[3];
                ldmx4t(r, bLB + bd);
                bl[np * 2][0] = r[0]; bl[np * 2][1] = r[1];
                bl[np * 2 + 1][0] = r[2]; bl[np * 2 + 1][1] = r[3];
            }
            #pragma unroll
            for (int mt = 0; mt < 2; mt++)
                #pragma unroll
                for (int nt = 0; nt < 8; nt++) {
                    mma_bf16(acc[mt][nt], ah[mt], bh[nt]);
                    mma_bf16(acc[mt][nt], ah[mt], bl[nt]);
                    mma_bf16(acc[mt][nt], al[mt], bh[nt]);
                }
        }
        __syncthreads();
    }

    // ================= fused attention epilogue =================
    const int rq = lane >> 2, cq = lane & 3;
    const bool isK = (wM < 4);
    float* smMax = (float*)(smem + PMAX);  // [2][128]
    float* smSum = (float*)(smem + PSUM);  // [2][128]

    // 1. per-warp row max over this warp's 64 cols
    if (isK) {
        #pragma unroll
        for (int mt = 0; mt < 2; mt++)
            #pragma unroll
            for (int rh = 0; rh < 2; rh++) {
                float m = -3.4e38f;
                #pragma unroll
                for (int nt = 0; nt < 8; nt++) {
                    m = fmaxf(m, acc[mt][nt][rh * 2]);
                    m = fmaxf(m, acc[mt][nt][rh * 2 + 1]);
                }
                m = fmaxf(m, __shfl_xor_sync(0xFFFFFFFFu, m, 1));
                m = fmaxf(m, __shfl_xor_sync(0xFFFFFFFFu, m, 2));
                if (cq == 0)
                    smMax[wN * 128 + wM * 32 + mt * 16 + rh * 8 + rq] = m;
            }
    }
    __syncthreads();

    // 2. exp with combined max + row sums
    if (isK) {
        #pragma unroll
        for (int mt = 0; mt < 2; mt++)
            #pragma unroll
            for (int rh = 0; rh < 2; rh++) {
                int row = wM * 32 + mt * 16 + rh * 8 + rq;
                float km = fmaxf(smMax[row], smMax[128 + row]);
                float ss = 0.f;
                #pragma unroll
                for (int nt = 0; nt < 8; nt++) {
                    float e0 = __expf(acc[mt][nt][rh * 2]     - km);
                    float e1 = __expf(acc[mt][nt][rh * 2 + 1] - km);
                    acc[mt][nt][rh * 2]     = e0;
                    acc[mt][nt][rh * 2 + 1] = e1;
                    ss += e0 + e1;
                }
                ss += __shfl_xor_sync(0xFFFFFFFFu, ss, 1);
                ss += __shfl_xor_sync(0xFFFFFFFFu, ss, 2);
                if (cq == 0) smSum[wN * 128 + row] = ss;
            }
    }

    // 3. two n-passes: stage expK/V tiles (bf16 hi/lo) + P-MMA
    float pp[2][4];
    #pragma unroll
    for (int mt = 0; mt < 2; mt++)
        #pragma unroll
        for (int q = 0; q < 4; q++) pp[mt][q] = 0.f;

    const int head = wid >> 2, sub = wid & 3;
    const int l16 = lane & 15;
    const uint32_t baddrBase =
        ((head * 32 + sub * 8 + (l16 & 7)) * PST + (l16 >> 3) * 8) * 2;

    #pragma unroll
    for (int p = 0; p < 2; p++) {
        __syncthreads();
        if (wN == p) {
            const int rowb = (wM & 3) * 32;
            #pragma unroll
            for (int mt = 0; mt < 2; mt++)
                #pragma unroll
                for (int rh = 0; rh < 2; rh++) {
                    int row = rowb + mt * 16 + rh * 8 + rq;
                    #pragma unroll
                    for (int nt = 0; nt < 8; nt++) {
                        int c = nt * 8 + cq * 2;
                        float v0 = acc[mt][nt][rh * 2];
                        float v1 = acc[mt][nt][rh * 2 + 1];
                        __nv_bfloat16 h0 = __float2bfloat16(v0);
                        __nv_bfloat16 h1 = __float2bfloat16(v1);
                        __nv_bfloat16 q0 = __float2bfloat16(v0 - __bfloat162float(h0));
                        __nv_bfloat16 q1 = __float2bfloat16(v1 - __bfloat162float(h1));
                        uint32_t off = (uint32_t)(row * PST + c) * 2;
                        *(uint32_t*)(smem + (isK ? PKH : PVH) + off) = pk2(h0, h1);
                        *(uint32_t*)(smem + (isK ? PKL : PVL) + off) = pk2(q0, q1);
                    }
                }
        }
        __syncthreads();

        #pragma unroll
        for (int ks = 0; ks < 4; ks++) {
            const int kb = ks * 16;
            uint32_t b2h[2], b2l[2];
            ldmx2(b2h, sb + PVH + baddrBase + (uint32_t)kb * 2);
            ldmx2(b2l, sb + PVL + baddrBase + (uint32_t)kb * 2);
            #pragma unroll
            for (int mt = 0; mt < 2; mt++) {
                uint32_t a2h[4], a2l[4];
                uint32_t ad = ((head * 32 + mt * 16 + aRow) * PST + kb + aKof) * 2;
                ldmx4(a2h, sb + PKH + ad);
                ldmx4(a2l, sb + PKL + ad);
                mma_bf16(pp[mt], a2h, b2h);
                mma_bf16(pp[mt], a2h, b2l);
                mma_bf16(pp[mt], a2l, b2h);
            }
        }
    }

    // 4. write P partials ([bh][s][d*e] layout), lmax, lsum
    const int bh = b * NH + hh * 4 + head;
    float* P = g_att_part + ((size_t)bh * SPLIT + s) * (HD * HD);
    #pragma unroll
    for (int mt = 0; mt < 2; mt++) {
        int d = mt * 16 + rq;
        int e = sub * 8 + cq * 2;
        *(float2*)&P[d * HD + e]       = make_float2(pp[mt][0], pp[mt][1]);
        *(float2*)&P[(d + 8) * HD + e] = make_float2(pp[mt][2], pp[mt][3]);
    }
    if (tid < 128) {
        int h = hh * 4 + (tid >> 5);
        int o = (s * (BB * NH) + b * NH + h) * HD + (tid & 31);
        g_lmax[o] = fmaxf(smMax[tid], smMax[128 + tid]);
        g_lsum[o] = smSum[tid] + smSum[128 + tid];
    }
}

// ---------------------------------------------------------------------------
// K3: fused split-combine + Weff slice.  One block per (b, h).
//   att[d][e] = (sum_s P[bh][s][d][e] * exp(lmax_s - gmax)) / denom
//   Weff[b][o][h*32+d] = sum_e Wp[o][h*32+e] * att[d][e]
// ---------------------------------------------------------------------------
__global__ __launch_bounds__(256) void att_weff_kernel(const float* __restrict__ wp) {
    const int bh = blockIdx.x;
    const int b = bh >> 3, h = bh & 7;
    const int t = threadIdx.x;

    __shared__ float satt[HD * HD];       // 4 KB
    __shared__ float sfac[SPLIT][HD];     // 4 KB
    __shared__ float sdinv[HD];

    if (t < HD) {
        float gm = -3.4e38f;
        #pragma unroll 4
        for (int s = 0; s < SPLIT; s++)
            gm = fmaxf(gm, g_lmax[(s * (BB * NH) + bh) * HD + t]);
        float den = 0.f;
        #pragma unroll 4
        for (int s = 0; s < SPLIT; s++) {
            float f = __expf(g_lmax[(s * (BB * NH) + bh) * HD + t] - gm);
            sfac[s][t] = f;
            den += g_lsum[(s * (BB * NH) + bh) * HD + t] * f;
        }
        sdinv[t] = 1.f / den;
    }
    __syncthreads();

    const float* P = g_att_part + (size_t)bh * SPLIT * (HD * HD);
    #pragma unroll
    for (int r = 0; r < 4; r++) {
        int idx = t + r * 256;
        int d = idx >> 5;
        float acc = 0.f;
        #pragma unroll 8
        for (int s = 0; s < SPLIT; s++)
            acc = fmaf(P[s * (HD * HD) + idx], sfac[s][d], acc);
        satt[idx] = acc * sdinv[d];
    }
    __syncthreads();

    // Weff slice: o = t, 32 outputs
    const float* wrow = wp + (size_t)t * CC + h * HD;
    float wreg[HD];
    #pragma unroll
    for (int e = 0; e < HD; e++) wreg[e] = wrow[e];
    float* wout = g_weff + ((size_t)b * CC + t) * CC + h * HD;
    #pragma unroll 2
    for (int d = 0; d < HD; d++) {
        float sum = 0.f;
        #pragma unroll
        for (int e = 0; e < HD; e++)
            sum = fmaf(wreg[e], satt[d * HD + e], sum);
        wout[d] = sum;
    }
}

// ---------------------------------------------------------------------------
// K4b: W2[b] = Weff[b] . Wq_q, split to bf16 hi/lo
// ---------------------------------------------------------------------------
__global__ __launch_bounds__(256) void w2_kernel(const float* __restrict__ wq) {
    __shared__ float sW[16 * 256];
    const int b = blockIdx.x, r0 = blockIdx.y * 16;
    const int t = threadIdx.x;

    const float4* src = (const float4*)(g_weff + ((size_t)b * CC + r0) * CC);
    #pragma unroll
    for (int i = 0; i < 4; i++)
        ((float4*)sW)[i * 256 + t] = src[i * 256 + t];
    __syncthreads();

    const int c = t;
    float acc[16];
    #pragma unroll
    for (int o = 0; o < 16; o++) acc[o] = 0.f;

    for (int d = 0; d < CC; d += 4) {
        float wv0 = wq[(size_t)(d + 0) * CC + c];
        float wv1 = wq[(size_t)(d + 1) * CC + c];
        float wv2 = wq[(size_t)(d + 2) * CC + c];
        float wv3 = wq[(size_t)(d + 3) * CC + c];
        #pragma unroll
        for (int o = 0; o < 16; o++) {
            float4 sw = *(const float4*)&sW[o * 256 + d];
            acc[o] = fmaf(sw.x, wv0, acc[o]);
            acc[o] = fmaf(sw.y, wv1, acc[o]);
            acc[o] = fmaf(sw.z, wv2, acc[o]);
            acc[o] = fmaf(sw.w, wv3, acc[o]);
        }
    }
    #pragma unroll
    for (int o = 0; o < 16; o++) {
        float v = acc[o];
        __nv_bfloat16 hh = __float2bfloat16(v);
        __nv_bfloat16 ll = __float2bfloat16(v - __bfloat162float(hh));
        size_t g = ((size_t)b * CC + r0 + o) * CC + c;
        g_w2h[g] = hh;
        g_w2l[g] = ll;
    }
}

// ---------------------------------------------------------------------------
// K5: final GEMM out = W2[b] @ xn + bias (256 threads, 3-stage cp.async)
// ---------------------------------------------------------------------------
__global__ __launch_bounds__(256)
void gemm_final(const float* __restrict__ bias, float* __restrict__ Cout) {
    extern __shared__ char smem[];
    const uint32_t sb = smem_u32(smem);

    const int tid = threadIdx.x;
    const int wid = tid >> 5, lane = tid & 31;
    const int wM = wid >> 1, wN = wid & 1;
    const int b  = blockIdx.z;
    const int m0 = blockIdx.y * 128;
    const int n0 = blockIdx.x * 128;

    const __nv_bfloat16* Ahb = g_w2h + (size_t)b * CC * CC;
    const __nv_bfloat16* Alb = g_w2l + (size_t)b * CC * CC;
    const __nv_bfloat16* Bh  = g_xh + (size_t)b * CC * HW;
    const __nv_bfloat16* Bl  = g_xl + (size_t)b * CC * HW;

    const int aRowL0 = tid >> 2, aQ4 = (tid & 3) * 8;
    const int bRowL0 = tid >> 4, bQ4 = (tid & 15) * 8;

    auto issue = [&](int kc, int stage) {
        const uint32_t st = sb + stage * ST_BYTES;
        const int k0 = kc * 32;
        #pragma unroll
        for (int it = 0; it < 2; it++) {
            int row = aRowL0 + it * 64;
            uint32_t d = (uint32_t)(row * AST + aQ4) * 2;
            cp16(st + ST_AH + d, Ahb + (size_t)(m0 + row) * CC + k0 + aQ4);
            cp16(st + ST_AL + d, Alb + (size_t)(m0 + row) * CC + k0 + aQ4);
        }
        #pragma unroll
        for (int it = 0; it < 2; it++) {
            int row = bRowL0 + it * 16;
            size_t g = ((size_t)(k0 + row)) * HW + n0 + bQ4;
            uint32_t d = (uint32_t)(row * BST + bQ4) * 2;
            cp16(st + ST_BH + d, Bh + g);
            cp16(st + ST_BL + d, Bl + g);
        }
        asm volatile("cp.async.commit_group;");
    };

    float acc[2][8][4];
    #pragma unroll
    for (int i = 0; i < 2; i++)
        #pragma unroll
        for (int j = 0; j < 8; j++)
            #pragma unroll
            for (int q = 0; q < 4; q++) acc[i][j][q] = 0.f;

    const int lt = lane >> 3, lr = lane & 7;
    const int aRow = lr + ((lt & 1) ? 8 : 0);
    const int aKof = (lt & 2) ? 8 : 0;
    const int bKof = lr + ((lt & 1) ? 8 : 0);
    const int bNof = (lt & 2) ? 8 : 0;

    issue(0, 0);
    issue(1, 1);

    for (int kc = 0; kc < 8; kc++) {
        const int stage = kc % 3;
        if (kc < 6) {
            issue(kc + 2, (kc + 2) % 3);
            asm volatile("cp.async.wait_group 2;");
        } else if (kc == 6) {
            asm volatile("cp.async.wait_group 1;");
        } else {
            asm volatile("cp.async.wait_group 0;");
        }
        __syncthreads();

        const uint32_t aHB = sb + stage * ST_BYTES + ST_AH;
        const uint32_t aLB = sb + stage * ST_BYTES + ST_AL;
        const uint32_t bHB = sb + stage * ST_BYTES + ST_BH;
        const uint32_t bLB = sb + stage * ST_BYTES + ST_BL;

        #pragma unroll
        for (int ks = 0; ks < 2; ks++) {
            const int kb = ks * 16;
            uint32_t ah[2][4], al[2][4], bh[8][2], bl[8][2];
            #pragma unroll
            for (int mt = 0; mt < 2; mt++) {
                uint32_t ad = ((wM * 32 + mt * 16 + aRow) * AST + kb + aKof) * 2;
                ldmx4(ah[mt], aHB + ad);
                ldmx4(al[mt], aLB + ad);
            }
            #pragma unroll
            for (int np = 0; np < 4; np++) {
                uint32_t bd = ((kb + bKof) * BST + wN * 64 + np * 16 + bNof) * 2;
                uint32_t r[4];
                ldmx4t(r, bHB + bd);
                bh[np * 2][0] = r[0]; bh[np * 2][1] = r[1];
                bh[np * 2 + 1][0] = r[2]; bh[np * 2 + 1][1] = r[3];
                ldmx4t(r, bLB + bd);
                bl[np * 2][0] = r[0]; bl[np * 2][1] = r[1];
                bl[np * 2 + 1][0] = r[2]; bl[np * 2 + 1][1] = r[3];
            }
            #pragma unroll
            for (int mt = 0; mt < 2; mt++)
                #pragma unroll
                for (int nt = 0; nt < 8; nt++) {
                    mma_bf16(acc[mt][nt], ah[mt], bh[nt]);
                    mma_bf16(acc[mt][nt], ah[mt], bl[nt]);
                    mma_bf16(acc[mt][nt], al[mt], bh[nt]);
                }
        }
        __syncthreads();
    }

    const int rbase = m0 + wM * 32 + (lane >> 2);
    const int cbase = n0 + wN * 64 + (lane & 3) * 2;
    #pragma unroll
    for (int mt = 0; mt < 2; mt++) {
        int r0 = rbase + mt * 16;
        float bi0 = bias[r0];
        float bi1 = bias[r0 + 8];
        #pragma unroll
        for (int nt = 0; nt < 8; nt++) {
            int cc = cbase + nt * 8;
            *(float2*)(Cout + ((size_t)b * CC + r0) * HW + cc) =
                make_float2(acc[mt][nt][0] + bi0, acc[mt][nt][1] + bi0);
            *(float2*)(Cout + ((size_t)b * CC + r0 + 8) * HW + cc) =
                make_float2(acc[mt][nt][2] + bi1, acc[mt][nt][3] + bi1);
        }
    }
}

// ---------------------------------------------------------------------------
extern "C" void kernel_launch(void* const* d_in, const int* in_sizes, int n_in,
                              void* d_out, int out_size) {
    const float* x      = (const float*)d_in[0];
    const float* gn_w   = (const float*)d_in[1];
    const float* gn_b   = (const float*)d_in[2];
    const float* w_qkv  = (const float*)d_in[3];
    const float* w_proj = (const float*)d_in[4];
    const float* b_proj = (const float*)d_in[5];
    float* out = (float*)d_out;

    cudaFuncSetAttribute(gemm_kv_att, cudaFuncAttributeMaxDynamicSharedMemorySize,
                         F_SMEM);
    cudaFuncSetAttribute(gemm_final, cudaFuncAttributeMaxDynamicSharedMemorySize,
                         SMEM_GEMM);

    // K1: fused groupnorm + split x; split+rearrange K/V weights
    prep_w_kernel<<<128, 256>>>(w_qkv);
    gn_prep_kernel<<<BB * NG, 256>>>(x, gn_w, gn_b);

    // K2: fused KV projection + attention partials
    {
        dim3 grid(SPLIT, 2, BB);
        gemm_kv_att<<<grid, 512, F_SMEM>>>();
    }

    // K3: combine splits + fold into Wp (per (b,h))
    att_weff_kernel<<<BB * NH, 256>>>(w_proj);

    // K4: W2 = Weff . Wq_q
    {
        dim3 grid(BB, CC / 16);
        w2_kernel<<<grid, 256>>>(w_qkv);
    }

    // K5: out = W2[b] @ xn + bias
    {
        dim3 grid(HW / 128, CC / 128, BB);
        gemm_final<<<grid, 256, SMEM_GEMM>>>(b_proj, out);
    }
}